// round 1
// baseline (speedup 1.0000x reference)
#include <cuda_runtime.h>
#include <math.h>

#define N_NODES 10000
#define N_EDGES 640000
#define NFEAT   64
#define EFEAT   64
#define NHID    128
#define EHID    128
#define CSIZE   128

// ---------------- scratch (device globals; no allocation) ----------------
__device__ float g_h_v[N_NODES * NHID];
__device__ float g_hvdot[N_NODES];
__device__ float g_h_e[(size_t)N_EDGES * EHID];   // 327.68 MB
__device__ float g_logit[N_EDGES];
__device__ float g_A[N_NODES * EHID];             // sum(alpha * h_e)
__device__ float g_cv[N_NODES * CSIZE];           // elu(A @ W_msg + b)
__device__ float g_gi[N_NODES * 3 * NHID];
__device__ float g_gh[N_NODES * 3 * NHID];
__device__ float g_WihT[NHID * 3 * NHID];         // [128][384]
__device__ float g_WhhT[NHID * 3 * NHID];
__device__ int   g_cnt[N_NODES];
__device__ int   g_off[N_NODES + 1];
__device__ int   g_cur[N_NODES];
__device__ int   g_eid[N_EDGES];

// ---------------- small helpers ----------------
__device__ __forceinline__ float leaky01(float v) { return v > 0.f ? v : 0.01f * v; }

// ---------------- CSR build ----------------
__global__ void zero_cnt_kernel() {
    int i = blockIdx.x * blockDim.x + threadIdx.x;
    if (i < N_NODES) g_cnt[i] = 0;
}

__global__ void hist_kernel(const int* __restrict__ dst) {
    int e = blockIdx.x * blockDim.x + threadIdx.x;
    if (e < N_EDGES) atomicAdd(&g_cnt[dst[e]], 1);
}

__global__ void scan_kernel() {
    __shared__ int s[1024];
    __shared__ int s_carry;
    if (threadIdx.x == 0) s_carry = 0;
    __syncthreads();
    for (int base = 0; base < N_NODES; base += 1024) {
        int i = base + threadIdx.x;
        int v = (i < N_NODES) ? g_cnt[i] : 0;
        s[threadIdx.x] = v;
        __syncthreads();
        for (int d = 1; d < 1024; d <<= 1) {
            int t = 0;
            if ((int)threadIdx.x >= d) t = s[threadIdx.x - d];
            __syncthreads();
            s[threadIdx.x] += t;
            __syncthreads();
        }
        int incl = s[threadIdx.x] + s_carry;
        if (i < N_NODES) { g_off[i] = incl - v; g_cur[i] = incl - v; }
        __syncthreads();
        if (threadIdx.x == 1023) s_carry = incl;
        __syncthreads();
    }
    if (threadIdx.x == 0) g_off[N_NODES] = s_carry;
}

__global__ void scatter_kernel(const int* __restrict__ dst) {
    int e = blockIdx.x * blockDim.x + threadIdx.x;
    if (e < N_EDGES) {
        int d = dst[e];
        int pos = atomicAdd(&g_cur[d], 1);
        g_eid[pos] = e;
    }
}

// ---------------- weight transpose (W_ih/W_hh are [384][128] row-major) ----------------
__global__ void transpose_w_kernel(const float* __restrict__ Wih,
                                   const float* __restrict__ Whh) {
    int idx = blockIdx.x * blockDim.x + threadIdx.x;
    if (idx < 384 * 128) {
        int r = idx / 128, k = idx % 128;
        g_WihT[k * 384 + r] = Wih[idx];
        g_WhhT[k * 384 + r] = Whh[idx];
    }
}

// ---------------- generic tiled GEMM: out = act(X @ W + b), 64 rows x 128 cols / CTA ----------------
// ACT: 0 none, 1 leaky_relu(0.01), 2 elu
template <int K, int ACT>
__global__ __launch_bounds__(256) void gemm_kernel(
    const float* __restrict__ X, int ldx, int rows,
    const float* __restrict__ W, int ldw,
    const float* __restrict__ b,
    float* __restrict__ out, int ldo)
{
    extern __shared__ float sm[];
    float* sW = sm;                 // K*128
    float* sX = sW + K * 128;       // 64*K
    float* sB = sX + 64 * K;        // 128
    int t = threadIdx.x;
    int r0g = blockIdx.x * 64;

    for (int i = t; i < K * 128; i += 256) {
        int k = i >> 7, c = i & 127;
        sW[i] = W[(size_t)k * ldw + c];
    }
    for (int i = t; i < 64 * K; i += 256) {
        int r = i / K, k = i % K;
        int gr = r0g + r;
        sX[i] = (gr < rows) ? X[(size_t)gr * ldx + k] : 0.f;
    }
    if (t < 128) sB[t] = b[t];
    __syncthreads();

    int cx = t & 31, cy = t >> 5;
    int r0 = cy * 8, c0 = cx * 4;
    float acc[8][4] = {};
#pragma unroll 4
    for (int k = 0; k < K; k++) {
        float4 w = *(const float4*)&sW[k * 128 + c0];
#pragma unroll
        for (int r = 0; r < 8; r++) {
            float x = sX[(r0 + r) * K + k];
            acc[r][0] += x * w.x; acc[r][1] += x * w.y;
            acc[r][2] += x * w.z; acc[r][3] += x * w.w;
        }
    }
#pragma unroll
    for (int r = 0; r < 8; r++) {
        int gr = r0g + r0 + r;
        if (gr >= rows) break;
#pragma unroll
        for (int c = 0; c < 4; c++) {
            float v = acc[r][c] + sB[c0 + c];
            if (ACT == 1) v = leaky01(v);
            else if (ACT == 2) v = (v > 0.f) ? v : (expf(v) - 1.f);
            acc[r][c] = v;
        }
        float4 o = make_float4(acc[r][0], acc[r][1], acc[r][2], acc[r][3]);
        *(float4*)&out[(size_t)gr * ldo + c0] = o;
    }
}

// ---------------- per-node dot: hvdot[v] = h_v[v] . W_logit[0:128] ----------------
__global__ void hvdot_kernel(const float* __restrict__ Wl) {
    int w = (blockIdx.x * blockDim.x + threadIdx.x) >> 5;
    int lane = threadIdx.x & 31;
    if (w >= N_NODES) return;
    float s = 0.f;
#pragma unroll
    for (int q = 0; q < 4; q++)
        s += g_h_v[w * 128 + lane + 32 * q] * Wl[lane + 32 * q];
    for (int o = 16; o; o >>= 1) s += __shfl_xor_sync(0xffffffffu, s, o);
    if (lane == 0) g_hvdot[w] = s;
}

// ---------------- edge GEMM (gather concat) + logit, 64 edges x 128 cols / CTA ----------------
__global__ __launch_bounds__(256) void edge_kernel(
    const float* __restrict__ nf, const float* __restrict__ ef,
    const int* __restrict__ src,
    const float* __restrict__ W_edge, const float* __restrict__ b_edge,
    const float* __restrict__ W_logit, const float* __restrict__ b_logit)
{
    extern __shared__ float sm[];
    float* sW  = sm;              // 16384
    float* sX  = sW + 16384;      // 8192
    float* sWL = sX + 8192;       // 256
    float* sB  = sWL + 256;       // 128
    int*   sSrc = (int*)(sB + 128); // 64
    int t = threadIdx.x;
    int e0 = blockIdx.x * 64;

    if (t < 64) sSrc[t] = src[e0 + t];
    __syncthreads();

    const float4* W4 = (const float4*)W_edge;
    float4* sW4 = (float4*)sW;
    for (int i = t; i < 4096; i += 256) sW4[i] = W4[i];

    const float4* nf4 = (const float4*)nf;
    const float4* ef4 = (const float4*)ef;
    float4* sX4 = (float4*)sX;
    for (int i = t; i < 2048; i += 256) {
        int r = i >> 5, c4 = i & 31;
        float4 v;
        if (c4 < 16) v = nf4[(size_t)sSrc[r] * 16 + c4];
        else         v = ef4[(size_t)(e0 + r) * 16 + (c4 - 16)];
        sX4[i] = v;
    }
    if (t < 256) sWL[t] = W_logit[t];
    if (t < 128) sB[t] = b_edge[t];
    __syncthreads();

    int cx = t & 31, cy = t >> 5;
    int r0 = cy * 8, c0 = cx * 4;
    float acc[8][4] = {};
#pragma unroll 4
    for (int k = 0; k < 128; k++) {
        float4 w = *(const float4*)&sW[k * 128 + c0];
#pragma unroll
        for (int r = 0; r < 8; r++) {
            float x = sX[(r0 + r) * 128 + k];
            acc[r][0] += x * w.x; acc[r][1] += x * w.y;
            acc[r][2] += x * w.z; acc[r][3] += x * w.w;
        }
    }

    float bl = *b_logit;
#pragma unroll
    for (int r = 0; r < 8; r++) {
#pragma unroll
        for (int c = 0; c < 4; c++)
            acc[r][c] = leaky01(acc[r][c] + sB[c0 + c]);

        // logit = leaky( hvdot[src] + h_e . W_logit[128:256] + b_logit )
        float p = acc[r][0] * sWL[128 + c0]     + acc[r][1] * sWL[128 + c0 + 1]
                + acc[r][2] * sWL[128 + c0 + 2] + acc[r][3] * sWL[128 + c0 + 3];
        for (int o = 16; o; o >>= 1) p += __shfl_xor_sync(0xffffffffu, p, o);
        if (cx == 0) {
            float s = p + g_hvdot[sSrc[r0 + r]] + bl;
            g_logit[e0 + r0 + r] = leaky01(s);
        }
        float4 o4 = make_float4(acc[r][0], acc[r][1], acc[r][2], acc[r][3]);
        *(float4*)&g_h_e[(size_t)(e0 + r0 + r) * 128 + c0] = o4;
    }
}

// ---------------- per-node softmax + weighted sum (one warp / node) ----------------
__global__ void aggregate_kernel() {
    int v = (blockIdx.x * blockDim.x + threadIdx.x) >> 5;
    int lane = threadIdx.x & 31;
    if (v >= N_NODES) return;
    int s = g_off[v], e = g_off[v + 1];
    float mx = -1e30f;
    for (int i = s + lane; i < e; i += 32)
        mx = fmaxf(mx, g_logit[g_eid[i]]);
    for (int o = 16; o; o >>= 1)
        mx = fmaxf(mx, __shfl_xor_sync(0xffffffffu, mx, o));
    float4 acc = make_float4(0.f, 0.f, 0.f, 0.f);
    float den = 0.f;
    for (int i = s; i < e; i++) {
        int ed = g_eid[i];
        float w = expf(g_logit[ed] - mx);
        den += w;
        float4 h = *(const float4*)&g_h_e[(size_t)ed * 128 + lane * 4];
        acc.x += w * h.x; acc.y += w * h.y; acc.z += w * h.z; acc.w += w * h.w;
    }
    float inv = (e > s) ? 1.f / den : 0.f;
    acc.x *= inv; acc.y *= inv; acc.z *= inv; acc.w *= inv;
    *(float4*)&g_A[v * 128 + lane * 4] = acc;
}

// ---------------- GRU gates + relu ----------------
__global__ void gate_kernel(float* __restrict__ out) {
    int idx = blockIdx.x * blockDim.x + threadIdx.x;
    if (idx >= N_NODES * NHID) return;
    int n = idx >> 7, j = idx & 127;
    const float* gi = &g_gi[n * 384];
    const float* gh = &g_gh[n * 384];
    float r = 1.f / (1.f + expf(-(gi[j] + gh[j])));
    float z = 1.f / (1.f + expf(-(gi[128 + j] + gh[128 + j])));
    float nn = tanhf(gi[256 + j] + r * gh[256 + j]);
    float hv = g_h_v[idx];
    float h = (1.f - z) * nn + z * hv;
    out[idx] = h > 0.f ? h : 0.f;
}

// ---------------- edge_feats passthrough copy ----------------
__global__ void copy_kernel(const float4* __restrict__ s, float4* __restrict__ d, int n4) {
    int i = blockIdx.x * blockDim.x + threadIdx.x;
    if (i < n4) d[i] = s[i];
}

// ---------------- launch ----------------
extern "C" void kernel_launch(void* const* d_in, const int* in_sizes, int n_in,
                              void* d_out, int out_size) {
    const float* node_feats = (const float*)d_in[0];
    const float* edge_feats = (const float*)d_in[1];
    const float* W_node  = (const float*)d_in[2];
    const float* b_node  = (const float*)d_in[3];
    const float* W_edge  = (const float*)d_in[4];
    const float* b_edge  = (const float*)d_in[5];
    const float* W_logit = (const float*)d_in[6];
    const float* b_logit = (const float*)d_in[7];
    const float* W_msg   = (const float*)d_in[8];
    const float* b_msg   = (const float*)d_in[9];
    const float* W_ih    = (const float*)d_in[10];
    const float* W_hh    = (const float*)d_in[11];
    const float* b_ih    = (const float*)d_in[12];
    const float* b_hh    = (const float*)d_in[13];
    const int*   src     = (const int*)d_in[14];
    const int*   dst     = (const int*)d_in[15];
    float* out = (float*)d_out;

    // symbol addresses (host API, capture-safe, no allocation)
    float *p_h_v, *p_A, *p_cv, *p_gi, *p_gh, *p_WihT, *p_WhhT;
    cudaGetSymbolAddress((void**)&p_h_v, g_h_v);
    cudaGetSymbolAddress((void**)&p_A, g_A);
    cudaGetSymbolAddress((void**)&p_cv, g_cv);
    cudaGetSymbolAddress((void**)&p_gi, g_gi);
    cudaGetSymbolAddress((void**)&p_gh, g_gh);
    cudaGetSymbolAddress((void**)&p_WihT, g_WihT);
    cudaGetSymbolAddress((void**)&p_WhhT, g_WhhT);

    const int SM_EDGE   = (16384 + 8192 + 256 + 128 + 64 + 16) * 4;
    const int SM_G128   = (128 * 128 + 64 * 128 + 128) * 4;
    const int SM_G64    = (64 * 128 + 64 * 64 + 128) * 4;
    cudaFuncSetAttribute(edge_kernel, cudaFuncAttributeMaxDynamicSharedMemorySize, SM_EDGE);
    cudaFuncSetAttribute(gemm_kernel<64, 1>,  cudaFuncAttributeMaxDynamicSharedMemorySize, SM_G64);
    cudaFuncSetAttribute(gemm_kernel<128, 2>, cudaFuncAttributeMaxDynamicSharedMemorySize, SM_G128);
    cudaFuncSetAttribute(gemm_kernel<128, 0>, cudaFuncAttributeMaxDynamicSharedMemorySize, SM_G128);

    // CSR build
    zero_cnt_kernel<<<(N_NODES + 255) / 256, 256>>>();
    hist_kernel<<<(N_EDGES + 255) / 256, 256>>>(dst);
    scan_kernel<<<1, 1024>>>();
    scatter_kernel<<<(N_EDGES + 255) / 256, 256>>>(dst);

    // weight transpose for GRU
    transpose_w_kernel<<<(384 * 128 + 255) / 256, 256>>>(W_ih, W_hh);

    // node embed: h_v = leaky(nf @ W_node + b_node)
    int ntiles = (N_NODES + 63) / 64;
    gemm_kernel<64, 1><<<ntiles, 256, SM_G64>>>(node_feats, 64, N_NODES,
                                                W_node, 128, b_node, p_h_v, 128);
    // per-node logit half
    hvdot_kernel<<<(N_NODES + 7) / 8, 256>>>(W_logit);

    // edge embed + logits (dominant GEMM)
    edge_kernel<<<N_EDGES / 64, 256, SM_EDGE>>>(node_feats, edge_feats, src,
                                                W_edge, b_edge, W_logit, b_logit);

    // softmax-weighted segment sum
    aggregate_kernel<<<(N_NODES + 7) / 8, 256>>>();

    // C_v = elu(A @ W_msg + b_msg)
    gemm_kernel<128, 2><<<ntiles, 256, SM_G128>>>(p_A, 128, N_NODES,
                                                  W_msg, 128, b_msg, p_cv, 128);
    // gi = C_v @ W_ih^T + b_ih ; gh = h_v @ W_hh^T + b_hh  (3 chunks of 128 cols each)
    for (int g = 0; g < 3; g++) {
        gemm_kernel<128, 0><<<ntiles, 256, SM_G128>>>(p_cv, 128, N_NODES,
            p_WihT + g * 128, 384, b_ih + g * 128, p_gi + g * 128, 384);
        gemm_kernel<128, 0><<<ntiles, 256, SM_G128>>>(p_h_v, 128, N_NODES,
            p_WhhT + g * 128, 384, b_hh + g * 128, p_gh + g * 128, 384);
    }

    // gates -> h_new at out[0 : N*128)
    gate_kernel<<<(N_NODES * NHID + 255) / 256, 256>>>(out);

    // edge_feats passthrough at out[N*128 : )
    if (out_size >= N_NODES * NHID + N_EDGES * EFEAT) {
        int n4 = (N_EDGES * EFEAT) / 4;
        copy_kernel<<<(n4 + 255) / 256, 256>>>((const float4*)edge_feats,
                                               (float4*)(out + N_NODES * NHID), n4);
    }
}

// round 3
// speedup vs baseline: 1.7077x; 1.7077x over previous
#include <cuda_runtime.h>
#include <cuda_bf16.h>
#include <math.h>
#include <stdint.h>

#define N_NODES 10000
#define N_EDGES 640000
#define NHID    128
#define EHID    128
#define CSIZE   128

// ---------------- scratch (device globals; no allocation) ----------------
__device__ float g_h_v[N_NODES * NHID];
__device__ float g_hvdot[N_NODES];
__device__ float g_h_e[(size_t)N_EDGES * EHID];   // 327.68 MB
__device__ float g_logit[N_EDGES];
__device__ float g_A[N_NODES * EHID];
__device__ float g_cv[N_NODES * CSIZE];
__device__ float g_gi[N_NODES * 3 * NHID];
__device__ float g_gh[N_NODES * 3 * NHID];
__device__ float g_WihT[NHID * 3 * NHID];
__device__ float g_WhhT[NHID * 3 * NHID];
__device__ int   g_cnt[N_NODES];
__device__ int   g_off[N_NODES + 1];
__device__ int   g_cur[N_NODES];
__device__ int   g_eid[N_EDGES];
// B operand image: [hi | lo], each [n=128][k stride 136] bf16  (W_edge^T split)
#define A_STRIDE 136
__device__ __nv_bfloat16 g_B[2 * 128 * A_STRIDE];

__device__ __forceinline__ float leaky01(float v) { return v > 0.f ? v : 0.01f * v; }

__device__ __forceinline__ uint32_t smem_u32(const void* p) {
    uint32_t a;
    asm("{ .reg .u64 t; cvta.to.shared.u64 t, %1; cvt.u32.u64 %0, t; }" : "=r"(a) : "l"(p));
    return a;
}
__device__ __forceinline__ void ldsm_x4(uint32_t* r, uint32_t addr) {
    asm volatile("ldmatrix.sync.aligned.m8n8.x4.shared.b16 {%0,%1,%2,%3}, [%4];"
        : "=r"(r[0]), "=r"(r[1]), "=r"(r[2]), "=r"(r[3]) : "r"(addr));
}
__device__ __forceinline__ void mma_bf16(float* c, const uint32_t* a, const uint32_t* b) {
    asm volatile("mma.sync.aligned.m16n8k16.row.col.f32.bf16.bf16.f32 "
        "{%0,%1,%2,%3}, {%4,%5,%6,%7}, {%8,%9}, {%0,%1,%2,%3};"
        : "+f"(c[0]), "+f"(c[1]), "+f"(c[2]), "+f"(c[3])
        : "r"(a[0]), "r"(a[1]), "r"(a[2]), "r"(a[3]), "r"(b[0]), "r"(b[1]));
}

// ---------------- CSR build ----------------
__global__ void hist_kernel(const int* __restrict__ dst) {
    int e = blockIdx.x * blockDim.x + threadIdx.x;
    if (e < N_EDGES) atomicAdd(&g_cnt[dst[e]], 1);
}
__global__ void scan_kernel() {
    __shared__ int s[1024];
    __shared__ int s_carry;
    if (threadIdx.x == 0) s_carry = 0;
    __syncthreads();
    for (int base = 0; base < N_NODES; base += 1024) {
        int i = base + threadIdx.x;
        int v = (i < N_NODES) ? g_cnt[i] : 0;
        s[threadIdx.x] = v;
        __syncthreads();
        for (int d = 1; d < 1024; d <<= 1) {
            int t = 0;
            if ((int)threadIdx.x >= d) t = s[threadIdx.x - d];
            __syncthreads();
            s[threadIdx.x] += t;
            __syncthreads();
        }
        int incl = s[threadIdx.x] + s_carry;
        if (i < N_NODES) { g_off[i] = incl - v; g_cur[i] = incl - v; }
        __syncthreads();
        if (threadIdx.x == 1023) s_carry = incl;
        __syncthreads();
    }
    if (threadIdx.x == 0) g_off[N_NODES] = s_carry;
}
__global__ void scatter_kernel(const int* __restrict__ dst) {
    int e = blockIdx.x * blockDim.x + threadIdx.x;
    if (e < N_EDGES) {
        int pos = atomicAdd(&g_cur[dst[e]], 1);
        g_eid[pos] = e;
    }
}

// ---------------- weight prep ----------------
__global__ void transpose_w_kernel(const float* __restrict__ Wih, const float* __restrict__ Whh) {
    int idx = blockIdx.x * blockDim.x + threadIdx.x;
    if (idx < 384 * 128) {
        int r = idx / 128, k = idx % 128;
        g_WihT[k * 384 + r] = Wih[idx];
        g_WhhT[k * 384 + r] = Whh[idx];
    }
}
// Split W_edge into bf16 hi/lo, transposed to B[n][k] = W[k][n], padded stride 136.
__global__ void bprep_kernel(const float* __restrict__ W) {
    int idx = blockIdx.x * blockDim.x + threadIdx.x;   // (n, kpair)
    if (idx >= 128 * 64) return;
    int n = idx >> 6, k = (idx & 63) * 2;
    float x0 = W[k * 128 + n], x1 = W[(k + 1) * 128 + n];
    __nv_bfloat162 h = __floats2bfloat162_rn(x0, x1);
    float2 hf = __bfloat1622float2(h);
    __nv_bfloat162 l = __floats2bfloat162_rn(x0 - hf.x, x1 - hf.y);
    *(uint32_t*)&g_B[n * A_STRIDE + k] = *(uint32_t*)&h;
    *(uint32_t*)&g_B[128 * A_STRIDE + n * A_STRIDE + k] = *(uint32_t*)&l;
}

// ---------------- generic tiled GEMM: out = act(X @ W + b), 64x128 tile ----------------
template <int K, int ACT>
__global__ __launch_bounds__(256) void gemm_kernel(
    const float* __restrict__ X, int ldx, int rows,
    const float* __restrict__ W, int ldw,
    const float* __restrict__ b,
    float* __restrict__ out, int ldo)
{
    extern __shared__ float sm[];
    float* sW = sm;
    float* sX = sW + K * 128;
    float* sB = sX + 64 * K;
    int t = threadIdx.x;
    int r0g = blockIdx.x * 64;
    for (int i = t; i < K * 128; i += 256) {
        int k = i >> 7, c = i & 127;
        sW[i] = W[(size_t)k * ldw + c];
    }
    for (int i = t; i < 64 * K; i += 256) {
        int r = i / K, k = i % K;
        int gr = r0g + r;
        sX[i] = (gr < rows) ? X[(size_t)gr * ldx + k] : 0.f;
    }
    if (t < 128) sB[t] = b[t];
    __syncthreads();
    int cx = t & 31, cy = t >> 5;
    int r0 = cy * 8, c0 = cx * 4;
    float acc[8][4] = {};
#pragma unroll 4
    for (int k = 0; k < K; k++) {
        float4 w = *(const float4*)&sW[k * 128 + c0];
#pragma unroll
        for (int r = 0; r < 8; r++) {
            float x = sX[(r0 + r) * K + k];
            acc[r][0] += x * w.x; acc[r][1] += x * w.y;
            acc[r][2] += x * w.z; acc[r][3] += x * w.w;
        }
    }
#pragma unroll
    for (int r = 0; r < 8; r++) {
        int gr = r0g + r0 + r;
        if (gr >= rows) break;
#pragma unroll
        for (int c = 0; c < 4; c++) {
            float v = acc[r][c] + sB[c0 + c];
            if (ACT == 1) v = leaky01(v);
            else if (ACT == 2) v = (v > 0.f) ? v : (expf(v) - 1.f);
            acc[r][c] = v;
        }
        *(float4*)&out[(size_t)gr * ldo + c0] = make_float4(acc[r][0], acc[r][1], acc[r][2], acc[r][3]);
    }
}

// ---------------- fused GRU GEMMs: one launch, blockIdx.y selects (mat, chunk) ----------------
__global__ __launch_bounds__(256) void gru_gemm_kernel(const float* __restrict__ b_ih,
                                                       const float* __restrict__ b_hh)
{
    extern __shared__ float sm[];
    float* sW = sm;
    float* sX = sW + 128 * 128;
    float* sB = sX + 64 * 128;
    int mat = blockIdx.y / 3, chunk = blockIdx.y % 3;
    const float* X = mat ? g_h_v : g_cv;
    const float* W = (mat ? g_WhhT : g_WihT) + chunk * 128;
    const float* b = (mat ? b_hh : b_ih) + chunk * 128;
    float* out = (mat ? g_gh : g_gi) + chunk * 128;
    int t = threadIdx.x;
    int r0g = blockIdx.x * 64;
    for (int i = t; i < 128 * 128; i += 256) {
        int k = i >> 7, c = i & 127;
        sW[i] = W[k * 384 + c];
    }
    for (int i = t; i < 64 * 128; i += 256) {
        int r = i >> 7, k = i & 127;
        int gr = r0g + r;
        sX[i] = (gr < N_NODES) ? X[gr * 128 + k] : 0.f;
    }
    if (t < 128) sB[t] = b[t];
    __syncthreads();
    int cx = t & 31, cy = t >> 5;
    int r0 = cy * 8, c0 = cx * 4;
    float acc[8][4] = {};
#pragma unroll 4
    for (int k = 0; k < 128; k++) {
        float4 w = *(const float4*)&sW[k * 128 + c0];
#pragma unroll
        for (int r = 0; r < 8; r++) {
            float x = sX[(r0 + r) * 128 + k];
            acc[r][0] += x * w.x; acc[r][1] += x * w.y;
            acc[r][2] += x * w.z; acc[r][3] += x * w.w;
        }
    }
#pragma unroll
    for (int r = 0; r < 8; r++) {
        int gr = r0g + r0 + r;
        if (gr >= N_NODES) break;
        *(float4*)&out[(size_t)gr * 384 + c0] = make_float4(
            acc[r][0] + sB[c0], acc[r][1] + sB[c0 + 1], acc[r][2] + sB[c0 + 2], acc[r][3] + sB[c0 + 3]);
    }
}

// ---------------- per-node dot: hvdot[v] = h_v[v] . W_logit[0:128] ----------------
__global__ void hvdot_kernel(const float* __restrict__ Wl) {
    int w = (blockIdx.x * blockDim.x + threadIdx.x) >> 5;
    int lane = threadIdx.x & 31;
    if (w >= N_NODES) return;
    float s = 0.f;
#pragma unroll
    for (int q = 0; q < 4; q++)
        s += g_h_v[w * 128 + lane + 32 * q] * Wl[lane + 32 * q];
    for (int o = 16; o; o >>= 1) s += __shfl_xor_sync(0xffffffffu, s, o);
    if (lane == 0) g_hvdot[w] = s;
}

// ============ edge GEMM on mma.sync (HMMA): 128 edges x 128 cols, K=128, bf16 split ============
#define SM_SRC   0
#define SM_BIAS  512
#define SM_WL    1024
#define SM_LOG   1536
#define SM_AHI   2560
#define SM_ALO   (SM_AHI + 34816)
#define SM_BHI   (SM_ALO + 34816)
#define SM_BLO   (SM_BHI + 34816)
#define SM_EDGE_TOTAL (SM_BLO + 34816)

__global__ __launch_bounds__(256)
void edge_mma_kernel(const float* __restrict__ nf, const float* __restrict__ ef,
                     const int* __restrict__ src,
                     const float* __restrict__ b_edge,
                     const float* __restrict__ W_logit, const float* __restrict__ b_logit)
{
    extern __shared__ __align__(16) char smem[];
    uint32_t sb = smem_u32(smem);
    int t = threadIdx.x, lane = t & 31, wid = t >> 5;
    int e0 = blockIdx.x * 128;
    int* sSrc = (int*)(smem + SM_SRC);
    float* sBias = (float*)(smem + SM_BIAS);
    float* sWL = (float*)(smem + SM_WL);
    float* sLog = (float*)(smem + SM_LOG);

    if (t < 128) {
        sSrc[t] = src[e0 + t];
        sBias[t] = b_edge[t];
        sWL[t] = W_logit[128 + t];
    }
    // copy B image (hi+lo, 68KB) from global (L2-hot)
    {
        const float4* bs = (const float4*)g_B;
        float4* bd = (float4*)(smem + SM_BHI);
#pragma unroll
        for (int i = 0; i < 17; i++) bd[t + 256 * i] = bs[t + 256 * i];
    }
    __syncthreads();

    // A gather/split: row r from [nf[src[r]] | ef[e0+r]], bf16 hi/lo
    {
        int r = t >> 1, hf = t & 1;
        const float4* xp = hf ? (const float4*)(ef + (size_t)(e0 + r) * 64)
                              : (const float4*)(nf + (size_t)sSrc[r] * 64);
        char* hi = smem + SM_AHI + r * (A_STRIDE * 2) + hf * 128;
        char* lo = smem + SM_ALO + r * (A_STRIDE * 2) + hf * 128;
#pragma unroll
        for (int j = 0; j < 16; j++) {
            float4 v = xp[j];
            __nv_bfloat162 h01 = __floats2bfloat162_rn(v.x, v.y);
            __nv_bfloat162 h23 = __floats2bfloat162_rn(v.z, v.w);
            float2 f01 = __bfloat1622float2(h01);
            float2 f23 = __bfloat1622float2(h23);
            __nv_bfloat162 l01 = __floats2bfloat162_rn(v.x - f01.x, v.y - f01.y);
            __nv_bfloat162 l23 = __floats2bfloat162_rn(v.z - f23.x, v.w - f23.y);
            *(uint2*)(hi + j * 8) = make_uint2(*(uint32_t*)&h01, *(uint32_t*)&h23);
            *(uint2*)(lo + j * 8) = make_uint2(*(uint32_t*)&l01, *(uint32_t*)&l23);
        }
    }
    __syncthreads();

    // warp tile: M=32 (mg), N=64 (ng)
    int mg = wid & 3, ng = wid >> 2;
    int m0 = mg * 32, n0 = ng * 64;
    float acc[2][8][4];
#pragma unroll
    for (int i = 0; i < 2; i++)
#pragma unroll
        for (int j = 0; j < 8; j++)
#pragma unroll
            for (int c = 0; c < 4; c++) acc[i][j][c] = 0.f;

    // per-lane byte offsets within a tile for ldmatrix
    uint32_t aOffL = ((lane & 15) * A_STRIDE + (lane >> 4) * 8) * 2;
    uint32_t bOffL = (((lane & 7) + ((lane >> 4) << 3)) * A_STRIDE + ((lane >> 3) & 1) * 8) * 2;

#pragma unroll
    for (int p = 0; p < 3; p++) {
        uint32_t Ab = sb + (p == 1 ? SM_ALO : SM_AHI);
        uint32_t Bb = sb + (p == 2 ? SM_BLO : SM_BHI);
#pragma unroll
        for (int k8 = 0; k8 < 8; k8++) {
            uint32_t kb = k8 * 32;   // 16 halves
            uint32_t a[2][4], b[4][4];
            ldsm_x4(a[0], Ab + aOffL + (uint32_t)m0 * 272 + kb);
            ldsm_x4(a[1], Ab + aOffL + (uint32_t)(m0 + 16) * 272 + kb);
#pragma unroll
            for (int q = 0; q < 4; q++)
                ldsm_x4(b[q], Bb + bOffL + (uint32_t)(n0 + q * 16) * 272 + kb);
#pragma unroll
            for (int ms = 0; ms < 2; ms++)
#pragma unroll
                for (int q = 0; q < 4; q++) {
                    mma_bf16(acc[ms][q * 2],     a[ms], &b[q][0]);
                    mma_bf16(acc[ms][q * 2 + 1], a[ms], &b[q][2]);
                }
        }
    }

    // epilogue: bias + leaky + store h_e + partial logit
#pragma unroll
    for (int ms = 0; ms < 2; ms++) {
        int r1 = m0 + ms * 16 + (lane >> 2);
        int r2 = r1 + 8;
        float lg1 = 0.f, lg2 = 0.f;
        float* o1 = g_h_e + (size_t)(e0 + r1) * 128;
        float* o2 = g_h_e + (size_t)(e0 + r2) * 128;
#pragma unroll
        for (int ns = 0; ns < 8; ns++) {
            int col = n0 + ns * 8 + (lane & 3) * 2;
            float v0 = leaky01(acc[ms][ns][0] + sBias[col]);
            float v1 = leaky01(acc[ms][ns][1] + sBias[col + 1]);
            float v2 = leaky01(acc[ms][ns][2] + sBias[col]);
            float v3 = leaky01(acc[ms][ns][3] + sBias[col + 1]);
            lg1 += v0 * sWL[col] + v1 * sWL[col + 1];
            lg2 += v2 * sWL[col] + v3 * sWL[col + 1];
            *(float2*)(o1 + col) = make_float2(v0, v1);
            *(float2*)(o2 + col) = make_float2(v2, v3);
        }
        lg1 += __shfl_xor_sync(0xffffffffu, lg1, 1);
        lg1 += __shfl_xor_sync(0xffffffffu, lg1, 2);
        lg2 += __shfl_xor_sync(0xffffffffu, lg2, 1);
        lg2 += __shfl_xor_sync(0xffffffffu, lg2, 2);
        if ((lane & 3) == 0) {
            sLog[r1 * 2 + ng] = lg1;
            sLog[r2 * 2 + ng] = lg2;
        }
    }
    __syncthreads();
    if (t < 128) {
        float s = sLog[t * 2] + sLog[t * 2 + 1] + g_hvdot[sSrc[t]] + b_logit[0];
        g_logit[e0 + t] = leaky01(s);
    }
}

// ---------------- per-node softmax + weighted sum (one warp / node) ----------------
__global__ void aggregate_kernel() {
    int v = (blockIdx.x * blockDim.x + threadIdx.x) >> 5;
    int lane = threadIdx.x & 31;
    if (v >= N_NODES) return;
    int s = g_off[v], e = g_off[v + 1];
    float mx = -1e30f;
    for (int i = s + lane; i < e; i += 32)
        mx = fmaxf(mx, g_logit[g_eid[i]]);
    for (int o = 16; o; o >>= 1)
        mx = fmaxf(mx, __shfl_xor_sync(0xffffffffu, mx, o));
    float4 acc = make_float4(0.f, 0.f, 0.f, 0.f);
    float den = 0.f;
    for (int i = s; i < e; i++) {
        int ed = g_eid[i];
        float w = expf(g_logit[ed] - mx);
        den += w;
        float4 h = *(const float4*)&g_h_e[(size_t)ed * 128 + lane * 4];
        acc.x += w * h.x; acc.y += w * h.y; acc.z += w * h.z; acc.w += w * h.w;
    }
    float inv = (e > s) ? 1.f / den : 0.f;
    acc.x *= inv; acc.y *= inv; acc.z *= inv; acc.w *= inv;
    *(float4*)&g_A[v * 128 + lane * 4] = acc;
}

// ---------------- GRU gates + relu ----------------
__global__ void gate_kernel(float* __restrict__ out) {
    int idx = blockIdx.x * blockDim.x + threadIdx.x;
    if (idx >= N_NODES * NHID) return;
    int n = idx >> 7, j = idx & 127;
    const float* gi = &g_gi[n * 384];
    const float* gh = &g_gh[n * 384];
    float r = 1.f / (1.f + expf(-(gi[j] + gh[j])));
    float z = 1.f / (1.f + expf(-(gi[128 + j] + gh[128 + j])));
    float nn = tanhf(gi[256 + j] + r * gh[256 + j]);
    float hv = g_h_v[idx];
    float h = (1.f - z) * nn + z * hv;
    out[idx] = h > 0.f ? h : 0.f;
}

__global__ void copy_kernel(const float4* __restrict__ s, float4* __restrict__ d, int n4) {
    int i = blockIdx.x * blockDim.x + threadIdx.x;
    if (i < n4) d[i] = s[i];
}

// ---------------- launch ----------------
extern "C" void kernel_launch(void* const* d_in, const int* in_sizes, int n_in,
                              void* d_out, int out_size) {
    const float* node_feats = (const float*)d_in[0];
    const float* edge_feats = (const float*)d_in[1];
    const float* W_node  = (const float*)d_in[2];
    const float* b_node  = (const float*)d_in[3];
    const float* W_edge  = (const float*)d_in[4];
    const float* b_edge  = (const float*)d_in[5];
    const float* W_logit = (const float*)d_in[6];
    const float* b_logit = (const float*)d_in[7];
    const float* W_msg   = (const float*)d_in[8];
    const float* b_msg   = (const float*)d_in[9];
    const float* W_ih    = (const float*)d_in[10];
    const float* W_hh    = (const float*)d_in[11];
    const float* b_ih    = (const float*)d_in[12];
    const float* b_hh    = (const float*)d_in[13];
    const int*   src     = (const int*)d_in[14];
    const int*   dst     = (const int*)d_in[15];
    float* out = (float*)d_out;

    float *p_h_v, *p_A, *p_cv;
    int* p_cnt;
    cudaGetSymbolAddress((void**)&p_h_v, g_h_v);
    cudaGetSymbolAddress((void**)&p_A, g_A);
    cudaGetSymbolAddress((void**)&p_cv, g_cv);
    cudaGetSymbolAddress((void**)&p_cnt, g_cnt);

    const int SM_G128 = (128 * 128 + 64 * 128 + 128) * 4;
    const int SM_G64  = (64 * 128 + 64 * 64 + 128) * 4;
    cudaFuncSetAttribute(edge_mma_kernel, cudaFuncAttributeMaxDynamicSharedMemorySize, SM_EDGE_TOTAL);
    cudaFuncSetAttribute(gemm_kernel<64, 1>,  cudaFuncAttributeMaxDynamicSharedMemorySize, SM_G64);
    cudaFuncSetAttribute(gemm_kernel<128, 2>, cudaFuncAttributeMaxDynamicSharedMemorySize, SM_G128);
    cudaFuncSetAttribute(gru_gemm_kernel, cudaFuncAttributeMaxDynamicSharedMemorySize, SM_G128);

    // CSR build
    cudaMemsetAsync(p_cnt, 0, N_NODES * sizeof(int));
    hist_kernel<<<(N_EDGES + 255) / 256, 256>>>(dst);
    scan_kernel<<<1, 1024>>>();
    scatter_kernel<<<(N_EDGES + 255) / 256, 256>>>(dst);

    // weight prep
    transpose_w_kernel<<<(384 * 128 + 255) / 256, 256>>>(W_ih, W_hh);
    bprep_kernel<<<(128 * 64 + 255) / 256, 256>>>(W_edge);

    // node embed: h_v = leaky(nf @ W_node + b_node)
    int ntiles = (N_NODES + 63) / 64;
    gemm_kernel<64, 1><<<ntiles, 256, SM_G64>>>(node_feats, 64, N_NODES,
                                                W_node, 128, b_node, p_h_v, 128);
    hvdot_kernel<<<(N_NODES + 7) / 8, 256>>>(W_logit);

    // edge embed + logits on tensor cores (HMMA)
    edge_mma_kernel<<<N_EDGES / 128, 256, SM_EDGE_TOTAL>>>(node_feats, edge_feats, src,
                                                           b_edge, W_logit, b_logit);

    // softmax-weighted segment sum
    aggregate_kernel<<<(N_NODES + 7) / 8, 256>>>();

    // C_v = elu(A @ W_msg + b_msg)
    gemm_kernel<128, 2><<<ntiles, 256, SM_G128>>>(p_A, 128, N_NODES,
                                                  W_msg, 128, b_msg, p_cv, 128);
    // gi / gh in one launch
    gru_gemm_kernel<<<dim3(ntiles, 6), 256, SM_G128>>>(b_ih, b_hh);

    // gates -> h_new
    gate_kernel<<<(N_NODES * NHID + 255) / 256, 256>>>(out);

    // edge_feats passthrough
    if (out_size >= N_NODES * NHID + N_EDGES * 64) {
        int n4 = (N_EDGES * 64) / 4;
        copy_kernel<<<(n4 + 255) / 256, 256>>>((const float4*)edge_feats,
                                               (float4*)(out + N_NODES * NHID), n4);
    }
}

// round 4
// speedup vs baseline: 1.7425x; 1.0204x over previous
#include <cuda_runtime.h>
#include <cuda_bf16.h>
#include <math.h>
#include <stdint.h>

#define N_NODES 10000
#define N_EDGES 640000
#define NHID    128
#define EHID    128
#define CSIZE   128

// ---------------- scratch (device globals; no allocation) ----------------
__device__ float g_h_v[N_NODES * NHID];
__device__ float g_hvdot[N_NODES];
__device__ float g_h_e[(size_t)N_EDGES * EHID];   // CSR-ordered rows
__device__ float g_logit[N_EDGES];                // CSR-ordered
__device__ float g_A[N_NODES * EHID];
__device__ float g_cv[N_NODES * CSIZE];
__device__ float g_gi[N_NODES * 3 * NHID];
__device__ float g_gh[N_NODES * 3 * NHID];
__device__ float g_WihT[NHID * 3 * NHID];
__device__ float g_WhhT[NHID * 3 * NHID];
__device__ int   g_cnt[N_NODES];
__device__ int   g_off[N_NODES + 1];
__device__ int   g_cur[N_NODES];
__device__ int   g_perm[N_EDGES];                 // edge -> CSR slot
// B operand image: [hi | lo], each [n=128][k stride 136] bf16  (W_edge^T split)
#define A_STRIDE 136
__device__ __nv_bfloat16 g_B[2 * 128 * A_STRIDE];

__device__ __forceinline__ float leaky01(float v) { return v > 0.f ? v : 0.01f * v; }

__device__ __forceinline__ uint32_t smem_u32(const void* p) {
    uint32_t a;
    asm("{ .reg .u64 t; cvta.to.shared.u64 t, %1; cvt.u32.u64 %0, t; }" : "=r"(a) : "l"(p));
    return a;
}
__device__ __forceinline__ void ldsm_x4(uint32_t* r, uint32_t addr) {
    asm volatile("ldmatrix.sync.aligned.m8n8.x4.shared.b16 {%0,%1,%2,%3}, [%4];"
        : "=r"(r[0]), "=r"(r[1]), "=r"(r[2]), "=r"(r[3]) : "r"(addr));
}
__device__ __forceinline__ void mma_bf16(float* c, const uint32_t* a, const uint32_t* b) {
    asm volatile("mma.sync.aligned.m16n8k16.row.col.f32.bf16.bf16.f32 "
        "{%0,%1,%2,%3}, {%4,%5,%6,%7}, {%8,%9}, {%0,%1,%2,%3};"
        : "+f"(c[0]), "+f"(c[1]), "+f"(c[2]), "+f"(c[3])
        : "r"(a[0]), "r"(a[1]), "r"(a[2]), "r"(a[3]), "r"(b[0]), "r"(b[1]));
}

// ---------------- CSR build ----------------
__global__ void hist_kernel(const int* __restrict__ dst) {
    int e = blockIdx.x * blockDim.x + threadIdx.x;
    if (e < N_EDGES) atomicAdd(&g_cnt[dst[e]], 1);
}
__global__ void scan_kernel() {
    __shared__ int s[1024];
    __shared__ int s_carry;
    if (threadIdx.x == 0) s_carry = 0;
    __syncthreads();
    for (int base = 0; base < N_NODES; base += 1024) {
        int i = base + threadIdx.x;
        int v = (i < N_NODES) ? g_cnt[i] : 0;
        s[threadIdx.x] = v;
        __syncthreads();
        for (int d = 1; d < 1024; d <<= 1) {
            int t = 0;
            if ((int)threadIdx.x >= d) t = s[threadIdx.x - d];
            __syncthreads();
            s[threadIdx.x] += t;
            __syncthreads();
        }
        int incl = s[threadIdx.x] + s_carry;
        if (i < N_NODES) { g_off[i] = incl - v; g_cur[i] = incl - v; }
        __syncthreads();
        if (threadIdx.x == 1023) s_carry = incl;
        __syncthreads();
    }
    if (threadIdx.x == 0) g_off[N_NODES] = s_carry;
}
__global__ void perm_kernel(const int* __restrict__ dst) {
    int e = blockIdx.x * blockDim.x + threadIdx.x;
    if (e < N_EDGES) g_perm[e] = atomicAdd(&g_cur[dst[e]], 1);
}

// ---------------- weight prep ----------------
__global__ void transpose_w_kernel(const float* __restrict__ Wih, const float* __restrict__ Whh) {
    int idx = blockIdx.x * blockDim.x + threadIdx.x;
    if (idx < 384 * 128) {
        int r = idx / 128, k = idx % 128;
        g_WihT[k * 384 + r] = Wih[idx];
        g_WhhT[k * 384 + r] = Whh[idx];
    }
}
__global__ void bprep_kernel(const float* __restrict__ W) {
    int idx = blockIdx.x * blockDim.x + threadIdx.x;   // (n, kpair)
    if (idx >= 128 * 64) return;
    int n = idx >> 6, k = (idx & 63) * 2;
    float x0 = W[k * 128 + n], x1 = W[(k + 1) * 128 + n];
    __nv_bfloat162 h = __floats2bfloat162_rn(x0, x1);
    float2 hf = __bfloat1622float2(h);
    __nv_bfloat162 l = __floats2bfloat162_rn(x0 - hf.x, x1 - hf.y);
    *(uint32_t*)&g_B[n * A_STRIDE + k] = *(uint32_t*)&h;
    *(uint32_t*)&g_B[128 * A_STRIDE + n * A_STRIDE + k] = *(uint32_t*)&l;
}

// ---------------- generic tiled GEMM: out = act(X @ W + b), 64x128 tile ----------------
template <int K, int ACT>
__global__ __launch_bounds__(256) void gemm_kernel(
    const float* __restrict__ X, int ldx, int rows,
    const float* __restrict__ W, int ldw,
    const float* __restrict__ b,
    float* __restrict__ out, int ldo)
{
    extern __shared__ float sm[];
    float* sW = sm;
    float* sX = sW + K * 128;
    float* sB = sX + 64 * K;
    int t = threadIdx.x;
    int r0g = blockIdx.x * 64;
    for (int i = t; i < K * 128; i += 256) {
        int k = i >> 7, c = i & 127;
        sW[i] = W[(size_t)k * ldw + c];
    }
    for (int i = t; i < 64 * K; i += 256) {
        int r = i / K, k = i % K;
        int gr = r0g + r;
        sX[i] = (gr < rows) ? X[(size_t)gr * ldx + k] : 0.f;
    }
    if (t < 128) sB[t] = b[t];
    __syncthreads();
    int cx = t & 31, cy = t >> 5;
    int r0 = cy * 8, c0 = cx * 4;
    float acc[8][4] = {};
#pragma unroll 4
    for (int k = 0; k < K; k++) {
        float4 w = *(const float4*)&sW[k * 128 + c0];
#pragma unroll
        for (int r = 0; r < 8; r++) {
            float x = sX[(r0 + r) * K + k];
            acc[r][0] += x * w.x; acc[r][1] += x * w.y;
            acc[r][2] += x * w.z; acc[r][3] += x * w.w;
        }
    }
#pragma unroll
    for (int r = 0; r < 8; r++) {
        int gr = r0g + r0 + r;
        if (gr >= rows) break;
#pragma unroll
        for (int c = 0; c < 4; c++) {
            float v = acc[r][c] + sB[c0 + c];
            if (ACT == 1) v = leaky01(v);
            else if (ACT == 2) v = (v > 0.f) ? v : (expf(v) - 1.f);
            acc[r][c] = v;
        }
        *(float4*)&out[(size_t)gr * ldo + c0] = make_float4(acc[r][0], acc[r][1], acc[r][2], acc[r][3]);
    }
}

// ---------------- fused GRU GEMMs: one launch, blockIdx.y selects (mat, chunk) ----------------
__global__ __launch_bounds__(256) void gru_gemm_kernel(const float* __restrict__ b_ih,
                                                       const float* __restrict__ b_hh)
{
    extern __shared__ float sm[];
    float* sW = sm;
    float* sX = sW + 128 * 128;
    float* sB = sX + 64 * 128;
    int mat = blockIdx.y / 3, chunk = blockIdx.y % 3;
    const float* X = mat ? g_h_v : g_cv;
    const float* W = (mat ? g_WhhT : g_WihT) + chunk * 128;
    const float* b = (mat ? b_hh : b_ih) + chunk * 128;
    float* out = (mat ? g_gh : g_gi) + chunk * 128;
    int t = threadIdx.x;
    int r0g = blockIdx.x * 64;
    for (int i = t; i < 128 * 128; i += 256) {
        int k = i >> 7, c = i & 127;
        sW[i] = W[k * 384 + c];
    }
    for (int i = t; i < 64 * 128; i += 256) {
        int r = i >> 7, k = i & 127;
        int gr = r0g + r;
        sX[i] = (gr < N_NODES) ? X[gr * 128 + k] : 0.f;
    }
    if (t < 128) sB[t] = b[t];
    __syncthreads();
    int cx = t & 31, cy = t >> 5;
    int r0 = cy * 8, c0 = cx * 4;
    float acc[8][4] = {};
#pragma unroll 4
    for (int k = 0; k < 128; k++) {
        float4 w = *(const float4*)&sW[k * 128 + c0];
#pragma unroll
        for (int r = 0; r < 8; r++) {
            float x = sX[(r0 + r) * 128 + k];
            acc[r][0] += x * w.x; acc[r][1] += x * w.y;
            acc[r][2] += x * w.z; acc[r][3] += x * w.w;
        }
    }
#pragma unroll
    for (int r = 0; r < 8; r++) {
        int gr = r0g + r0 + r;
        if (gr >= N_NODES) break;
        *(float4*)&out[(size_t)gr * 384 + c0] = make_float4(
            acc[r][0] + sB[c0], acc[r][1] + sB[c0 + 1], acc[r][2] + sB[c0 + 2], acc[r][3] + sB[c0 + 3]);
    }
}

// ---------------- per-node dot: hvdot[v] = h_v[v] . W_logit[0:128] ----------------
__global__ void hvdot_kernel(const float* __restrict__ Wl) {
    int w = (blockIdx.x * blockDim.x + threadIdx.x) >> 5;
    int lane = threadIdx.x & 31;
    if (w >= N_NODES) return;
    float s = 0.f;
#pragma unroll
    for (int q = 0; q < 4; q++)
        s += g_h_v[w * 128 + lane + 32 * q] * Wl[lane + 32 * q];
    for (int o = 16; o; o >>= 1) s += __shfl_xor_sync(0xffffffffu, s, o);
    if (lane == 0) g_hvdot[w] = s;
}

// ============ edge GEMM on HMMA: 128 edges x 128 cols, K=128, bf16 split ============
// Writes h_e + logit to CSR slots (perm), and streams ef rows to the output tail.
#define SM_SRC   0
#define SM_PERM  512
#define SM_BIAS  1024
#define SM_WL    1536
#define SM_LOG   2048
#define SM_AHI   3072
#define SM_ALO   (SM_AHI + 34816)
#define SM_BHI   (SM_ALO + 34816)
#define SM_BLO   (SM_BHI + 34816)
#define SM_EDGE_TOTAL (SM_BLO + 34816)

__global__ __launch_bounds__(256)
void edge_mma_kernel(const float* __restrict__ nf, const float* __restrict__ ef,
                     const int* __restrict__ src,
                     const float* __restrict__ b_edge,
                     const float* __restrict__ W_logit, const float* __restrict__ b_logit,
                     float* __restrict__ outEF)
{
    extern __shared__ __align__(16) char smem[];
    uint32_t sb = smem_u32(smem);
    int t = threadIdx.x, lane = t & 31, wid = t >> 5;
    int e0 = blockIdx.x * 128;
    int* sSrc = (int*)(smem + SM_SRC);
    int* sPerm = (int*)(smem + SM_PERM);
    float* sBias = (float*)(smem + SM_BIAS);
    float* sWL = (float*)(smem + SM_WL);
    float* sLog = (float*)(smem + SM_LOG);

    if (t < 128) {
        sSrc[t] = src[e0 + t];
        sPerm[t] = g_perm[e0 + t];
        sBias[t] = b_edge[t];
        sWL[t] = W_logit[128 + t];
    }
    // copy B image (hi+lo, 68KB) from global (L2-hot)
    {
        const float4* bs = (const float4*)g_B;
        float4* bd = (float4*)(smem + SM_BHI);
#pragma unroll
        for (int i = 0; i < 17; i++) bd[t + 256 * i] = bs[t + 256 * i];
    }
    __syncthreads();

    // A gather/split: row r from [nf[src[r]] | ef[e0+r]], bf16 hi/lo.
    // hf==1 threads also stream the ef row to the output passthrough region.
    {
        int r = t >> 1, hf = t & 1;
        const float4* xp = hf ? (const float4*)(ef + (size_t)(e0 + r) * 64)
                              : (const float4*)(nf + (size_t)sSrc[r] * 64);
        float4* eo = (hf && outEF) ? (float4*)(outEF + (size_t)(e0 + r) * 64) : nullptr;
        char* hi = smem + SM_AHI + r * (A_STRIDE * 2) + hf * 128;
        char* lo = smem + SM_ALO + r * (A_STRIDE * 2) + hf * 128;
#pragma unroll
        for (int j = 0; j < 16; j++) {
            float4 v = xp[j];
            if (eo) eo[j] = v;
            __nv_bfloat162 h01 = __floats2bfloat162_rn(v.x, v.y);
            __nv_bfloat162 h23 = __floats2bfloat162_rn(v.z, v.w);
            float2 f01 = __bfloat1622float2(h01);
            float2 f23 = __bfloat1622float2(h23);
            __nv_bfloat162 l01 = __floats2bfloat162_rn(v.x - f01.x, v.y - f01.y);
            __nv_bfloat162 l23 = __floats2bfloat162_rn(v.z - f23.x, v.w - f23.y);
            *(uint2*)(hi + j * 8) = make_uint2(*(uint32_t*)&h01, *(uint32_t*)&h23);
            *(uint2*)(lo + j * 8) = make_uint2(*(uint32_t*)&l01, *(uint32_t*)&l23);
        }
    }
    __syncthreads();

    // warp tile: M=32 (mg), N=64 (ng)
    int mg = wid & 3, ng = wid >> 2;
    int m0 = mg * 32, n0 = ng * 64;
    float acc[2][8][4];
#pragma unroll
    for (int i = 0; i < 2; i++)
#pragma unroll
        for (int j = 0; j < 8; j++)
#pragma unroll
            for (int c = 0; c < 4; c++) acc[i][j][c] = 0.f;

    uint32_t aOffL = ((lane & 15) * A_STRIDE + (lane >> 4) * 8) * 2;
    uint32_t bOffL = (((lane & 7) + ((lane >> 4) << 3)) * A_STRIDE + ((lane >> 3) & 1) * 8) * 2;

#pragma unroll
    for (int p = 0; p < 3; p++) {
        uint32_t Ab = sb + (p == 1 ? SM_ALO : SM_AHI);
        uint32_t Bb = sb + (p == 2 ? SM_BLO : SM_BHI);
#pragma unroll
        for (int k8 = 0; k8 < 8; k8++) {
            uint32_t kb = k8 * 32;
            uint32_t a[2][4], b[4][4];
            ldsm_x4(a[0], Ab + aOffL + (uint32_t)m0 * 272 + kb);
            ldsm_x4(a[1], Ab + aOffL + (uint32_t)(m0 + 16) * 272 + kb);
#pragma unroll
            for (int q = 0; q < 4; q++)
                ldsm_x4(b[q], Bb + bOffL + (uint32_t)(n0 + q * 16) * 272 + kb);
#pragma unroll
            for (int ms = 0; ms < 2; ms++)
#pragma unroll
                for (int q = 0; q < 4; q++) {
                    mma_bf16(acc[ms][q * 2],     a[ms], &b[q][0]);
                    mma_bf16(acc[ms][q * 2 + 1], a[ms], &b[q][2]);
                }
        }
    }

    // epilogue: bias + leaky + store h_e (CSR slot) + partial logit
#pragma unroll
    for (int ms = 0; ms < 2; ms++) {
        int r1 = m0 + ms * 16 + (lane >> 2);
        int r2 = r1 + 8;
        float lg1 = 0.f, lg2 = 0.f;
        float* o1 = g_h_e + (size_t)sPerm[r1] * 128;
        float* o2 = g_h_e + (size_t)sPerm[r2] * 128;
#pragma unroll
        for (int ns = 0; ns < 8; ns++) {
            int col = n0 + ns * 8 + (lane & 3) * 2;
            float v0 = leaky01(acc[ms][ns][0] + sBias[col]);
            float v1 = leaky01(acc[ms][ns][1] + sBias[col + 1]);
            float v2 = leaky01(acc[ms][ns][2] + sBias[col]);
            float v3 = leaky01(acc[ms][ns][3] + sBias[col + 1]);
            lg1 += v0 * sWL[col] + v1 * sWL[col + 1];
            lg2 += v2 * sWL[col] + v3 * sWL[col + 1];
            *(float2*)(o1 + col) = make_float2(v0, v1);
            *(float2*)(o2 + col) = make_float2(v2, v3);
        }
        lg1 += __shfl_xor_sync(0xffffffffu, lg1, 1);
        lg1 += __shfl_xor_sync(0xffffffffu, lg1, 2);
        lg2 += __shfl_xor_sync(0xffffffffu, lg2, 1);
        lg2 += __shfl_xor_sync(0xffffffffu, lg2, 2);
        if ((lane & 3) == 0) {
            sLog[r1 * 2 + ng] = lg1;
            sLog[r2 * 2 + ng] = lg2;
        }
    }
    __syncthreads();
    if (t < 128) {
        float s = sLog[t * 2] + sLog[t * 2 + 1] + g_hvdot[sSrc[t]] + b_logit[0];
        g_logit[sPerm[t]] = leaky01(s);
    }
}

// ---------------- per-node softmax + weighted sum (one warp / node, CSR-sequential) ----------------
__global__ void aggregate_kernel() {
    int v = (blockIdx.x * blockDim.x + threadIdx.x) >> 5;
    int lane = threadIdx.x & 31;
    if (v >= N_NODES) return;
    int s = g_off[v], e = g_off[v + 1];
    float mx = -1e30f;
    for (int i = s + lane; i < e; i += 32)
        mx = fmaxf(mx, g_logit[i]);
    for (int o = 16; o; o >>= 1)
        mx = fmaxf(mx, __shfl_xor_sync(0xffffffffu, mx, o));
    float4 acc = make_float4(0.f, 0.f, 0.f, 0.f);
    float den = 0.f;
    int i = s;
    for (; i + 2 <= e; i += 2) {
        float w0 = expf(g_logit[i] - mx);
        float w1 = expf(g_logit[i + 1] - mx);
        float4 h0 = *(const float4*)&g_h_e[(size_t)i * 128 + lane * 4];
        float4 h1 = *(const float4*)&g_h_e[(size_t)(i + 1) * 128 + lane * 4];
        den += w0 + w1;
        acc.x += w0 * h0.x + w1 * h1.x;
        acc.y += w0 * h0.y + w1 * h1.y;
        acc.z += w0 * h0.z + w1 * h1.z;
        acc.w += w0 * h0.w + w1 * h1.w;
    }
    if (i < e) {
        float w = expf(g_logit[i] - mx);
        float4 h = *(const float4*)&g_h_e[(size_t)i * 128 + lane * 4];
        den += w;
        acc.x += w * h.x; acc.y += w * h.y; acc.z += w * h.z; acc.w += w * h.w;
    }
    float inv = (e > s) ? 1.f / den : 0.f;
    acc.x *= inv; acc.y *= inv; acc.z *= inv; acc.w *= inv;
    *(float4*)&g_A[v * 128 + lane * 4] = acc;
}

// ---------------- GRU gates + relu ----------------
__global__ void gate_kernel(float* __restrict__ out) {
    int idx = blockIdx.x * blockDim.x + threadIdx.x;
    if (idx >= N_NODES * NHID) return;
    int n = idx >> 7, j = idx & 127;
    const float* gi = &g_gi[n * 384];
    const float* gh = &g_gh[n * 384];
    float r = 1.f / (1.f + expf(-(gi[j] + gh[j])));
    float z = 1.f / (1.f + expf(-(gi[128 + j] + gh[128 + j])));
    float nn = tanhf(gi[256 + j] + r * gh[256 + j]);
    float hv = g_h_v[idx];
    float h = (1.f - z) * nn + z * hv;
    out[idx] = h > 0.f ? h : 0.f;
}

// ---------------- launch ----------------
extern "C" void kernel_launch(void* const* d_in, const int* in_sizes, int n_in,
                              void* d_out, int out_size) {
    const float* node_feats = (const float*)d_in[0];
    const float* edge_feats = (const float*)d_in[1];
    const float* W_node  = (const float*)d_in[2];
    const float* b_node  = (const float*)d_in[3];
    const float* W_edge  = (const float*)d_in[4];
    const float* b_edge  = (const float*)d_in[5];
    const float* W_logit = (const float*)d_in[6];
    const float* b_logit = (const float*)d_in[7];
    const float* W_msg   = (const float*)d_in[8];
    const float* b_msg   = (const float*)d_in[9];
    const float* W_ih    = (const float*)d_in[10];
    const float* W_hh    = (const float*)d_in[11];
    const float* b_ih    = (const float*)d_in[12];
    const float* b_hh    = (const float*)d_in[13];
    const int*   src     = (const int*)d_in[14];
    const int*   dst     = (const int*)d_in[15];
    float* out = (float*)d_out;

    float *p_h_v, *p_A, *p_cv;
    int* p_cnt;
    cudaGetSymbolAddress((void**)&p_h_v, g_h_v);
    cudaGetSymbolAddress((void**)&p_A, g_A);
    cudaGetSymbolAddress((void**)&p_cv, g_cv);
    cudaGetSymbolAddress((void**)&p_cnt, g_cnt);

    const int SM_G128 = (128 * 128 + 64 * 128 + 128) * 4;
    const int SM_G64  = (64 * 128 + 64 * 64 + 128) * 4;
    cudaFuncSetAttribute(edge_mma_kernel, cudaFuncAttributeMaxDynamicSharedMemorySize, SM_EDGE_TOTAL);
    cudaFuncSetAttribute(gemm_kernel<64, 1>,  cudaFuncAttributeMaxDynamicSharedMemorySize, SM_G64);
    cudaFuncSetAttribute(gemm_kernel<128, 2>, cudaFuncAttributeMaxDynamicSharedMemorySize, SM_G128);
    cudaFuncSetAttribute(gru_gemm_kernel, cudaFuncAttributeMaxDynamicSharedMemorySize, SM_G128);

    // CSR build (perm variant)
    cudaMemsetAsync(p_cnt, 0, N_NODES * sizeof(int));
    hist_kernel<<<(N_EDGES + 255) / 256, 256>>>(dst);
    scan_kernel<<<1, 1024>>>();
    perm_kernel<<<(N_EDGES + 255) / 256, 256>>>(dst);

    // weight prep
    transpose_w_kernel<<<(384 * 128 + 255) / 256, 256>>>(W_ih, W_hh);
    bprep_kernel<<<(128 * 64 + 255) / 256, 256>>>(W_edge);

    // node embed: h_v = leaky(nf @ W_node + b_node)
    int ntiles = (N_NODES + 63) / 64;
    gemm_kernel<64, 1><<<ntiles, 256, SM_G64>>>(node_feats, 64, N_NODES,
                                                W_node, 128, b_node, p_h_v, 128);
    hvdot_kernel<<<(N_NODES + 7) / 8, 256>>>(W_logit);

    // edge embed + logits on tensor cores (HMMA), CSR-ordered output + ef passthrough
    float* outEF = (out_size >= N_NODES * NHID + N_EDGES * 64) ? (out + N_NODES * NHID) : nullptr;
    edge_mma_kernel<<<N_EDGES / 128, 256, SM_EDGE_TOTAL>>>(node_feats, edge_feats, src,
                                                           b_edge, W_logit, b_logit, outEF);

    // softmax-weighted segment sum (sequential CSR reads)
    aggregate_kernel<<<(N_NODES + 7) / 8, 256>>>();

    // C_v = elu(A @ W_msg + b_msg)
    gemm_kernel<128, 2><<<ntiles, 256, SM_G128>>>(p_A, 128, N_NODES,
                                                  W_msg, 128, b_msg, p_cv, 128);
    // gi / gh in one launch
    gru_gemm_kernel<<<dim3(ntiles, 6), 256, SM_G128>>>(b_ih, b_hh);

    // gates -> h_new
    gate_kernel<<<(N_NODES * NHID + 255) / 256, 256>>>(out);
}

// round 5
// speedup vs baseline: 1.8759x; 1.0765x over previous
#include <cuda_runtime.h>
#include <cuda_bf16.h>
#include <cuda_fp16.h>
#include <math.h>
#include <stdint.h>

#define N_NODES 10000
#define N_EDGES 640000
#define NHID    128
#define EHID    128
#define CSIZE   128

// ---------------- scratch (device globals; no allocation) ----------------
__device__ float g_h_v[N_NODES * NHID];
__device__ float g_hvdot[N_NODES];
__device__ __half g_h_e16[(size_t)N_EDGES * EHID];  // CSR-ordered rows, fp16 (164MB)
__device__ float g_logit[N_EDGES];                  // CSR-ordered
__device__ float g_A[N_NODES * EHID];
__device__ float g_cv[N_NODES * CSIZE];
__device__ float g_gi[N_NODES * 3 * NHID];
__device__ float g_gh[N_NODES * 3 * NHID];
__device__ float g_WihT[NHID * 3 * NHID];
__device__ float g_WhhT[NHID * 3 * NHID];
__device__ int   g_cnt[N_NODES];
__device__ int   g_off[N_NODES + 1];
__device__ int   g_cur[N_NODES];
// B operand image: [hi | lo], each [n=128][k stride 136] bf16  (W_edge^T split)
#define A_STRIDE 136
__device__ __nv_bfloat16 g_B[2 * 128 * A_STRIDE];

__device__ __forceinline__ float leaky01(float v) { return v > 0.f ? v : 0.01f * v; }

__device__ __forceinline__ uint32_t smem_u32(const void* p) {
    uint32_t a;
    asm("{ .reg .u64 t; cvta.to.shared.u64 t, %1; cvt.u32.u64 %0, t; }" : "=r"(a) : "l"(p));
    return a;
}
__device__ __forceinline__ void ldsm_x4(uint32_t* r, uint32_t addr) {
    asm volatile("ldmatrix.sync.aligned.m8n8.x4.shared.b16 {%0,%1,%2,%3}, [%4];"
        : "=r"(r[0]), "=r"(r[1]), "=r"(r[2]), "=r"(r[3]) : "r"(addr));
}
__device__ __forceinline__ void mma_bf16(float* c, const uint32_t* a, const uint32_t* b) {
    asm volatile("mma.sync.aligned.m16n8k16.row.col.f32.bf16.bf16.f32 "
        "{%0,%1,%2,%3}, {%4,%5,%6,%7}, {%8,%9}, {%0,%1,%2,%3};"
        : "+f"(c[0]), "+f"(c[1]), "+f"(c[2]), "+f"(c[3])
        : "r"(a[0]), "r"(a[1]), "r"(a[2]), "r"(a[3]), "r"(b[0]), "r"(b[1]));
}

// ---------------- launch #1: histogram + weight prep (bprep + GRU W transpose) ----------------
__global__ void hist_prep_kernel(const int* __restrict__ dst,
                                 const float* __restrict__ We,
                                 const float* __restrict__ Wih,
                                 const float* __restrict__ Whh)
{
    int e = blockIdx.x * blockDim.x + threadIdx.x;
    if (e < N_EDGES) atomicAdd(&g_cnt[dst[e]], 1);
    // bprep: split W_edge into bf16 hi/lo, transposed B[n][k]=W[k][n], stride 136
    if (e < 128 * 64) {
        int n = e >> 6, k = (e & 63) * 2;
        float x0 = We[k * 128 + n], x1 = We[(k + 1) * 128 + n];
        __nv_bfloat162 h = __floats2bfloat162_rn(x0, x1);
        float2 hf = __bfloat1622float2(h);
        __nv_bfloat162 l = __floats2bfloat162_rn(x0 - hf.x, x1 - hf.y);
        *(uint32_t*)&g_B[n * A_STRIDE + k] = *(uint32_t*)&h;
        *(uint32_t*)&g_B[128 * A_STRIDE + n * A_STRIDE + k] = *(uint32_t*)&l;
    }
    // GRU weight transpose
    if (e < 384 * 128) {
        int r = e / 128, k = e % 128;
        g_WihT[k * 384 + r] = Wih[e];
        g_WhhT[k * 384 + r] = Whh[e];
    }
}

// ---------------- launch #2: exclusive scan of counts -> off/cur ----------------
__global__ void scan_kernel() {
    __shared__ int s[1024];
    __shared__ int s_carry;
    if (threadIdx.x == 0) s_carry = 0;
    __syncthreads();
    for (int base = 0; base < N_NODES; base += 1024) {
        int i = base + threadIdx.x;
        int v = (i < N_NODES) ? g_cnt[i] : 0;
        s[threadIdx.x] = v;
        __syncthreads();
        for (int d = 1; d < 1024; d <<= 1) {
            int t = 0;
            if ((int)threadIdx.x >= d) t = s[threadIdx.x - d];
            __syncthreads();
            s[threadIdx.x] += t;
            __syncthreads();
        }
        int incl = s[threadIdx.x] + s_carry;
        if (i < N_NODES) { g_off[i] = incl - v; g_cur[i] = incl - v; }
        __syncthreads();
        if (threadIdx.x == 1023) s_carry = incl;
        __syncthreads();
    }
    if (threadIdx.x == 0) g_off[N_NODES] = s_carry;
}

// ---------------- launch #3: node embed GEMM (K=64, leaky) + fused hvdot ----------------
__global__ __launch_bounds__(256) void node_embed_kernel(
    const float* __restrict__ nf, const float* __restrict__ Wn,
    const float* __restrict__ bn, const float* __restrict__ Wl)
{
    extern __shared__ float sm[];
    float* sW = sm;            // 64*128
    float* sX = sm + 8192;     // 64*64
    float* sB = sm + 12288;    // 128
    float* sWL = sm + 12416;   // 128
    int t = threadIdx.x;
    int r0g = blockIdx.x * 64;
    for (int i = t; i < 64 * 128; i += 256) {
        int k = i >> 7, c = i & 127;
        sW[i] = Wn[k * 128 + c];
    }
    for (int i = t; i < 64 * 64; i += 256) {
        int r = i >> 6, k = i & 63;
        int gr = r0g + r;
        sX[i] = (gr < N_NODES) ? nf[gr * 64 + k] : 0.f;
    }
    if (t < 128) { sB[t] = bn[t]; sWL[t] = Wl[t]; }
    __syncthreads();
    int cx = t & 31, cy = t >> 5;
    int r0 = cy * 8, c0 = cx * 4;
    float acc[8][4] = {};
#pragma unroll 4
    for (int k = 0; k < 64; k++) {
        float4 w = *(const float4*)&sW[k * 128 + c0];
#pragma unroll
        for (int r = 0; r < 8; r++) {
            float x = sX[(r0 + r) * 64 + k];
            acc[r][0] += x * w.x; acc[r][1] += x * w.y;
            acc[r][2] += x * w.z; acc[r][3] += x * w.w;
        }
    }
    float wl0 = sWL[c0], wl1 = sWL[c0 + 1], wl2 = sWL[c0 + 2], wl3 = sWL[c0 + 3];
#pragma unroll
    for (int r = 0; r < 8; r++) {
        int gr = r0g + r0 + r;
        if (gr >= N_NODES) break;
        float v0 = leaky01(acc[r][0] + sB[c0]);
        float v1 = leaky01(acc[r][1] + sB[c0 + 1]);
        float v2 = leaky01(acc[r][2] + sB[c0 + 2]);
        float v3 = leaky01(acc[r][3] + sB[c0 + 3]);
        *(float4*)&g_h_v[(size_t)gr * 128 + c0] = make_float4(v0, v1, v2, v3);
        float p = v0 * wl0 + v1 * wl1 + v2 * wl2 + v3 * wl3;
        for (int o = 16; o; o >>= 1) p += __shfl_xor_sync(0xffffffffu, p, o);
        if (cx == 0) g_hvdot[gr] = p;
    }
}

// ============ launch #4: edge GEMM on HMMA (profiled slot) ============
// 128 edges x 128 cols, K=128, 3-pass bf16 split; CSR slot via atomic;
// writes h_e (fp16) + logit to CSR slots; streams ef rows to output tail.
#define SM_SRC   0
#define SM_PERM  512
#define SM_BIAS  1024
#define SM_WL    1536
#define SM_LOG   2048
#define SM_AHI   3072
#define SM_ALO   (SM_AHI + 34816)
#define SM_BHI   (SM_ALO + 34816)
#define SM_BLO   (SM_BHI + 34816)
#define SM_EDGE_TOTAL (SM_BLO + 34816)

__global__ __launch_bounds__(256)
void edge_mma_kernel(const float* __restrict__ nf, const float* __restrict__ ef,
                     const int* __restrict__ src, const int* __restrict__ dst,
                     const float* __restrict__ b_edge,
                     const float* __restrict__ W_logit, const float* __restrict__ b_logit,
                     float* __restrict__ outEF)
{
    extern __shared__ __align__(16) char smem[];
    uint32_t sb = smem_u32(smem);
    int t = threadIdx.x, lane = t & 31, wid = t >> 5;
    int e0 = blockIdx.x * 128;
    int* sSrc = (int*)(smem + SM_SRC);
    int* sPerm = (int*)(smem + SM_PERM);
    float* sBias = (float*)(smem + SM_BIAS);
    float* sWL = (float*)(smem + SM_WL);
    float* sLog = (float*)(smem + SM_LOG);

    if (t < 128) {
        sSrc[t] = src[e0 + t];
        sPerm[t] = atomicAdd(&g_cur[dst[e0 + t]], 1);
        sBias[t] = b_edge[t];
        sWL[t] = W_logit[128 + t];
    }
    // copy B image (hi+lo, 68KB) from global (L2-hot)
    {
        const float4* bs = (const float4*)g_B;
        float4* bd = (float4*)(smem + SM_BHI);
#pragma unroll
        for (int i = 0; i < 17; i++) bd[t + 256 * i] = bs[t + 256 * i];
    }
    __syncthreads();

    // A gather/split: row r from [nf[src[r]] | ef[e0+r]], bf16 hi/lo.
    // hf==1 threads also stream the ef row to the output passthrough region.
    {
        int r = t >> 1, hf = t & 1;
        const float4* xp = hf ? (const float4*)(ef + (size_t)(e0 + r) * 64)
                              : (const float4*)(nf + (size_t)sSrc[r] * 64);
        float4* eo = (hf && outEF) ? (float4*)(outEF + (size_t)(e0 + r) * 64) : nullptr;
        char* hi = smem + SM_AHI + r * (A_STRIDE * 2) + hf * 128;
        char* lo = smem + SM_ALO + r * (A_STRIDE * 2) + hf * 128;
#pragma unroll
        for (int j = 0; j < 16; j++) {
            float4 v = xp[j];
            if (eo) eo[j] = v;
            __nv_bfloat162 h01 = __floats2bfloat162_rn(v.x, v.y);
            __nv_bfloat162 h23 = __floats2bfloat162_rn(v.z, v.w);
            float2 f01 = __bfloat1622float2(h01);
            float2 f23 = __bfloat1622float2(h23);
            __nv_bfloat162 l01 = __floats2bfloat162_rn(v.x - f01.x, v.y - f01.y);
            __nv_bfloat162 l23 = __floats2bfloat162_rn(v.z - f23.x, v.w - f23.y);
            *(uint2*)(hi + j * 8) = make_uint2(*(uint32_t*)&h01, *(uint32_t*)&h23);
            *(uint2*)(lo + j * 8) = make_uint2(*(uint32_t*)&l01, *(uint32_t*)&l23);
        }
    }
    __syncthreads();

    // warp tile: M=32 (mg), N=64 (ng)
    int mg = wid & 3, ng = wid >> 2;
    int m0 = mg * 32, n0 = ng * 64;
    float acc[2][8][4];
#pragma unroll
    for (int i = 0; i < 2; i++)
#pragma unroll
        for (int j = 0; j < 8; j++)
#pragma unroll
            for (int c = 0; c < 4; c++) acc[i][j][c] = 0.f;

    uint32_t aOffL = ((lane & 15) * A_STRIDE + (lane >> 4) * 8) * 2;
    uint32_t bOffL = (((lane & 7) + ((lane >> 4) << 3)) * A_STRIDE + ((lane >> 3) & 1) * 8) * 2;

#pragma unroll
    for (int p = 0; p < 3; p++) {
        uint32_t Ab = sb + (p == 1 ? SM_ALO : SM_AHI);
        uint32_t Bb = sb + (p == 2 ? SM_BLO : SM_BHI);
#pragma unroll
        for (int k8 = 0; k8 < 8; k8++) {
            uint32_t kb = k8 * 32;
            uint32_t a[2][4], b[4][4];
            ldsm_x4(a[0], Ab + aOffL + (uint32_t)m0 * 272 + kb);
            ldsm_x4(a[1], Ab + aOffL + (uint32_t)(m0 + 16) * 272 + kb);
#pragma unroll
            for (int q = 0; q < 4; q++)
                ldsm_x4(b[q], Bb + bOffL + (uint32_t)(n0 + q * 16) * 272 + kb);
#pragma unroll
            for (int ms = 0; ms < 2; ms++)
#pragma unroll
                for (int q = 0; q < 4; q++) {
                    mma_bf16(acc[ms][q * 2],     a[ms], &b[q][0]);
                    mma_bf16(acc[ms][q * 2 + 1], a[ms], &b[q][2]);
                }
        }
    }

    // epilogue: bias + leaky + store h_e fp16 (CSR slot) + partial logit
#pragma unroll
    for (int ms = 0; ms < 2; ms++) {
        int r1 = m0 + ms * 16 + (lane >> 2);
        int r2 = r1 + 8;
        float lg1 = 0.f, lg2 = 0.f;
        __half* o1 = g_h_e16 + (size_t)sPerm[r1] * 128;
        __half* o2 = g_h_e16 + (size_t)sPerm[r2] * 128;
#pragma unroll
        for (int ns = 0; ns < 8; ns++) {
            int col = n0 + ns * 8 + (lane & 3) * 2;
            float v0 = leaky01(acc[ms][ns][0] + sBias[col]);
            float v1 = leaky01(acc[ms][ns][1] + sBias[col + 1]);
            float v2 = leaky01(acc[ms][ns][2] + sBias[col]);
            float v3 = leaky01(acc[ms][ns][3] + sBias[col + 1]);
            lg1 += v0 * sWL[col] + v1 * sWL[col + 1];
            lg2 += v2 * sWL[col] + v3 * sWL[col + 1];
            *(__half2*)(o1 + col) = __floats2half2_rn(v0, v1);
            *(__half2*)(o2 + col) = __floats2half2_rn(v2, v3);
        }
        lg1 += __shfl_xor_sync(0xffffffffu, lg1, 1);
        lg1 += __shfl_xor_sync(0xffffffffu, lg1, 2);
        lg2 += __shfl_xor_sync(0xffffffffu, lg2, 1);
        lg2 += __shfl_xor_sync(0xffffffffu, lg2, 2);
        if ((lane & 3) == 0) {
            sLog[r1 * 2 + ng] = lg1;
            sLog[r2 * 2 + ng] = lg2;
        }
    }
    __syncthreads();
    if (t < 128) {
        float s = sLog[t * 2] + sLog[t * 2 + 1] + g_hvdot[sSrc[t]] + b_logit[0];
        g_logit[sPerm[t]] = leaky01(s);
    }
}

// ---------------- launch #5: per-node softmax + weighted sum (CSR-sequential, fp16 reads) ----------------
__global__ void aggregate_kernel() {
    int v = (blockIdx.x * blockDim.x + threadIdx.x) >> 5;
    int lane = threadIdx.x & 31;
    if (v >= N_NODES) return;
    int s = g_off[v], e = g_off[v + 1];
    float mx = -1e30f;
    for (int i = s + lane; i < e; i += 32)
        mx = fmaxf(mx, g_logit[i]);
    for (int o = 16; o; o >>= 1)
        mx = fmaxf(mx, __shfl_xor_sync(0xffffffffu, mx, o));
    float4 acc = make_float4(0.f, 0.f, 0.f, 0.f);
    float den = 0.f;
    for (int i = s; i < e; i++) {
        float w = expf(g_logit[i] - mx);
        den += w;
        uint2 raw = *(const uint2*)(g_h_e16 + (size_t)i * 128 + lane * 4);
        float2 f01 = __half22float2(*(__half2*)&raw.x);
        float2 f23 = __half22float2(*(__half2*)&raw.y);
        acc.x += w * f01.x; acc.y += w * f01.y;
        acc.z += w * f23.x; acc.w += w * f23.y;
    }
    float inv = (e > s) ? 1.f / den : 0.f;
    acc.x *= inv; acc.y *= inv; acc.z *= inv; acc.w *= inv;
    *(float4*)&g_A[v * 128 + lane * 4] = acc;
}

// ---------------- generic tiled GEMM: out = act(X @ W + b), 64x128 tile ----------------
template <int K, int ACT>
__global__ __launch_bounds__(256) void gemm_kernel(
    const float* __restrict__ X, int ldx, int rows,
    const float* __restrict__ W, int ldw,
    const float* __restrict__ b,
    float* __restrict__ out, int ldo)
{
    extern __shared__ float sm[];
    float* sW = sm;
    float* sX = sW + K * 128;
    float* sB = sX + 64 * K;
    int t = threadIdx.x;
    int r0g = blockIdx.x * 64;
    for (int i = t; i < K * 128; i += 256) {
        int k = i >> 7, c = i & 127;
        sW[i] = W[(size_t)k * ldw + c];
    }
    for (int i = t; i < 64 * K; i += 256) {
        int r = i / K, k = i % K;
        int gr = r0g + r;
        sX[i] = (gr < rows) ? X[(size_t)gr * ldx + k] : 0.f;
    }
    if (t < 128) sB[t] = b[t];
    __syncthreads();
    int cx = t & 31, cy = t >> 5;
    int r0 = cy * 8, c0 = cx * 4;
    float acc[8][4] = {};
#pragma unroll 4
    for (int k = 0; k < K; k++) {
        float4 w = *(const float4*)&sW[k * 128 + c0];
#pragma unroll
        for (int r = 0; r < 8; r++) {
            float x = sX[(r0 + r) * K + k];
            acc[r][0] += x * w.x; acc[r][1] += x * w.y;
            acc[r][2] += x * w.z; acc[r][3] += x * w.w;
        }
    }
#pragma unroll
    for (int r = 0; r < 8; r++) {
        int gr = r0g + r0 + r;
        if (gr >= rows) break;
#pragma unroll
        for (int c = 0; c < 4; c++) {
            float v = acc[r][c] + sB[c0 + c];
            if (ACT == 1) v = leaky01(v);
            else if (ACT == 2) v = (v > 0.f) ? v : (expf(v) - 1.f);
            acc[r][c] = v;
        }
        *(float4*)&out[(size_t)gr * ldo + c0] = make_float4(acc[r][0], acc[r][1], acc[r][2], acc[r][3]);
    }
}

// ---------------- fused GRU GEMMs: one launch, blockIdx.y selects (mat, chunk) ----------------
__global__ __launch_bounds__(256) void gru_gemm_kernel(const float* __restrict__ b_ih,
                                                       const float* __restrict__ b_hh)
{
    extern __shared__ float sm[];
    float* sW = sm;
    float* sX = sW + 128 * 128;
    float* sB = sX + 64 * 128;
    int mat = blockIdx.y / 3, chunk = blockIdx.y % 3;
    const float* X = mat ? g_h_v : g_cv;
    const float* W = (mat ? g_WhhT : g_WihT) + chunk * 128;
    const float* b = (mat ? b_hh : b_ih) + chunk * 128;
    float* out = (mat ? g_gh : g_gi) + chunk * 128;
    int t = threadIdx.x;
    int r0g = blockIdx.x * 64;
    for (int i = t; i < 128 * 128; i += 256) {
        int k = i >> 7, c = i & 127;
        sW[i] = W[k * 384 + c];
    }
    for (int i = t; i < 64 * 128; i += 256) {
        int r = i >> 7, k = i & 127;
        int gr = r0g + r;
        sX[i] = (gr < N_NODES) ? X[gr * 128 + k] : 0.f;
    }
    if (t < 128) sB[t] = b[t];
    __syncthreads();
    int cx = t & 31, cy = t >> 5;
    int r0 = cy * 8, c0 = cx * 4;
    float acc[8][4] = {};
#pragma unroll 4
    for (int k = 0; k < 128; k++) {
        float4 w = *(const float4*)&sW[k * 128 + c0];
#pragma unroll
        for (int r = 0; r < 8; r++) {
            float x = sX[(r0 + r) * 128 + k];
            acc[r][0] += x * w.x; acc[r][1] += x * w.y;
            acc[r][2] += x * w.z; acc[r][3] += x * w.w;
        }
    }
#pragma unroll
    for (int r = 0; r < 8; r++) {
        int gr = r0g + r0 + r;
        if (gr >= N_NODES) break;
        *(float4*)&out[(size_t)gr * 384 + c0] = make_float4(
            acc[r][0] + sB[c0], acc[r][1] + sB[c0 + 1], acc[r][2] + sB[c0 + 2], acc[r][3] + sB[c0 + 3]);
    }
}

// ---------------- GRU gates + relu ----------------
__global__ void gate_kernel(float* __restrict__ out) {
    int idx = blockIdx.x * blockDim.x + threadIdx.x;
    if (idx >= N_NODES * NHID) return;
    int n = idx >> 7, j = idx & 127;
    const float* gi = &g_gi[n * 384];
    const float* gh = &g_gh[n * 384];
    float r = 1.f / (1.f + expf(-(gi[j] + gh[j])));
    float z = 1.f / (1.f + expf(-(gi[128 + j] + gh[128 + j])));
    float nn = tanhf(gi[256 + j] + r * gh[256 + j]);
    float hv = g_h_v[idx];
    float h = (1.f - z) * nn + z * hv;
    out[idx] = h > 0.f ? h : 0.f;
}

// ---------------- launch ----------------
extern "C" void kernel_launch(void* const* d_in, const int* in_sizes, int n_in,
                              void* d_out, int out_size) {
    const float* node_feats = (const float*)d_in[0];
    const float* edge_feats = (const float*)d_in[1];
    const float* W_node  = (const float*)d_in[2];
    const float* b_node  = (const float*)d_in[3];
    const float* W_edge  = (const float*)d_in[4];
    const float* b_edge  = (const float*)d_in[5];
    const float* W_logit = (const float*)d_in[6];
    const float* b_logit = (const float*)d_in[7];
    const float* W_msg   = (const float*)d_in[8];
    const float* b_msg   = (const float*)d_in[9];
    const float* W_ih    = (const float*)d_in[10];
    const float* W_hh    = (const float*)d_in[11];
    const float* b_ih    = (const float*)d_in[12];
    const float* b_hh    = (const float*)d_in[13];
    const int*   src     = (const int*)d_in[14];
    const int*   dst     = (const int*)d_in[15];
    float* out = (float*)d_out;

    float *p_A, *p_cv;
    int* p_cnt;
    cudaGetSymbolAddress((void**)&p_A, g_A);
    cudaGetSymbolAddress((void**)&p_cv, g_cv);
    cudaGetSymbolAddress((void**)&p_cnt, g_cnt);

    const int SM_G128 = (128 * 128 + 64 * 128 + 128) * 4;
    const int SM_NODE = (64 * 128 + 64 * 64 + 256) * 4;
    cudaFuncSetAttribute(edge_mma_kernel, cudaFuncAttributeMaxDynamicSharedMemorySize, SM_EDGE_TOTAL);
    cudaFuncSetAttribute(node_embed_kernel, cudaFuncAttributeMaxDynamicSharedMemorySize, SM_NODE);
    cudaFuncSetAttribute(gemm_kernel<128, 2>, cudaFuncAttributeMaxDynamicSharedMemorySize, SM_G128);
    cudaFuncSetAttribute(gru_gemm_kernel, cudaFuncAttributeMaxDynamicSharedMemorySize, SM_G128);

    cudaMemsetAsync(p_cnt, 0, N_NODES * sizeof(int));

    // #1 histogram + all weight prep
    hist_prep_kernel<<<(N_EDGES + 255) / 256, 256>>>(dst, W_edge, W_ih, W_hh);
    // #2 scan
    scan_kernel<<<1, 1024>>>();
    // #3 node embed + fused hvdot
    int ntiles = (N_NODES + 63) / 64;
    node_embed_kernel<<<ntiles, 256, SM_NODE>>>(node_feats, W_node, b_node, W_logit);
    // #4 edge GEMM on tensor cores (profiled slot)
    float* outEF = (out_size >= N_NODES * NHID + N_EDGES * 64) ? (out + N_NODES * NHID) : nullptr;
    edge_mma_kernel<<<N_EDGES / 128, 256, SM_EDGE_TOTAL>>>(node_feats, edge_feats, src, dst,
                                                           b_edge, W_logit, b_logit, outEF);
    // #5 softmax-weighted segment sum
    aggregate_kernel<<<(N_NODES + 7) / 8, 256>>>();
    // #6 C_v = elu(A @ W_msg + b_msg)
    gemm_kernel<128, 2><<<ntiles, 256, SM_G128>>>(p_A, 128, N_NODES,
                                                  W_msg, 128, b_msg, p_cv, 128);
    // #7 gi / gh in one launch
    gru_gemm_kernel<<<dim3(ntiles, 6), 256, SM_G128>>>(b_ih, b_hh);
    // #8 gates -> h_new
    gate_kernel<<<(N_NODES * NHID + 255) / 256, 256>>>(out);
}

// round 6
// speedup vs baseline: 2.1301x; 1.1356x over previous
#include <cuda_runtime.h>
#include <cuda_bf16.h>
#include <cuda_fp16.h>
#include <math.h>
#include <stdint.h>

#define N_NODES 10000
#define N_EDGES 640000
#define NHID    128
#define EHID    128
#define CSIZE   128

// ---------------- scratch (device globals; no allocation) ----------------
__device__ float g_h_v[N_NODES * NHID];
__device__ float g_hvdot[N_NODES];
__device__ __half g_h_e16[(size_t)N_EDGES * EHID];  // CSR-ordered rows, fp16 (164MB)
__device__ float g_logit[N_EDGES];                  // CSR-ordered
__device__ float g_A[N_NODES * EHID];
__device__ float g_cv[N_NODES * CSIZE];
__device__ float g_gi[N_NODES * 3 * NHID];
__device__ float g_gh[N_NODES * 3 * NHID];
__device__ float g_WihT[NHID * 3 * NHID];
__device__ float g_WhhT[NHID * 3 * NHID];
__device__ int   g_cnt[N_NODES];
__device__ int   g_off[N_NODES + 1];
__device__ int   g_cur[N_NODES];
// B operand image: fp16 W_edge^T, [n=128][k stride 136]
#define A_STRIDE 136
__device__ __half g_B[128 * A_STRIDE];

__device__ __forceinline__ float leaky01(float v) { return v > 0.f ? v : 0.01f * v; }

__device__ __forceinline__ uint32_t smem_u32(const void* p) {
    uint32_t a;
    asm("{ .reg .u64 t; cvta.to.shared.u64 t, %1; cvt.u32.u64 %0, t; }" : "=r"(a) : "l"(p));
    return a;
}
__device__ __forceinline__ void ldsm_x4(uint32_t* r, uint32_t addr) {
    asm volatile("ldmatrix.sync.aligned.m8n8.x4.shared.b16 {%0,%1,%2,%3}, [%4];"
        : "=r"(r[0]), "=r"(r[1]), "=r"(r[2]), "=r"(r[3]) : "r"(addr));
}
__device__ __forceinline__ void mma_f16(float* c, const uint32_t* a, const uint32_t* b) {
    asm volatile("mma.sync.aligned.m16n8k16.row.col.f32.f16.f16.f32 "
        "{%0,%1,%2,%3}, {%4,%5,%6,%7}, {%8,%9}, {%0,%1,%2,%3};"
        : "+f"(c[0]), "+f"(c[1]), "+f"(c[2]), "+f"(c[3])
        : "r"(a[0]), "r"(a[1]), "r"(a[2]), "r"(a[3]), "r"(b[0]), "r"(b[1]));
}

// ---------------- launch #1: histogram + weight prep ----------------
__global__ void hist_prep_kernel(const int* __restrict__ dst,
                                 const float* __restrict__ We,
                                 const float* __restrict__ Wih,
                                 const float* __restrict__ Whh)
{
    int e = blockIdx.x * blockDim.x + threadIdx.x;
    if (e < N_EDGES) atomicAdd(&g_cnt[dst[e]], 1);
    // B image: W_edge^T in fp16, stride 136
    if (e < 128 * 64) {
        int n = e >> 6, k = (e & 63) * 2;
        __half2 h = __floats2half2_rn(We[k * 128 + n], We[(k + 1) * 128 + n]);
        *(uint32_t*)&g_B[n * A_STRIDE + k] = *(uint32_t*)&h;
    }
    // GRU weight transpose
    if (e < 384 * 128) {
        int r = e / 128, k = e % 128;
        g_WihT[k * 384 + r] = Wih[e];
        g_WhhT[k * 384 + r] = Whh[e];
    }
}

// ---------------- launch #2: exclusive scan of counts -> off/cur ----------------
__global__ void scan_kernel() {
    __shared__ int s[1024];
    __shared__ int s_carry;
    if (threadIdx.x == 0) s_carry = 0;
    __syncthreads();
    for (int base = 0; base < N_NODES; base += 1024) {
        int i = base + threadIdx.x;
        int v = (i < N_NODES) ? g_cnt[i] : 0;
        s[threadIdx.x] = v;
        __syncthreads();
        for (int d = 1; d < 1024; d <<= 1) {
            int t = 0;
            if ((int)threadIdx.x >= d) t = s[threadIdx.x - d];
            __syncthreads();
            s[threadIdx.x] += t;
            __syncthreads();
        }
        int incl = s[threadIdx.x] + s_carry;
        if (i < N_NODES) { g_off[i] = incl - v; g_cur[i] = incl - v; }
        __syncthreads();
        if (threadIdx.x == 1023) s_carry = incl;
        __syncthreads();
    }
    if (threadIdx.x == 0) g_off[N_NODES] = s_carry;
}

// ---------------- launch #3: node embed GEMM (K=64, leaky) + fused hvdot ----------------
__global__ __launch_bounds__(256) void node_embed_kernel(
    const float* __restrict__ nf, const float* __restrict__ Wn,
    const float* __restrict__ bn, const float* __restrict__ Wl)
{
    extern __shared__ float sm[];
    float* sW = sm;            // 64*128
    float* sX = sm + 8192;     // 64*64
    float* sB = sm + 12288;    // 128
    float* sWL = sm + 12416;   // 128
    int t = threadIdx.x;
    int r0g = blockIdx.x * 64;
    for (int i = t; i < 64 * 128; i += 256) {
        int k = i >> 7, c = i & 127;
        sW[i] = Wn[k * 128 + c];
    }
    for (int i = t; i < 64 * 64; i += 256) {
        int r = i >> 6, k = i & 63;
        int gr = r0g + r;
        sX[i] = (gr < N_NODES) ? nf[gr * 64 + k] : 0.f;
    }
    if (t < 128) { sB[t] = bn[t]; sWL[t] = Wl[t]; }
    __syncthreads();
    int cx = t & 31, cy = t >> 5;
    int r0 = cy * 8, c0 = cx * 4;
    float acc[8][4] = {};
#pragma unroll 4
    for (int k = 0; k < 64; k++) {
        float4 w = *(const float4*)&sW[k * 128 + c0];
#pragma unroll
        for (int r = 0; r < 8; r++) {
            float x = sX[(r0 + r) * 64 + k];
            acc[r][0] += x * w.x; acc[r][1] += x * w.y;
            acc[r][2] += x * w.z; acc[r][3] += x * w.w;
        }
    }
    float wl0 = sWL[c0], wl1 = sWL[c0 + 1], wl2 = sWL[c0 + 2], wl3 = sWL[c0 + 3];
#pragma unroll
    for (int r = 0; r < 8; r++) {
        int gr = r0g + r0 + r;
        if (gr >= N_NODES) break;
        float v0 = leaky01(acc[r][0] + sB[c0]);
        float v1 = leaky01(acc[r][1] + sB[c0 + 1]);
        float v2 = leaky01(acc[r][2] + sB[c0 + 2]);
        float v3 = leaky01(acc[r][3] + sB[c0 + 3]);
        *(float4*)&g_h_v[(size_t)gr * 128 + c0] = make_float4(v0, v1, v2, v3);
        float p = v0 * wl0 + v1 * wl1 + v2 * wl2 + v3 * wl3;
        for (int o = 16; o; o >>= 1) p += __shfl_xor_sync(0xffffffffu, p, o);
        if (cx == 0) g_hvdot[gr] = p;
    }
}

// ============ launch #4: edge GEMM on HMMA, fp16 2-pass split, 2 CTAs/SM ============
#define SM_SRC   0
#define SM_PERM  512
#define SM_BIAS  1024
#define SM_WL    1536
#define SM_LOG   2048
#define SM_AHI   3072
#define SM_ALO   (SM_AHI + 34816)
#define SM_B     (SM_ALO + 34816)
#define SM_EDGE_TOTAL (SM_B + 34816)   // 107520 bytes -> 2 CTAs/SM

__global__ __launch_bounds__(256, 2)
void edge_mma_kernel(const float* __restrict__ nf, const float* __restrict__ ef,
                     const int* __restrict__ src, const int* __restrict__ dst,
                     const float* __restrict__ b_edge,
                     const float* __restrict__ W_logit, const float* __restrict__ b_logit,
                     float* __restrict__ outEF)
{
    extern __shared__ __align__(16) char smem[];
    uint32_t sb = smem_u32(smem);
    int t = threadIdx.x, lane = t & 31, wid = t >> 5;
    int e0 = blockIdx.x * 128;
    int* sSrc = (int*)(smem + SM_SRC);
    int* sPerm = (int*)(smem + SM_PERM);
    float* sBias = (float*)(smem + SM_BIAS);
    float* sWL = (float*)(smem + SM_WL);
    float* sLog = (float*)(smem + SM_LOG);

    if (t < 128) {
        sSrc[t] = src[e0 + t];
        sPerm[t] = atomicAdd(&g_cur[dst[e0 + t]], 1);
        sBias[t] = b_edge[t];
        sWL[t] = W_logit[128 + t];
    }
    // copy B image (34KB, L2-hot)
    {
        const float4* bs = (const float4*)g_B;
        float4* bd = (float4*)(smem + SM_B);
#pragma unroll
        for (int i = 0; i < 8; i++) bd[t + 256 * i] = bs[t + 256 * i];
        if (t < 128) bd[2048 + t] = bs[2048 + t];
    }
    __syncthreads();

    // A gather/split: row r from [nf[src[r]] | ef[e0+r]], fp16 hi/lo.
    // hf==1 threads also stream the ef row to the output passthrough region.
    {
        int r = t >> 1, hf = t & 1;
        const float4* xp = hf ? (const float4*)(ef + (size_t)(e0 + r) * 64)
                              : (const float4*)(nf + (size_t)sSrc[r] * 64);
        float4* eo = (hf && outEF) ? (float4*)(outEF + (size_t)(e0 + r) * 64) : nullptr;
        char* hi = smem + SM_AHI + r * (A_STRIDE * 2) + hf * 128;
        char* lo = smem + SM_ALO + r * (A_STRIDE * 2) + hf * 128;
#pragma unroll
        for (int j = 0; j < 16; j++) {
            float4 v = xp[j];
            if (eo) eo[j] = v;
            __half2 h01 = __floats2half2_rn(v.x, v.y);
            __half2 h23 = __floats2half2_rn(v.z, v.w);
            float2 f01 = __half22float2(h01);
            float2 f23 = __half22float2(h23);
            __half2 l01 = __floats2half2_rn(v.x - f01.x, v.y - f01.y);
            __half2 l23 = __floats2half2_rn(v.z - f23.x, v.w - f23.y);
            *(uint2*)(hi + j * 8) = make_uint2(*(uint32_t*)&h01, *(uint32_t*)&h23);
            *(uint2*)(lo + j * 8) = make_uint2(*(uint32_t*)&l01, *(uint32_t*)&l23);
        }
    }
    __syncthreads();

    // warp tile: M=32 (mg), N=64 (ng)
    int mg = wid & 3, ng = wid >> 2;
    int m0 = mg * 32, n0 = ng * 64;
    float acc[2][8][4];
#pragma unroll
    for (int i = 0; i < 2; i++)
#pragma unroll
        for (int j = 0; j < 8; j++)
#pragma unroll
            for (int c = 0; c < 4; c++) acc[i][j][c] = 0.f;

    uint32_t aOffL = ((lane & 15) * A_STRIDE + (lane >> 4) * 8) * 2;
    uint32_t bOffL = (((lane & 7) + ((lane >> 4) << 3)) * A_STRIDE + ((lane >> 3) & 1) * 8) * 2;
    uint32_t AbH = sb + SM_AHI, AbL = sb + SM_ALO, Bb = sb + SM_B;

#pragma unroll
    for (int k8 = 0; k8 < 8; k8++) {
        uint32_t kb = k8 * 32;
        uint32_t b[4][4];
#pragma unroll
        for (int q = 0; q < 4; q++)
            ldsm_x4(b[q], Bb + bOffL + (uint32_t)(n0 + q * 16) * 272 + kb);
        uint32_t ah[2][4], al[2][4];
        ldsm_x4(ah[0], AbH + aOffL + (uint32_t)m0 * 272 + kb);
        ldsm_x4(ah[1], AbH + aOffL + (uint32_t)(m0 + 16) * 272 + kb);
        ldsm_x4(al[0], AbL + aOffL + (uint32_t)m0 * 272 + kb);
        ldsm_x4(al[1], AbL + aOffL + (uint32_t)(m0 + 16) * 272 + kb);
#pragma unroll
        for (int ms = 0; ms < 2; ms++)
#pragma unroll
            for (int q = 0; q < 4; q++) {
                mma_f16(acc[ms][q * 2],     ah[ms], &b[q][0]);
                mma_f16(acc[ms][q * 2 + 1], ah[ms], &b[q][2]);
                mma_f16(acc[ms][q * 2],     al[ms], &b[q][0]);
                mma_f16(acc[ms][q * 2 + 1], al[ms], &b[q][2]);
            }
    }

    // epilogue: bias + leaky + store h_e fp16 (CSR slot) + partial logit
#pragma unroll
    for (int ms = 0; ms < 2; ms++) {
        int r1 = m0 + ms * 16 + (lane >> 2);
        int r2 = r1 + 8;
        float lg1 = 0.f, lg2 = 0.f;
        __half* o1 = g_h_e16 + (size_t)sPerm[r1] * 128;
        __half* o2 = g_h_e16 + (size_t)sPerm[r2] * 128;
#pragma unroll
        for (int ns = 0; ns < 8; ns++) {
            int col = n0 + ns * 8 + (lane & 3) * 2;
            float v0 = leaky01(acc[ms][ns][0] + sBias[col]);
            float v1 = leaky01(acc[ms][ns][1] + sBias[col + 1]);
            float v2 = leaky01(acc[ms][ns][2] + sBias[col]);
            float v3 = leaky01(acc[ms][ns][3] + sBias[col + 1]);
            lg1 += v0 * sWL[col] + v1 * sWL[col + 1];
            lg2 += v2 * sWL[col] + v3 * sWL[col + 1];
            *(__half2*)(o1 + col) = __floats2half2_rn(v0, v1);
            *(__half2*)(o2 + col) = __floats2half2_rn(v2, v3);
        }
        lg1 += __shfl_xor_sync(0xffffffffu, lg1, 1);
        lg1 += __shfl_xor_sync(0xffffffffu, lg1, 2);
        lg2 += __shfl_xor_sync(0xffffffffu, lg2, 1);
        lg2 += __shfl_xor_sync(0xffffffffu, lg2, 2);
        if ((lane & 3) == 0) {
            sLog[r1 * 2 + ng] = lg1;
            sLog[r2 * 2 + ng] = lg2;
        }
    }
    __syncthreads();
    if (t < 128) {
        float s = sLog[t * 2] + sLog[t * 2 + 1] + g_hvdot[sSrc[t]] + b_logit[0];
        g_logit[sPerm[t]] = leaky01(s);
    }
}

// ---------------- launch #5: per-node softmax + weighted sum (CSR-sequential, fp16 reads) ----------------
__global__ void aggregate_kernel() {
    int v = (blockIdx.x * blockDim.x + threadIdx.x) >> 5;
    int lane = threadIdx.x & 31;
    if (v >= N_NODES) return;
    int s = g_off[v], e = g_off[v + 1];
    float mx = -1e30f;
    for (int i = s + lane; i < e; i += 32)
        mx = fmaxf(mx, g_logit[i]);
    for (int o = 16; o; o >>= 1)
        mx = fmaxf(mx, __shfl_xor_sync(0xffffffffu, mx, o));
    float4 acc = make_float4(0.f, 0.f, 0.f, 0.f);
    float den = 0.f;
    for (int i = s; i < e; i++) {
        float w = expf(g_logit[i] - mx);
        den += w;
        uint2 raw = *(const uint2*)(g_h_e16 + (size_t)i * 128 + lane * 4);
        float2 f01 = __half22float2(*(__half2*)&raw.x);
        float2 f23 = __half22float2(*(__half2*)&raw.y);
        acc.x += w * f01.x; acc.y += w * f01.y;
        acc.z += w * f23.x; acc.w += w * f23.y;
    }
    float inv = (e > s) ? 1.f / den : 0.f;
    acc.x *= inv; acc.y *= inv; acc.z *= inv; acc.w *= inv;
    *(float4*)&g_A[v * 128 + lane * 4] = acc;
}

// ---------------- generic tiled GEMM: out = act(X @ W + b), 64x128 tile ----------------
template <int K, int ACT>
__global__ __launch_bounds__(256) void gemm_kernel(
    const float* __restrict__ X, int ldx, int rows,
    const float* __restrict__ W, int ldw,
    const float* __restrict__ b,
    float* __restrict__ out, int ldo)
{
    extern __shared__ float sm[];
    float* sW = sm;
    float* sX = sW + K * 128;
    float* sB = sX + 64 * K;
    int t = threadIdx.x;
    int r0g = blockIdx.x * 64;
    for (int i = t; i < K * 128; i += 256) {
        int k = i >> 7, c = i & 127;
        sW[i] = W[(size_t)k * ldw + c];
    }
    for (int i = t; i < 64 * K; i += 256) {
        int r = i / K, k = i % K;
        int gr = r0g + r;
        sX[i] = (gr < rows) ? X[(size_t)gr * ldx + k] : 0.f;
    }
    if (t < 128) sB[t] = b[t];
    __syncthreads();
    int cx = t & 31, cy = t >> 5;
    int r0 = cy * 8, c0 = cx * 4;
    float acc[8][4] = {};
#pragma unroll 4
    for (int k = 0; k < K; k++) {
        float4 w = *(const float4*)&sW[k * 128 + c0];
#pragma unroll
        for (int r = 0; r < 8; r++) {
            float x = sX[(r0 + r) * K + k];
            acc[r][0] += x * w.x; acc[r][1] += x * w.y;
            acc[r][2] += x * w.z; acc[r][3] += x * w.w;
        }
    }
#pragma unroll
    for (int r = 0; r < 8; r++) {
        int gr = r0g + r0 + r;
        if (gr >= rows) break;
#pragma unroll
        for (int c = 0; c < 4; c++) {
            float v = acc[r][c] + sB[c0 + c];
            if (ACT == 1) v = leaky01(v);
            else if (ACT == 2) v = (v > 0.f) ? v : (expf(v) - 1.f);
            acc[r][c] = v;
        }
        *(float4*)&out[(size_t)gr * ldo + c0] = make_float4(acc[r][0], acc[r][1], acc[r][2], acc[r][3]);
    }
}

// ---------------- fused GRU GEMMs: one launch, blockIdx.y selects (mat, chunk) ----------------
__global__ __launch_bounds__(256) void gru_gemm_kernel(const float* __restrict__ b_ih,
                                                       const float* __restrict__ b_hh)
{
    extern __shared__ float sm[];
    float* sW = sm;
    float* sX = sW + 128 * 128;
    float* sB = sX + 64 * 128;
    int mat = blockIdx.y / 3, chunk = blockIdx.y % 3;
    const float* X = mat ? g_h_v : g_cv;
    const float* W = (mat ? g_WhhT : g_WihT) + chunk * 128;
    const float* b = (mat ? b_hh : b_ih) + chunk * 128;
    float* out = (mat ? g_gh : g_gi) + chunk * 128;
    int t = threadIdx.x;
    int r0g = blockIdx.x * 64;
    for (int i = t; i < 128 * 128; i += 256) {
        int k = i >> 7, c = i & 127;
        sW[i] = W[k * 384 + c];
    }
    for (int i = t; i < 64 * 128; i += 256) {
        int r = i >> 7, k = i & 127;
        int gr = r0g + r;
        sX[i] = (gr < N_NODES) ? X[gr * 128 + k] : 0.f;
    }
    if (t < 128) sB[t] = b[t];
    __syncthreads();
    int cx = t & 31, cy = t >> 5;
    int r0 = cy * 8, c0 = cx * 4;
    float acc[8][4] = {};
#pragma unroll 4
    for (int k = 0; k < 128; k++) {
        float4 w = *(const float4*)&sW[k * 128 + c0];
#pragma unroll
        for (int r = 0; r < 8; r++) {
            float x = sX[(r0 + r) * 128 + k];
            acc[r][0] += x * w.x; acc[r][1] += x * w.y;
            acc[r][2] += x * w.z; acc[r][3] += x * w.w;
        }
    }
#pragma unroll
    for (int r = 0; r < 8; r++) {
        int gr = r0g + r0 + r;
        if (gr >= N_NODES) break;
        *(float4*)&out[(size_t)gr * 384 + c0] = make_float4(
            acc[r][0] + sB[c0], acc[r][1] + sB[c0 + 1], acc[r][2] + sB[c0 + 2], acc[r][3] + sB[c0 + 3]);
    }
}

// ---------------- GRU gates + relu ----------------
__global__ void gate_kernel(float* __restrict__ out) {
    int idx = blockIdx.x * blockDim.x + threadIdx.x;
    if (idx >= N_NODES * NHID) return;
    int n = idx >> 7, j = idx & 127;
    const float* gi = &g_gi[n * 384];
    const float* gh = &g_gh[n * 384];
    float r = 1.f / (1.f + expf(-(gi[j] + gh[j])));
    float z = 1.f / (1.f + expf(-(gi[128 + j] + gh[128 + j])));
    float nn = tanhf(gi[256 + j] + r * gh[256 + j]);
    float hv = g_h_v[idx];
    float h = (1.f - z) * nn + z * hv;
    out[idx] = h > 0.f ? h : 0.f;
}

// ---------------- launch ----------------
extern "C" void kernel_launch(void* const* d_in, const int* in_sizes, int n_in,
                              void* d_out, int out_size) {
    const float* node_feats = (const float*)d_in[0];
    const float* edge_feats = (const float*)d_in[1];
    const float* W_node  = (const float*)d_in[2];
    const float* b_node  = (const float*)d_in[3];
    const float* W_edge  = (const float*)d_in[4];
    const float* b_edge  = (const float*)d_in[5];
    const float* W_logit = (const float*)d_in[6];
    const float* b_logit = (const float*)d_in[7];
    const float* W_msg   = (const float*)d_in[8];
    const float* b_msg   = (const float*)d_in[9];
    const float* W_ih    = (const float*)d_in[10];
    const float* W_hh    = (const float*)d_in[11];
    const float* b_ih    = (const float*)d_in[12];
    const float* b_hh    = (const float*)d_in[13];
    const int*   src     = (const int*)d_in[14];
    const int*   dst     = (const int*)d_in[15];
    float* out = (float*)d_out;

    float *p_A, *p_cv;
    int* p_cnt;
    cudaGetSymbolAddress((void**)&p_A, g_A);
    cudaGetSymbolAddress((void**)&p_cv, g_cv);
    cudaGetSymbolAddress((void**)&p_cnt, g_cnt);

    const int SM_G128 = (128 * 128 + 64 * 128 + 128) * 4;
    const int SM_NODE = (64 * 128 + 64 * 64 + 256) * 4;
    cudaFuncSetAttribute(edge_mma_kernel, cudaFuncAttributeMaxDynamicSharedMemorySize, SM_EDGE_TOTAL);
    cudaFuncSetAttribute(node_embed_kernel, cudaFuncAttributeMaxDynamicSharedMemorySize, SM_NODE);
    cudaFuncSetAttribute(gemm_kernel<128, 2>, cudaFuncAttributeMaxDynamicSharedMemorySize, SM_G128);
    cudaFuncSetAttribute(gru_gemm_kernel, cudaFuncAttributeMaxDynamicSharedMemorySize, SM_G128);

    cudaMemsetAsync(p_cnt, 0, N_NODES * sizeof(int));

    // #1 histogram + all weight prep
    hist_prep_kernel<<<(N_EDGES + 255) / 256, 256>>>(dst, W_edge, W_ih, W_hh);
    // #2 scan
    scan_kernel<<<1, 1024>>>();
    // #3 node embed + fused hvdot
    int ntiles = (N_NODES + 63) / 64;
    node_embed_kernel<<<ntiles, 256, SM_NODE>>>(node_feats, W_node, b_node, W_logit);
    // #4 edge GEMM on tensor cores (profiled slot)
    float* outEF = (out_size >= N_NODES * NHID + N_EDGES * 64) ? (out + N_NODES * NHID) : nullptr;
    edge_mma_kernel<<<N_EDGES / 128, 256, SM_EDGE_TOTAL>>>(node_feats, edge_feats, src, dst,
                                                           b_edge, W_logit, b_logit, outEF);
    // #5 softmax-weighted segment sum
    aggregate_kernel<<<(N_NODES + 7) / 8, 256>>>();
    // #6 C_v = elu(A @ W_msg + b_msg)
    gemm_kernel<128, 2><<<ntiles, 256, SM_G128>>>(p_A, 128, N_NODES,
                                                  W_msg, 128, b_msg, p_cv, 128);
    // #7 gi / gh in one launch
    gru_gemm_kernel<<<dim3(ntiles, 6), 256, SM_G128>>>(b_ih, b_hh);
    // #8 gates -> h_new
    gate_kernel<<<(N_NODES * NHID + 255) / 256, 256>>>(out);
}

// round 7
// speedup vs baseline: 2.4586x; 1.1542x over previous
#include <cuda_runtime.h>
#include <cuda_bf16.h>
#include <cuda_fp16.h>
#include <math.h>
#include <stdint.h>

#define N_NODES 10000
#define N_EDGES 640000
#define NHID    128
#define EHID    128
#define CSIZE   128

// ---------------- scratch (device globals; no allocation) ----------------
__device__ float g_h_v[N_NODES * NHID];
__device__ float g_hvdot[N_NODES];
__device__ __half g_h_e16[(size_t)N_EDGES * EHID];  // CSR-ordered rows, fp16 (164MB)
__device__ float g_logit[N_EDGES];                  // CSR-ordered
__device__ float g_A[N_NODES * EHID];
__device__ float g_cv[N_NODES * CSIZE];
__device__ float g_gi[N_NODES * 3 * NHID];
__device__ float g_gh[N_NODES * 3 * NHID];
__device__ float g_WihT[NHID * 3 * NHID];
__device__ float g_WhhT[NHID * 3 * NHID];
__device__ int   g_cnt[N_NODES];
__device__ int   g_off[N_NODES + 1];
__device__ int   g_cur[N_NODES];
// B operand image: fp16 W_edge^T, [n=128][k stride 136]
#define A_STRIDE 136
__device__ __half g_B[128 * A_STRIDE];

__device__ __forceinline__ float leaky01(float v) { return v > 0.f ? v : 0.01f * v; }

__device__ __forceinline__ uint32_t smem_u32(const void* p) {
    uint32_t a;
    asm("{ .reg .u64 t; cvta.to.shared.u64 t, %1; cvt.u32.u64 %0, t; }" : "=r"(a) : "l"(p));
    return a;
}
__device__ __forceinline__ void ldsm_x4(uint32_t* r, uint32_t addr) {
    asm volatile("ldmatrix.sync.aligned.m8n8.x4.shared.b16 {%0,%1,%2,%3}, [%4];"
        : "=r"(r[0]), "=r"(r[1]), "=r"(r[2]), "=r"(r[3]) : "r"(addr));
}
__device__ __forceinline__ void mma_f16(float* c, const uint32_t* a, const uint32_t* b) {
    asm volatile("mma.sync.aligned.m16n8k16.row.col.f32.f16.f16.f32 "
        "{%0,%1,%2,%3}, {%4,%5,%6,%7}, {%8,%9}, {%0,%1,%2,%3};"
        : "+f"(c[0]), "+f"(c[1]), "+f"(c[2]), "+f"(c[3])
        : "r"(a[0]), "r"(a[1]), "r"(a[2]), "r"(a[3]), "r"(b[0]), "r"(b[1]));
}

// ---------------- launch #1: histogram + weight prep ----------------
__global__ void hist_prep_kernel(const int* __restrict__ dst,
                                 const float* __restrict__ We,
                                 const float* __restrict__ Wih,
                                 const float* __restrict__ Whh)
{
    int e = blockIdx.x * blockDim.x + threadIdx.x;
    if (e < N_EDGES) atomicAdd(&g_cnt[dst[e]], 1);
    // B image: W_edge^T in fp16, stride 136
    if (e < 128 * 64) {
        int n = e >> 6, k = (e & 63) * 2;
        __half2 h = __floats2half2_rn(We[k * 128 + n], We[(k + 1) * 128 + n]);
        *(uint32_t*)&g_B[n * A_STRIDE + k] = *(uint32_t*)&h;
    }
    // GRU weight transpose
    if (e < 384 * 128) {
        int r = e / 128, k = e % 128;
        g_WihT[k * 384 + r] = Wih[e];
        g_WhhT[k * 384 + r] = Whh[e];
    }
}

// ---------------- launch #2: exclusive scan of counts -> off/cur ----------------
__global__ void scan_kernel() {
    __shared__ int s[1024];
    __shared__ int s_carry;
    if (threadIdx.x == 0) s_carry = 0;
    __syncthreads();
    for (int base = 0; base < N_NODES; base += 1024) {
        int i = base + threadIdx.x;
        int v = (i < N_NODES) ? g_cnt[i] : 0;
        s[threadIdx.x] = v;
        __syncthreads();
        for (int d = 1; d < 1024; d <<= 1) {
            int t = 0;
            if ((int)threadIdx.x >= d) t = s[threadIdx.x - d];
            __syncthreads();
            s[threadIdx.x] += t;
            __syncthreads();
        }
        int incl = s[threadIdx.x] + s_carry;
        if (i < N_NODES) { g_off[i] = incl - v; g_cur[i] = incl - v; }
        __syncthreads();
        if (threadIdx.x == 1023) s_carry = incl;
        __syncthreads();
    }
    if (threadIdx.x == 0) g_off[N_NODES] = s_carry;
}

// ---------------- launch #3: node embed GEMM (K=64, leaky) + fused hvdot ----------------
__global__ __launch_bounds__(256) void node_embed_kernel(
    const float* __restrict__ nf, const float* __restrict__ Wn,
    const float* __restrict__ bn, const float* __restrict__ Wl)
{
    extern __shared__ float sm[];
    float* sW = sm;            // 64*128
    float* sX = sm + 8192;     // 64*64
    float* sB = sm + 12288;    // 128
    float* sWL = sm + 12416;   // 128
    int t = threadIdx.x;
    int r0g = blockIdx.x * 64;
    for (int i = t; i < 64 * 128; i += 256) {
        int k = i >> 7, c = i & 127;
        sW[i] = Wn[k * 128 + c];
    }
    for (int i = t; i < 64 * 64; i += 256) {
        int r = i >> 6, k = i & 63;
        int gr = r0g + r;
        sX[i] = (gr < N_NODES) ? nf[gr * 64 + k] : 0.f;
    }
    if (t < 128) { sB[t] = bn[t]; sWL[t] = Wl[t]; }
    __syncthreads();
    int cx = t & 31, cy = t >> 5;
    int r0 = cy * 8, c0 = cx * 4;
    float acc[8][4] = {};
#pragma unroll 4
    for (int k = 0; k < 64; k++) {
        float4 w = *(const float4*)&sW[k * 128 + c0];
#pragma unroll
        for (int r = 0; r < 8; r++) {
            float x = sX[(r0 + r) * 64 + k];
            acc[r][0] += x * w.x; acc[r][1] += x * w.y;
            acc[r][2] += x * w.z; acc[r][3] += x * w.w;
        }
    }
    float wl0 = sWL[c0], wl1 = sWL[c0 + 1], wl2 = sWL[c0 + 2], wl3 = sWL[c0 + 3];
#pragma unroll
    for (int r = 0; r < 8; r++) {
        int gr = r0g + r0 + r;
        if (gr >= N_NODES) break;
        float v0 = leaky01(acc[r][0] + sB[c0]);
        float v1 = leaky01(acc[r][1] + sB[c0 + 1]);
        float v2 = leaky01(acc[r][2] + sB[c0 + 2]);
        float v3 = leaky01(acc[r][3] + sB[c0 + 3]);
        *(float4*)&g_h_v[(size_t)gr * 128 + c0] = make_float4(v0, v1, v2, v3);
        float p = v0 * wl0 + v1 * wl1 + v2 * wl2 + v3 * wl3;
        for (int o = 16; o; o >>= 1) p += __shfl_xor_sync(0xffffffffu, p, o);
        if (cx == 0) g_hvdot[gr] = p;
    }
}

// ============ launch #4: edge GEMM on HMMA, single-pass fp16, 2 CTAs/SM ============
#define SM_SRC   0
#define SM_PERM  512
#define SM_BIAS  1024
#define SM_WL    1536
#define SM_LOG   2048
#define SM_AHI   3072
#define SM_B     (SM_AHI + 34816)
#define SM_EDGE_TOTAL (SM_B + 34816)   // 72704 bytes

__global__ __launch_bounds__(256, 2)
void edge_mma_kernel(const float* __restrict__ nf, const float* __restrict__ ef,
                     const int* __restrict__ src, const int* __restrict__ dst,
                     const float* __restrict__ b_edge,
                     const float* __restrict__ W_logit, const float* __restrict__ b_logit,
                     float* __restrict__ outEF)
{
    extern __shared__ __align__(16) char smem[];
    uint32_t sb = smem_u32(smem);
    int t = threadIdx.x, lane = t & 31, wid = t >> 5;
    int e0 = blockIdx.x * 128;
    int* sSrc = (int*)(smem + SM_SRC);
    int* sPerm = (int*)(smem + SM_PERM);
    float* sBias = (float*)(smem + SM_BIAS);
    float* sWL = (float*)(smem + SM_WL);
    float* sLog = (float*)(smem + SM_LOG);

    if (t < 128) {
        sSrc[t] = src[e0 + t];
        sPerm[t] = atomicAdd(&g_cur[dst[e0 + t]], 1);
        sBias[t] = b_edge[t];
        sWL[t] = W_logit[128 + t];
    }
    // copy B image (34KB, L2-hot)
    {
        const float4* bs = (const float4*)g_B;
        float4* bd = (float4*)(smem + SM_B);
#pragma unroll
        for (int i = 0; i < 8; i++) bd[t + 256 * i] = bs[t + 256 * i];
        if (t < 128) bd[2048 + t] = bs[2048 + t];
    }
    __syncthreads();

    // A gather: row r from [nf[src[r]] | ef[e0+r]], fp16.
    // hf==1 threads also stream the ef row to the output passthrough region.
    {
        int r = t >> 1, hf = t & 1;
        const float4* xp = hf ? (const float4*)(ef + (size_t)(e0 + r) * 64)
                              : (const float4*)(nf + (size_t)sSrc[r] * 64);
        float4* eo = (hf && outEF) ? (float4*)(outEF + (size_t)(e0 + r) * 64) : nullptr;
        char* hi = smem + SM_AHI + r * (A_STRIDE * 2) + hf * 128;
#pragma unroll
        for (int j = 0; j < 16; j++) {
            float4 v = xp[j];
            if (eo) eo[j] = v;
            __half2 h01 = __floats2half2_rn(v.x, v.y);
            __half2 h23 = __floats2half2_rn(v.z, v.w);
            *(uint2*)(hi + j * 8) = make_uint2(*(uint32_t*)&h01, *(uint32_t*)&h23);
        }
    }
    __syncthreads();

    // warp tile: M=32 (mg), N=64 (ng)
    int mg = wid & 3, ng = wid >> 2;
    int m0 = mg * 32, n0 = ng * 64;
    float acc[2][8][4];
#pragma unroll
    for (int i = 0; i < 2; i++)
#pragma unroll
        for (int j = 0; j < 8; j++)
#pragma unroll
            for (int c = 0; c < 4; c++) acc[i][j][c] = 0.f;

    uint32_t aOffL = ((lane & 15) * A_STRIDE + (lane >> 4) * 8) * 2;
    uint32_t bOffL = (((lane & 7) + ((lane >> 4) << 3)) * A_STRIDE + ((lane >> 3) & 1) * 8) * 2;
    uint32_t Ab = sb + SM_AHI, Bb = sb + SM_B;

#pragma unroll
    for (int k8 = 0; k8 < 8; k8++) {
        uint32_t kb = k8 * 32;
        uint32_t b[4][4];
#pragma unroll
        for (int q = 0; q < 4; q++)
            ldsm_x4(b[q], Bb + bOffL + (uint32_t)(n0 + q * 16) * 272 + kb);
        uint32_t a[2][4];
        ldsm_x4(a[0], Ab + aOffL + (uint32_t)m0 * 272 + kb);
        ldsm_x4(a[1], Ab + aOffL + (uint32_t)(m0 + 16) * 272 + kb);
#pragma unroll
        for (int ms = 0; ms < 2; ms++)
#pragma unroll
            for (int q = 0; q < 4; q++) {
                mma_f16(acc[ms][q * 2],     a[ms], &b[q][0]);
                mma_f16(acc[ms][q * 2 + 1], a[ms], &b[q][2]);
            }
    }

    // epilogue: bias + leaky + store h_e fp16 (CSR slot) + partial logit
#pragma unroll
    for (int ms = 0; ms < 2; ms++) {
        int r1 = m0 + ms * 16 + (lane >> 2);
        int r2 = r1 + 8;
        float lg1 = 0.f, lg2 = 0.f;
        __half* o1 = g_h_e16 + (size_t)sPerm[r1] * 128;
        __half* o2 = g_h_e16 + (size_t)sPerm[r2] * 128;
#pragma unroll
        for (int ns = 0; ns < 8; ns++) {
            int col = n0 + ns * 8 + (lane & 3) * 2;
            float v0 = leaky01(acc[ms][ns][0] + sBias[col]);
            float v1 = leaky01(acc[ms][ns][1] + sBias[col + 1]);
            float v2 = leaky01(acc[ms][ns][2] + sBias[col]);
            float v3 = leaky01(acc[ms][ns][3] + sBias[col + 1]);
            lg1 += v0 * sWL[col] + v1 * sWL[col + 1];
            lg2 += v2 * sWL[col] + v3 * sWL[col + 1];
            *(__half2*)(o1 + col) = __floats2half2_rn(v0, v1);
            *(__half2*)(o2 + col) = __floats2half2_rn(v2, v3);
        }
        lg1 += __shfl_xor_sync(0xffffffffu, lg1, 1);
        lg1 += __shfl_xor_sync(0xffffffffu, lg1, 2);
        lg2 += __shfl_xor_sync(0xffffffffu, lg2, 1);
        lg2 += __shfl_xor_sync(0xffffffffu, lg2, 2);
        if ((lane & 3) == 0) {
            sLog[r1 * 2 + ng] = lg1;
            sLog[r2 * 2 + ng] = lg2;
        }
    }
    __syncthreads();
    if (t < 128) {
        float s = sLog[t * 2] + sLog[t * 2 + 1] + g_hvdot[sSrc[t]] + b_logit[0];
        g_logit[sPerm[t]] = leaky01(s);
    }
}

// ---------------- launch #5: per-node softmax + weighted sum (CSR-sequential, fp16 reads) ----------------
__global__ void aggregate_kernel() {
    int v = (blockIdx.x * blockDim.x + threadIdx.x) >> 5;
    int lane = threadIdx.x & 31;
    if (v >= N_NODES) return;
    int s = g_off[v], e = g_off[v + 1];
    float mx = -1e30f;
    for (int i = s + lane; i < e; i += 32)
        mx = fmaxf(mx, g_logit[i]);
    for (int o = 16; o; o >>= 1)
        mx = fmaxf(mx, __shfl_xor_sync(0xffffffffu, mx, o));
    float4 acc = make_float4(0.f, 0.f, 0.f, 0.f);
    float den = 0.f;
    for (int i = s; i < e; i++) {
        float w = expf(g_logit[i] - mx);
        den += w;
        uint2 raw = *(const uint2*)(g_h_e16 + (size_t)i * 128 + lane * 4);
        float2 f01 = __half22float2(*(__half2*)&raw.x);
        float2 f23 = __half22float2(*(__half2*)&raw.y);
        acc.x += w * f01.x; acc.y += w * f01.y;
        acc.z += w * f23.x; acc.w += w * f23.y;
    }
    float inv = (e > s) ? 1.f / den : 0.f;
    acc.x *= inv; acc.y *= inv; acc.z *= inv; acc.w *= inv;
    *(float4*)&g_A[v * 128 + lane * 4] = acc;
}

// ---------------- generic tiled GEMM: out = act(X @ W + b), 64x128 tile ----------------
template <int K, int ACT>
__global__ __launch_bounds__(256) void gemm_kernel(
    const float* __restrict__ X, int ldx, int rows,
    const float* __restrict__ W, int ldw,
    const float* __restrict__ b,
    float* __restrict__ out, int ldo)
{
    extern __shared__ float sm[];
    float* sW = sm;
    float* sX = sW + K * 128;
    float* sB = sX + 64 * K;
    int t = threadIdx.x;
    int r0g = blockIdx.x * 64;
    for (int i = t; i < K * 128; i += 256) {
        int k = i >> 7, c = i & 127;
        sW[i] = W[(size_t)k * ldw + c];
    }
    for (int i = t; i < 64 * K; i += 256) {
        int r = i / K, k = i % K;
        int gr = r0g + r;
        sX[i] = (gr < rows) ? X[(size_t)gr * ldx + k] : 0.f;
    }
    if (t < 128) sB[t] = b[t];
    __syncthreads();
    int cx = t & 31, cy = t >> 5;
    int r0 = cy * 8, c0 = cx * 4;
    float acc[8][4] = {};
#pragma unroll 4
    for (int k = 0; k < K; k++) {
        float4 w = *(const float4*)&sW[k * 128 + c0];
#pragma unroll
        for (int r = 0; r < 8; r++) {
            float x = sX[(r0 + r) * K + k];
            acc[r][0] += x * w.x; acc[r][1] += x * w.y;
            acc[r][2] += x * w.z; acc[r][3] += x * w.w;
        }
    }
#pragma unroll
    for (int r = 0; r < 8; r++) {
        int gr = r0g + r0 + r;
        if (gr >= rows) break;
#pragma unroll
        for (int c = 0; c < 4; c++) {
            float v = acc[r][c] + sB[c0 + c];
            if (ACT == 1) v = leaky01(v);
            else if (ACT == 2) v = (v > 0.f) ? v : (expf(v) - 1.f);
            acc[r][c] = v;
        }
        *(float4*)&out[(size_t)gr * ldo + c0] = make_float4(acc[r][0], acc[r][1], acc[r][2], acc[r][3]);
    }
}

// ---------------- fused GRU GEMMs: one launch, blockIdx.y selects (mat, chunk) ----------------
__global__ __launch_bounds__(256) void gru_gemm_kernel(const float* __restrict__ b_ih,
                                                       const float* __restrict__ b_hh)
{
    extern __shared__ float sm[];
    float* sW = sm;
    float* sX = sW + 128 * 128;
    float* sB = sX + 64 * 128;
    int mat = blockIdx.y / 3, chunk = blockIdx.y % 3;
    const float* X = mat ? g_h_v : g_cv;
    const float* W = (mat ? g_WhhT : g_WihT) + chunk * 128;
    const float* b = (mat ? b_hh : b_ih) + chunk * 128;
    float* out = (mat ? g_gh : g_gi) + chunk * 128;
    int t = threadIdx.x;
    int r0g = blockIdx.x * 64;
    for (int i = t; i < 128 * 128; i += 256) {
        int k = i >> 7, c = i & 127;
        sW[i] = W[k * 384 + c];
    }
    for (int i = t; i < 64 * 128; i += 256) {
        int r = i >> 7, k = i & 127;
        int gr = r0g + r;
        sX[i] = (gr < N_NODES) ? X[gr * 128 + k] : 0.f;
    }
    if (t < 128) sB[t] = b[t];
    __syncthreads();
    int cx = t & 31, cy = t >> 5;
    int r0 = cy * 8, c0 = cx * 4;
    float acc[8][4] = {};
#pragma unroll 4
    for (int k = 0; k < 128; k++) {
        float4 w = *(const float4*)&sW[k * 128 + c0];
#pragma unroll
        for (int r = 0; r < 8; r++) {
            float x = sX[(r0 + r) * 128 + k];
            acc[r][0] += x * w.x; acc[r][1] += x * w.y;
            acc[r][2] += x * w.z; acc[r][3] += x * w.w;
        }
    }
#pragma unroll
    for (int r = 0; r < 8; r++) {
        int gr = r0g + r0 + r;
        if (gr >= N_NODES) break;
        *(float4*)&out[(size_t)gr * 384 + c0] = make_float4(
            acc[r][0] + sB[c0], acc[r][1] + sB[c0 + 1], acc[r][2] + sB[c0 + 2], acc[r][3] + sB[c0 + 3]);
    }
}

// ---------------- GRU gates + relu ----------------
__global__ void gate_kernel(float* __restrict__ out) {
    int idx = blockIdx.x * blockDim.x + threadIdx.x;
    if (idx >= N_NODES * NHID) return;
    int n = idx >> 7, j = idx & 127;
    const float* gi = &g_gi[n * 384];
    const float* gh = &g_gh[n * 384];
    float r = 1.f / (1.f + expf(-(gi[j] + gh[j])));
    float z = 1.f / (1.f + expf(-(gi[128 + j] + gh[128 + j])));
    float nn = tanhf(gi[256 + j] + r * gh[256 + j]);
    float hv = g_h_v[idx];
    float h = (1.f - z) * nn + z * hv;
    out[idx] = h > 0.f ? h : 0.f;
}

// ---------------- launch ----------------
extern "C" void kernel_launch(void* const* d_in, const int* in_sizes, int n_in,
                              void* d_out, int out_size) {
    const float* node_feats = (const float*)d_in[0];
    const float* edge_feats = (const float*)d_in[1];
    const float* W_node  = (const float*)d_in[2];
    const float* b_node  = (const float*)d_in[3];
    const float* W_edge  = (const float*)d_in[4];
    const float* b_edge  = (const float*)d_in[5];
    const float* W_logit = (const float*)d_in[6];
    const float* b_logit = (const float*)d_in[7];
    const float* W_msg   = (const float*)d_in[8];
    const float* b_msg   = (const float*)d_in[9];
    const float* W_ih    = (const float*)d_in[10];
    const float* W_hh    = (const float*)d_in[11];
    const float* b_ih    = (const float*)d_in[12];
    const float* b_hh    = (const float*)d_in[13];
    const int*   src     = (const int*)d_in[14];
    const int*   dst     = (const int*)d_in[15];
    float* out = (float*)d_out;

    float *p_A, *p_cv;
    int* p_cnt;
    cudaGetSymbolAddress((void**)&p_A, g_A);
    cudaGetSymbolAddress((void**)&p_cv, g_cv);
    cudaGetSymbolAddress((void**)&p_cnt, g_cnt);

    const int SM_G128 = (128 * 128 + 64 * 128 + 128) * 4;
    const int SM_NODE = (64 * 128 + 64 * 64 + 256) * 4;
    cudaFuncSetAttribute(edge_mma_kernel, cudaFuncAttributeMaxDynamicSharedMemorySize, SM_EDGE_TOTAL);
    cudaFuncSetAttribute(node_embed_kernel, cudaFuncAttributeMaxDynamicSharedMemorySize, SM_NODE);
    cudaFuncSetAttribute(gemm_kernel<128, 2>, cudaFuncAttributeMaxDynamicSharedMemorySize, SM_G128);
    cudaFuncSetAttribute(gru_gemm_kernel, cudaFuncAttributeMaxDynamicSharedMemorySize, SM_G128);

    cudaMemsetAsync(p_cnt, 0, N_NODES * sizeof(int));

    // #1 histogram + all weight prep
    hist_prep_kernel<<<(N_EDGES + 255) / 256, 256>>>(dst, W_edge, W_ih, W_hh);
    // #2 scan
    scan_kernel<<<1, 1024>>>();
    // #3 node embed + fused hvdot
    int ntiles = (N_NODES + 63) / 64;
    node_embed_kernel<<<ntiles, 256, SM_NODE>>>(node_feats, W_node, b_node, W_logit);
    // #4 edge GEMM on tensor cores (profiled slot)
    float* outEF = (out_size >= N_NODES * NHID + N_EDGES * 64) ? (out + N_NODES * NHID) : nullptr;
    edge_mma_kernel<<<N_EDGES / 128, 256, SM_EDGE_TOTAL>>>(node_feats, edge_feats, src, dst,
                                                           b_edge, W_logit, b_logit, outEF);
    // #5 softmax-weighted segment sum
    aggregate_kernel<<<(N_NODES + 7) / 8, 256>>>();
    // #6 C_v = elu(A @ W_msg + b_msg)
    gemm_kernel<128, 2><<<ntiles, 256, SM_G128>>>(p_A, 128, N_NODES,
                                                  W_msg, 128, b_msg, p_cv, 128);
    // #7 gi / gh in one launch
    gru_gemm_kernel<<<dim3(ntiles, 6), 256, SM_G128>>>(b_ih, b_hh);
    // #8 gates -> h_new
    gate_kernel<<<(N_NODES * NHID + 255) / 256, 256>>>(out);
}

// round 8
// speedup vs baseline: 2.4750x; 1.0066x over previous
#include <cuda_runtime.h>
#include <cuda_bf16.h>
#include <cuda_fp16.h>
#include <math.h>
#include <stdint.h>

#define N_NODES 10000
#define N_EDGES 640000
#define NHID    128
#define EHID    128
#define CSIZE   128

// ---------------- scratch (device globals; no allocation) ----------------
__device__ float g_h_v[N_NODES * NHID];
__device__ float g_hvdot[N_NODES];
__device__ __half g_h_e16[(size_t)N_EDGES * EHID];  // CSR-ordered rows, fp16 (164MB)
__device__ float g_logit[N_EDGES];                  // CSR-ordered
__device__ float g_A[N_NODES * EHID];
__device__ float g_cv[N_NODES * CSIZE];
__device__ float g_gi[N_NODES * 3 * NHID];
__device__ float g_gh[N_NODES * 3 * NHID];
__device__ float g_WihT[NHID * 3 * NHID];
__device__ float g_WhhT[NHID * 3 * NHID];
__device__ int   g_cnt[N_NODES];
__device__ int   g_off[N_NODES + 1];
__device__ int   g_cur[N_NODES];
// B operand as pre-built mma fragments: [ng(2)][k8(8)][q(4)][lane(32)] uint4
__device__ uint4 g_Bfrag[2048];

#define A_STRIDE 136   // halves; 272 bytes

__device__ __forceinline__ float leaky01(float v) { return v > 0.f ? v : 0.01f * v; }

__device__ __forceinline__ uint32_t smem_u32(const void* p) {
    uint32_t a;
    asm("{ .reg .u64 t; cvta.to.shared.u64 t, %1; cvt.u32.u64 %0, t; }" : "=r"(a) : "l"(p));
    return a;
}
__device__ __forceinline__ void ldsm_x4(uint32_t* r, uint32_t addr) {
    asm volatile("ldmatrix.sync.aligned.m8n8.x4.shared.b16 {%0,%1,%2,%3}, [%4];"
        : "=r"(r[0]), "=r"(r[1]), "=r"(r[2]), "=r"(r[3]) : "r"(addr));
}
__device__ __forceinline__ void mma_f16(float* c, const uint32_t* a, const uint32_t* b) {
    asm volatile("mma.sync.aligned.m16n8k16.row.col.f32.f16.f16.f32 "
        "{%0,%1,%2,%3}, {%4,%5,%6,%7}, {%8,%9}, {%0,%1,%2,%3};"
        : "+f"(c[0]), "+f"(c[1]), "+f"(c[2]), "+f"(c[3])
        : "r"(a[0]), "r"(a[1]), "r"(a[2]), "r"(a[3]), "r"(b[0]), "r"(b[1]));
}

// ---------------- launch #1: histogram + weight prep ----------------
__global__ void hist_prep_kernel(const int* __restrict__ dst,
                                 const float* __restrict__ We,
                                 const float* __restrict__ Wih,
                                 const float* __restrict__ Whh)
{
    int e = blockIdx.x * blockDim.x + threadIdx.x;
    if (e < N_EDGES) atomicAdd(&g_cnt[dst[e]], 1);
    // B fragment image: mma m16n8k16 .col B fragments of W_edge (B[n][k] = We[k][n])
    if (e < 2048) {
        int lane = e & 31, q = (e >> 5) & 3, k8 = (e >> 7) & 7, ng = e >> 10;
        int n1 = ng * 64 + q * 16 + (lane >> 2);
        int n2 = n1 + 8;
        int k0 = k8 * 16 + 2 * (lane & 3);
        uint4 v;
        __half2 h;
        h = __floats2half2_rn(We[k0 * 128 + n1], We[(k0 + 1) * 128 + n1]); v.x = *(uint32_t*)&h;
        h = __floats2half2_rn(We[(k0 + 8) * 128 + n1], We[(k0 + 9) * 128 + n1]); v.y = *(uint32_t*)&h;
        h = __floats2half2_rn(We[k0 * 128 + n2], We[(k0 + 1) * 128 + n2]); v.z = *(uint32_t*)&h;
        h = __floats2half2_rn(We[(k0 + 8) * 128 + n2], We[(k0 + 9) * 128 + n2]); v.w = *(uint32_t*)&h;
        g_Bfrag[e] = v;
    }
    // GRU weight transpose
    if (e < 384 * 128) {
        int r = e / 128, k = e % 128;
        g_WihT[k * 384 + r] = Wih[e];
        g_WhhT[k * 384 + r] = Whh[e];
    }
}

// ---------------- launch #2: exclusive scan of counts -> off/cur ----------------
__global__ void scan_kernel() {
    __shared__ int s[1024];
    __shared__ int s_carry;
    if (threadIdx.x == 0) s_carry = 0;
    __syncthreads();
    for (int base = 0; base < N_NODES; base += 1024) {
        int i = base + threadIdx.x;
        int v = (i < N_NODES) ? g_cnt[i] : 0;
        s[threadIdx.x] = v;
        __syncthreads();
        for (int d = 1; d < 1024; d <<= 1) {
            int t = 0;
            if ((int)threadIdx.x >= d) t = s[threadIdx.x - d];
            __syncthreads();
            s[threadIdx.x] += t;
            __syncthreads();
        }
        int incl = s[threadIdx.x] + s_carry;
        if (i < N_NODES) { g_off[i] = incl - v; g_cur[i] = incl - v; }
        __syncthreads();
        if (threadIdx.x == 1023) s_carry = incl;
        __syncthreads();
    }
    if (threadIdx.x == 0) g_off[N_NODES] = s_carry;
}

// ---------------- launch #3: node embed GEMM (K=64, leaky) + fused hvdot ----------------
__global__ __launch_bounds__(256) void node_embed_kernel(
    const float* __restrict__ nf, const float* __restrict__ Wn,
    const float* __restrict__ bn, const float* __restrict__ Wl)
{
    extern __shared__ float sm[];
    float* sW = sm;            // 64*128
    float* sX = sm + 8192;     // 64*64
    float* sB = sm + 12288;    // 128
    float* sWL = sm + 12416;   // 128
    int t = threadIdx.x;
    int r0g = blockIdx.x * 64;
    for (int i = t; i < 64 * 128; i += 256) {
        int k = i >> 7, c = i & 127;
        sW[i] = Wn[k * 128 + c];
    }
    for (int i = t; i < 64 * 64; i += 256) {
        int r = i >> 6, k = i & 63;
        int gr = r0g + r;
        sX[i] = (gr < N_NODES) ? nf[gr * 64 + k] : 0.f;
    }
    if (t < 128) { sB[t] = bn[t]; sWL[t] = Wl[t]; }
    __syncthreads();
    int cx = t & 31, cy = t >> 5;
    int r0 = cy * 8, c0 = cx * 4;
    float acc[8][4] = {};
#pragma unroll 4
    for (int k = 0; k < 64; k++) {
        float4 w = *(const float4*)&sW[k * 128 + c0];
#pragma unroll
        for (int r = 0; r < 8; r++) {
            float x = sX[(r0 + r) * 64 + k];
            acc[r][0] += x * w.x; acc[r][1] += x * w.y;
            acc[r][2] += x * w.z; acc[r][3] += x * w.w;
        }
    }
    float wl0 = sWL[c0], wl1 = sWL[c0 + 1], wl2 = sWL[c0 + 2], wl3 = sWL[c0 + 3];
#pragma unroll
    for (int r = 0; r < 8; r++) {
        int gr = r0g + r0 + r;
        if (gr >= N_NODES) break;
        float v0 = leaky01(acc[r][0] + sB[c0]);
        float v1 = leaky01(acc[r][1] + sB[c0 + 1]);
        float v2 = leaky01(acc[r][2] + sB[c0 + 2]);
        float v3 = leaky01(acc[r][3] + sB[c0 + 3]);
        *(float4*)&g_h_v[(size_t)gr * 128 + c0] = make_float4(v0, v1, v2, v3);
        float p = v0 * wl0 + v1 * wl1 + v2 * wl2 + v3 * wl3;
        for (int o = 16; o; o >>= 1) p += __shfl_xor_sync(0xffffffffu, p, o);
        if (cx == 0) g_hvdot[gr] = p;
    }
}

// ============ launch #4: edge GEMM on HMMA, 64 edges/CTA, B via fragment LDG, 4 CTAs/SM ============
#define SM_SRC   0
#define SM_PERM  256
#define SM_BIAS  512
#define SM_WL    1024
#define SM_LOG   1536
#define SM_A     2048
#define SM_EDGE_TOTAL (SM_A + 64 * 272)   // 19456 bytes -> 4 CTAs/SM

__global__ __launch_bounds__(128, 4)
void edge_mma_kernel(const float* __restrict__ nf, const float* __restrict__ ef,
                     const int* __restrict__ src, const int* __restrict__ dst,
                     const float* __restrict__ b_edge,
                     const float* __restrict__ W_logit, const float* __restrict__ b_logit,
                     float* __restrict__ outEF)
{
    extern __shared__ __align__(16) char smem[];
    uint32_t sb = smem_u32(smem);
    int t = threadIdx.x, lane = t & 31, wid = t >> 5;
    int e0 = blockIdx.x * 64;
    int* sSrc = (int*)(smem + SM_SRC);
    int* sPerm = (int*)(smem + SM_PERM);
    float* sBias = (float*)(smem + SM_BIAS);
    float* sWL = (float*)(smem + SM_WL);
    float* sLog = (float*)(smem + SM_LOG);

    if (t < 64) {
        sSrc[t] = src[e0 + t];
        sPerm[t] = atomicAdd(&g_cur[dst[e0 + t]], 1);
    }
    sBias[t] = b_edge[t];
    sWL[t] = W_logit[128 + t];
    __syncthreads();

    // A gather: row r from [nf[src[r]] | ef[e0+r]], fp16, packed STS.128.
    // hf==1 threads also stream the ef row to the output passthrough region.
    {
        int r = t >> 1, hf = t & 1;
        const float4* xp = hf ? (const float4*)(ef + (size_t)(e0 + r) * 64)
                              : (const float4*)(nf + (size_t)sSrc[r] * 64);
        float4* eo = (hf && outEF) ? (float4*)(outEF + (size_t)(e0 + r) * 64) : nullptr;
        char* hi = smem + SM_A + r * 272 + hf * 128;
#pragma unroll
        for (int j2 = 0; j2 < 8; j2++) {
            float4 v0 = xp[2 * j2];
            float4 v1 = xp[2 * j2 + 1];
            if (eo) { eo[2 * j2] = v0; eo[2 * j2 + 1] = v1; }
            __half2 a0 = __floats2half2_rn(v0.x, v0.y);
            __half2 a1 = __floats2half2_rn(v0.z, v0.w);
            __half2 a2 = __floats2half2_rn(v1.x, v1.y);
            __half2 a3 = __floats2half2_rn(v1.z, v1.w);
            uint4 pk = make_uint4(*(uint32_t*)&a0, *(uint32_t*)&a1,
                                  *(uint32_t*)&a2, *(uint32_t*)&a3);
            *(uint4*)(hi + j2 * 16) = pk;
        }
    }
    __syncthreads();

    // warp tile: 4 warps, M=32 (mg in 0..1), N=64 (ng in 0..1)
    int mg = wid & 1, ng = wid >> 1;
    int m0 = mg * 32, n0 = ng * 64;
    float acc[2][8][4];
#pragma unroll
    for (int i = 0; i < 2; i++)
#pragma unroll
        for (int j = 0; j < 8; j++)
#pragma unroll
            for (int c = 0; c < 4; c++) acc[i][j][c] = 0.f;

    uint32_t aOffL = ((lane & 15) * A_STRIDE + (lane >> 4) * 8) * 2;
    uint32_t Ab = sb + SM_A;
    const uint4* bf = g_Bfrag + ng * 1024 + lane;

#pragma unroll
    for (int k8 = 0; k8 < 8; k8++) {
        uint32_t kb = k8 * 32;
        uint4 bq[4];
#pragma unroll
        for (int q = 0; q < 4; q++)
            bq[q] = bf[k8 * 128 + q * 32];
        uint32_t a[2][4];
        ldsm_x4(a[0], Ab + aOffL + (uint32_t)m0 * 272 + kb);
        ldsm_x4(a[1], Ab + aOffL + (uint32_t)(m0 + 16) * 272 + kb);
#pragma unroll
        for (int ms = 0; ms < 2; ms++)
#pragma unroll
            for (int q = 0; q < 4; q++) {
                const uint32_t* bb = (const uint32_t*)&bq[q];
                mma_f16(acc[ms][q * 2],     a[ms], bb);
                mma_f16(acc[ms][q * 2 + 1], a[ms], bb + 2);
            }
    }

    // epilogue: bias + leaky + store h_e fp16 (CSR slot) + partial logit
#pragma unroll
    for (int ms = 0; ms < 2; ms++) {
        int r1 = m0 + ms * 16 + (lane >> 2);
        int r2 = r1 + 8;
        float lg1 = 0.f, lg2 = 0.f;
        __half* o1 = g_h_e16 + (size_t)sPerm[r1] * 128;
        __half* o2 = g_h_e16 + (size_t)sPerm[r2] * 128;
#pragma unroll
        for (int ns = 0; ns < 8; ns++) {
            int col = n0 + ns * 8 + (lane & 3) * 2;
            float v0 = leaky01(acc[ms][ns][0] + sBias[col]);
            float v1 = leaky01(acc[ms][ns][1] + sBias[col + 1]);
            float v2 = leaky01(acc[ms][ns][2] + sBias[col]);
            float v3 = leaky01(acc[ms][ns][3] + sBias[col + 1]);
            lg1 += v0 * sWL[col] + v1 * sWL[col + 1];
            lg2 += v2 * sWL[col] + v3 * sWL[col + 1];
            *(__half2*)(o1 + col) = __floats2half2_rn(v0, v1);
            *(__half2*)(o2 + col) = __floats2half2_rn(v2, v3);
        }
        lg1 += __shfl_xor_sync(0xffffffffu, lg1, 1);
        lg1 += __shfl_xor_sync(0xffffffffu, lg1, 2);
        lg2 += __shfl_xor_sync(0xffffffffu, lg2, 1);
        lg2 += __shfl_xor_sync(0xffffffffu, lg2, 2);
        if ((lane & 3) == 0) {
            sLog[r1 * 2 + ng] = lg1;
            sLog[r2 * 2 + ng] = lg2;
        }
    }
    __syncthreads();
    if (t < 64) {
        float s = sLog[t * 2] + sLog[t * 2 + 1] + g_hvdot[sSrc[t]] + b_logit[0];
        g_logit[sPerm[t]] = leaky01(s);
    }
}

// ---------------- launch #5: per-node softmax + weighted sum (CSR-sequential, fp16 reads) ----------------
__global__ void aggregate_kernel() {
    int v = (blockIdx.x * blockDim.x + threadIdx.x) >> 5;
    int lane = threadIdx.x & 31;
    if (v >= N_NODES) return;
    int s = g_off[v], e = g_off[v + 1];
    float mx = -1e30f;
    for (int i = s + lane; i < e; i += 32)
        mx = fmaxf(mx, g_logit[i]);
    for (int o = 16; o; o >>= 1)
        mx = fmaxf(mx, __shfl_xor_sync(0xffffffffu, mx, o));
    float4 acc = make_float4(0.f, 0.f, 0.f, 0.f);
    float den = 0.f;
    for (int i = s; i < e; i++) {
        float w = expf(g_logit[i] - mx);
        den += w;
        uint2 raw = *(const uint2*)(g_h_e16 + (size_t)i * 128 + lane * 4);
        float2 f01 = __half22float2(*(__half2*)&raw.x);
        float2 f23 = __half22float2(*(__half2*)&raw.y);
        acc.x += w * f01.x; acc.y += w * f01.y;
        acc.z += w * f23.x; acc.w += w * f23.y;
    }
    float inv = (e > s) ? 1.f / den : 0.f;
    acc.x *= inv; acc.y *= inv; acc.z *= inv; acc.w *= inv;
    *(float4*)&g_A[v * 128 + lane * 4] = acc;
}

// ---------------- generic tiled GEMM: out = act(X @ W + b), 64x128 tile ----------------
template <int K, int ACT>
__global__ __launch_bounds__(256) void gemm_kernel(
    const float* __restrict__ X, int ldx, int rows,
    const float* __restrict__ W, int ldw,
    const float* __restrict__ b,
    float* __restrict__ out, int ldo)
{
    extern __shared__ float sm[];
    float* sW = sm;
    float* sX = sW + K * 128;
    float* sB = sX + 64 * K;
    int t = threadIdx.x;
    int r0g = blockIdx.x * 64;
    for (int i = t; i < K * 128; i += 256) {
        int k = i >> 7, c = i & 127;
        sW[i] = W[(size_t)k * ldw + c];
    }
    for (int i = t; i < 64 * K; i += 256) {
        int r = i / K, k = i % K;
        int gr = r0g + r;
        sX[i] = (gr < rows) ? X[(size_t)gr * ldx + k] : 0.f;
    }
    if (t < 128) sB[t] = b[t];
    __syncthreads();
    int cx = t & 31, cy = t >> 5;
    int r0 = cy * 8, c0 = cx * 4;
    float acc[8][4] = {};
#pragma unroll 4
    for (int k = 0; k < K; k++) {
        float4 w = *(const float4*)&sW[k * 128 + c0];
#pragma unroll
        for (int r = 0; r < 8; r++) {
            float x = sX[(r0 + r) * K + k];
            acc[r][0] += x * w.x; acc[r][1] += x * w.y;
            acc[r][2] += x * w.z; acc[r][3] += x * w.w;
        }
    }
#pragma unroll
    for (int r = 0; r < 8; r++) {
        int gr = r0g + r0 + r;
        if (gr >= rows) break;
#pragma unroll
        for (int c = 0; c < 4; c++) {
            float v = acc[r][c] + sB[c0 + c];
            if (ACT == 1) v = leaky01(v);
            else if (ACT == 2) v = (v > 0.f) ? v : (expf(v) - 1.f);
            acc[r][c] = v;
        }
        *(float4*)&out[(size_t)gr * ldo + c0] = make_float4(acc[r][0], acc[r][1], acc[r][2], acc[r][3]);
    }
}

// ---------------- fused GRU GEMMs: one launch, blockIdx.y selects (mat, chunk) ----------------
__global__ __launch_bounds__(256) void gru_gemm_kernel(const float* __restrict__ b_ih,
                                                       const float* __restrict__ b_hh)
{
    extern __shared__ float sm[];
    float* sW = sm;
    float* sX = sW + 128 * 128;
    float* sB = sX + 64 * 128;
    int mat = blockIdx.y / 3, chunk = blockIdx.y % 3;
    const float* X = mat ? g_h_v : g_cv;
    const float* W = (mat ? g_WhhT : g_WihT) + chunk * 128;
    const float* b = (mat ? b_hh : b_ih) + chunk * 128;
    float* out = (mat ? g_gh : g_gi) + chunk * 128;
    int t = threadIdx.x;
    int r0g = blockIdx.x * 64;
    for (int i = t; i < 128 * 128; i += 256) {
        int k = i >> 7, c = i & 127;
        sW[i] = W[k * 384 + c];
    }
    for (int i = t; i < 64 * 128; i += 256) {
        int r = i >> 7, k = i & 127;
        int gr = r0g + r;
        sX[i] = (gr < N_NODES) ? X[gr * 128 + k] : 0.f;
    }
    if (t < 128) sB[t] = b[t];
    __syncthreads();
    int cx = t & 31, cy = t >> 5;
    int r0 = cy * 8, c0 = cx * 4;
    float acc[8][4] = {};
#pragma unroll 4
    for (int k = 0; k < 128; k++) {
        float4 w = *(const float4*)&sW[k * 128 + c0];
#pragma unroll
        for (int r = 0; r < 8; r++) {
            float x = sX[(r0 + r) * 128 + k];
            acc[r][0] += x * w.x; acc[r][1] += x * w.y;
            acc[r][2] += x * w.z; acc[r][3] += x * w.w;
        }
    }
#pragma unroll
    for (int r = 0; r < 8; r++) {
        int gr = r0g + r0 + r;
        if (gr >= N_NODES) break;
        *(float4*)&out[(size_t)gr * 384 + c0] = make_float4(
            acc[r][0] + sB[c0], acc[r][1] + sB[c0 + 1], acc[r][2] + sB[c0 + 2], acc[r][3] + sB[c0 + 3]);
    }
}

// ---------------- GRU gates + relu ----------------
__global__ void gate_kernel(float* __restrict__ out) {
    int idx = blockIdx.x * blockDim.x + threadIdx.x;
    if (idx >= N_NODES * NHID) return;
    int n = idx >> 7, j = idx & 127;
    const float* gi = &g_gi[n * 384];
    const float* gh = &g_gh[n * 384];
    float r = 1.f / (1.f + expf(-(gi[j] + gh[j])));
    float z = 1.f / (1.f + expf(-(gi[128 + j] + gh[128 + j])));
    float nn = tanhf(gi[256 + j] + r * gh[256 + j]);
    float hv = g_h_v[idx];
    float h = (1.f - z) * nn + z * hv;
    out[idx] = h > 0.f ? h : 0.f;
}

// ---------------- launch ----------------
extern "C" void kernel_launch(void* const* d_in, const int* in_sizes, int n_in,
                              void* d_out, int out_size) {
    const float* node_feats = (const float*)d_in[0];
    const float* edge_feats = (const float*)d_in[1];
    const float* W_node  = (const float*)d_in[2];
    const float* b_node  = (const float*)d_in[3];
    const float* W_edge  = (const float*)d_in[4];
    const float* b_edge  = (const float*)d_in[5];
    const float* W_logit = (const float*)d_in[6];
    const float* b_logit = (const float*)d_in[7];
    const float* W_msg   = (const float*)d_in[8];
    const float* b_msg   = (const float*)d_in[9];
    const float* W_ih    = (const float*)d_in[10];
    const float* W_hh    = (const float*)d_in[11];
    const float* b_ih    = (const float*)d_in[12];
    const float* b_hh    = (const float*)d_in[13];
    const int*   src     = (const int*)d_in[14];
    const int*   dst     = (const int*)d_in[15];
    float* out = (float*)d_out;

    float *p_A, *p_cv;
    int* p_cnt;
    cudaGetSymbolAddress((void**)&p_A, g_A);
    cudaGetSymbolAddress((void**)&p_cv, g_cv);
    cudaGetSymbolAddress((void**)&p_cnt, g_cnt);

    const int SM_G128 = (128 * 128 + 64 * 128 + 128) * 4;
    const int SM_NODE = (64 * 128 + 64 * 64 + 256) * 4;
    cudaFuncSetAttribute(edge_mma_kernel, cudaFuncAttributeMaxDynamicSharedMemorySize, SM_EDGE_TOTAL);
    cudaFuncSetAttribute(node_embed_kernel, cudaFuncAttributeMaxDynamicSharedMemorySize, SM_NODE);
    cudaFuncSetAttribute(gemm_kernel<128, 2>, cudaFuncAttributeMaxDynamicSharedMemorySize, SM_G128);
    cudaFuncSetAttribute(gru_gemm_kernel, cudaFuncAttributeMaxDynamicSharedMemorySize, SM_G128);

    cudaMemsetAsync(p_cnt, 0, N_NODES * sizeof(int));

    // #1 histogram + all weight prep
    hist_prep_kernel<<<(N_EDGES + 255) / 256, 256>>>(dst, W_edge, W_ih, W_hh);
    // #2 scan
    scan_kernel<<<1, 1024>>>();
    // #3 node embed + fused hvdot
    int ntiles = (N_NODES + 63) / 64;
    node_embed_kernel<<<ntiles, 256, SM_NODE>>>(node_feats, W_node, b_node, W_logit);
    // #4 edge GEMM on tensor cores (profiled slot)
    float* outEF = (out_size >= N_NODES * NHID + N_EDGES * 64) ? (out + N_NODES * NHID) : nullptr;
    edge_mma_kernel<<<N_EDGES / 64, 128, SM_EDGE_TOTAL>>>(node_feats, edge_feats, src, dst,
                                                          b_edge, W_logit, b_logit, outEF);
    // #5 softmax-weighted segment sum
    aggregate_kernel<<<(N_NODES + 7) / 8, 256>>>();
    // #6 C_v = elu(A @ W_msg + b_msg)
    gemm_kernel<128, 2><<<ntiles, 256, SM_G128>>>(p_A, 128, N_NODES,
                                                  W_msg, 128, b_msg, p_cv, 128);
    // #7 gi / gh in one launch
    gru_gemm_kernel<<<dim3(ntiles, 6), 256, SM_G128>>>(b_ih, b_hh);
    // #8 gates -> h_new
    gate_kernel<<<(N_NODES * NHID + 255) / 256, 256>>>(out);
}

// round 9
// speedup vs baseline: 3.2295x; 1.3049x over previous
#include <cuda_runtime.h>
#include <cuda_bf16.h>
#include <cuda_fp16.h>
#include <math.h>
#include <stdint.h>

#define N_NODES 10000
#define N_EDGES 640000
#define NHID    128
#define EHID    128
#define CSIZE   128

// ---------------- scratch (device globals; no allocation) ----------------
__device__ float g_h_v[N_NODES * NHID];
__device__ __half g_h_v16[N_NODES * NHID];
__device__ float g_hvdot[N_NODES];
__device__ __half g_h_e16[(size_t)N_EDGES * EHID];  // CSR-ordered rows, fp16 (164MB)
__device__ float g_logit[N_EDGES];                  // CSR-ordered
__device__ __half g_A16[N_NODES * EHID];
__device__ __half g_cv16[N_NODES * CSIZE];
__device__ float g_gi[N_NODES * 3 * NHID];
__device__ float g_gh[N_NODES * 3 * NHID];
__device__ int   g_cnt[N_NODES];
__device__ int   g_off[N_NODES + 1];
__device__ int   g_cur[N_NODES];
// fragment images: [ng(2)][k8(8)][q(4)][lane(32)] uint4 each (2048 entries / 128x128 matrix)
__device__ uint4 g_BfragE[2048];        // W_edge^T
__device__ uint4 g_WihFrag[3 * 2048];   // W_ih rows (B[n][k] = Wih[n][k])
__device__ uint4 g_WhhFrag[3 * 2048];
__device__ uint4 g_WmsgFrag[2048];      // W_msg^T

#define A_STRIDE 136   // halves; 272 bytes

__device__ __forceinline__ float leaky01(float v) { return v > 0.f ? v : 0.01f * v; }

__device__ __forceinline__ uint32_t smem_u32(const void* p) {
    uint32_t a;
    asm("{ .reg .u64 t; cvta.to.shared.u64 t, %1; cvt.u32.u64 %0, t; }" : "=r"(a) : "l"(p));
    return a;
}
__device__ __forceinline__ void ldsm_x4(uint32_t* r, uint32_t addr) {
    asm volatile("ldmatrix.sync.aligned.m8n8.x4.shared.b16 {%0,%1,%2,%3}, [%4];"
        : "=r"(r[0]), "=r"(r[1]), "=r"(r[2]), "=r"(r[3]) : "r"(addr));
}
__device__ __forceinline__ void mma_f16(float* c, const uint32_t* a, const uint32_t* b) {
    asm volatile("mma.sync.aligned.m16n8k16.row.col.f32.f16.f16.f32 "
        "{%0,%1,%2,%3}, {%4,%5,%6,%7}, {%8,%9}, {%0,%1,%2,%3};"
        : "+f"(c[0]), "+f"(c[1]), "+f"(c[2]), "+f"(c[3])
        : "r"(a[0]), "r"(a[1]), "r"(a[2]), "r"(a[3]), "r"(b[0]), "r"(b[1]));
}

// fragment builders for mma m16n8k16 .col B fragments
__device__ __forceinline__ uint4 frag_colmajor(const float* M, int f) {  // B[n][k] = M[k*128+n]
    int lane = f & 31, q = (f >> 5) & 3, k8 = (f >> 7) & 7, ng = f >> 10;
    int n1 = ng * 64 + q * 16 + (lane >> 2), n2 = n1 + 8;
    int k0 = k8 * 16 + 2 * (lane & 3);
    uint4 v; __half2 h;
    h = __floats2half2_rn(M[k0 * 128 + n1], M[(k0 + 1) * 128 + n1]); v.x = *(uint32_t*)&h;
    h = __floats2half2_rn(M[(k0 + 8) * 128 + n1], M[(k0 + 9) * 128 + n1]); v.y = *(uint32_t*)&h;
    h = __floats2half2_rn(M[k0 * 128 + n2], M[(k0 + 1) * 128 + n2]); v.z = *(uint32_t*)&h;
    h = __floats2half2_rn(M[(k0 + 8) * 128 + n2], M[(k0 + 9) * 128 + n2]); v.w = *(uint32_t*)&h;
    return v;
}
__device__ __forceinline__ uint4 frag_rowmajor(const float* M, int f, int nbase) { // B[n][k] = M[(nbase+n)*128+k]
    int lane = f & 31, q = (f >> 5) & 3, k8 = (f >> 7) & 7, ng = f >> 10;
    int n1 = nbase + ng * 64 + q * 16 + (lane >> 2), n2 = n1 + 8;
    int k0 = k8 * 16 + 2 * (lane & 3);
    uint4 v; __half2 h;
    h = __floats2half2_rn(M[n1 * 128 + k0], M[n1 * 128 + k0 + 1]); v.x = *(uint32_t*)&h;
    h = __floats2half2_rn(M[n1 * 128 + k0 + 8], M[n1 * 128 + k0 + 9]); v.y = *(uint32_t*)&h;
    h = __floats2half2_rn(M[n2 * 128 + k0], M[n2 * 128 + k0 + 1]); v.z = *(uint32_t*)&h;
    h = __floats2half2_rn(M[n2 * 128 + k0 + 8], M[n2 * 128 + k0 + 9]); v.w = *(uint32_t*)&h;
    return v;
}

// ---------------- launch #1: histogram + all fragment-image prep ----------------
__global__ void hist_prep_kernel(const int* __restrict__ dst,
                                 const float* __restrict__ We,
                                 const float* __restrict__ Wih,
                                 const float* __restrict__ Whh,
                                 const float* __restrict__ Wmsg)
{
    int e = blockIdx.x * blockDim.x + threadIdx.x;
    if (e < N_EDGES) atomicAdd(&g_cnt[dst[e]], 1);
    if (e < 2048) {
        g_BfragE[e] = frag_colmajor(We, e);
    } else if (e < 2048 + 3 * 2048) {
        int idx = e - 2048;
        g_WihFrag[idx] = frag_rowmajor(Wih, idx & 2047, (idx >> 11) * 128);
    } else if (e < 2048 + 6 * 2048) {
        int idx = e - 2048 - 3 * 2048;
        g_WhhFrag[idx] = frag_rowmajor(Whh, idx & 2047, (idx >> 11) * 128);
    } else if (e < 2048 + 7 * 2048) {
        int idx = e - 2048 - 6 * 2048;
        g_WmsgFrag[idx] = frag_colmajor(Wmsg, idx);
    }
}

// ---------------- launch #2: exclusive scan of counts -> off/cur ----------------
__global__ void scan_kernel() {
    __shared__ int s[1024];
    __shared__ int s_carry;
    if (threadIdx.x == 0) s_carry = 0;
    __syncthreads();
    for (int base = 0; base < N_NODES; base += 1024) {
        int i = base + threadIdx.x;
        int v = (i < N_NODES) ? g_cnt[i] : 0;
        s[threadIdx.x] = v;
        __syncthreads();
        for (int d = 1; d < 1024; d <<= 1) {
            int t = 0;
            if ((int)threadIdx.x >= d) t = s[threadIdx.x - d];
            __syncthreads();
            s[threadIdx.x] += t;
            __syncthreads();
        }
        int incl = s[threadIdx.x] + s_carry;
        if (i < N_NODES) { g_off[i] = incl - v; g_cur[i] = incl - v; }
        __syncthreads();
        if (threadIdx.x == 1023) s_carry = incl;
        __syncthreads();
    }
    if (threadIdx.x == 0) g_off[N_NODES] = s_carry;
}

// ---------------- launch #3: node embed GEMM (K=64, leaky) + fused hvdot + fp16 copy ----------------
__global__ __launch_bounds__(256) void node_embed_kernel(
    const float* __restrict__ nf, const float* __restrict__ Wn,
    const float* __restrict__ bn, const float* __restrict__ Wl)
{
    extern __shared__ float sm[];
    float* sW = sm;            // 64*128
    float* sX = sm + 8192;     // 64*64
    float* sB = sm + 12288;    // 128
    float* sWL = sm + 12416;   // 128
    int t = threadIdx.x;
    int r0g = blockIdx.x * 64;
    for (int i = t; i < 64 * 128; i += 256) {
        int k = i >> 7, c = i & 127;
        sW[i] = Wn[k * 128 + c];
    }
    for (int i = t; i < 64 * 64; i += 256) {
        int r = i >> 6, k = i & 63;
        int gr = r0g + r;
        sX[i] = (gr < N_NODES) ? nf[gr * 64 + k] : 0.f;
    }
    if (t < 128) { sB[t] = bn[t]; sWL[t] = Wl[t]; }
    __syncthreads();
    int cx = t & 31, cy = t >> 5;
    int r0 = cy * 8, c0 = cx * 4;
    float acc[8][4] = {};
#pragma unroll 4
    for (int k = 0; k < 64; k++) {
        float4 w = *(const float4*)&sW[k * 128 + c0];
#pragma unroll
        for (int r = 0; r < 8; r++) {
            float x = sX[(r0 + r) * 64 + k];
            acc[r][0] += x * w.x; acc[r][1] += x * w.y;
            acc[r][2] += x * w.z; acc[r][3] += x * w.w;
        }
    }
    float wl0 = sWL[c0], wl1 = sWL[c0 + 1], wl2 = sWL[c0 + 2], wl3 = sWL[c0 + 3];
#pragma unroll
    for (int r = 0; r < 8; r++) {
        int gr = r0g + r0 + r;
        if (gr >= N_NODES) break;
        float v0 = leaky01(acc[r][0] + sB[c0]);
        float v1 = leaky01(acc[r][1] + sB[c0 + 1]);
        float v2 = leaky01(acc[r][2] + sB[c0 + 2]);
        float v3 = leaky01(acc[r][3] + sB[c0 + 3]);
        *(float4*)&g_h_v[(size_t)gr * 128 + c0] = make_float4(v0, v1, v2, v3);
        __half2 p01 = __floats2half2_rn(v0, v1);
        __half2 p23 = __floats2half2_rn(v2, v3);
        *(uint2*)&g_h_v16[(size_t)gr * 128 + c0] = make_uint2(*(uint32_t*)&p01, *(uint32_t*)&p23);
        float p = v0 * wl0 + v1 * wl1 + v2 * wl2 + v3 * wl3;
        for (int o = 16; o; o >>= 1) p += __shfl_xor_sync(0xffffffffu, p, o);
        if (cx == 0) g_hvdot[gr] = p;
    }
}

// ============ launch #4: edge GEMM on HMMA, 64 edges/CTA, B via fragment LDG, 4 CTAs/SM ============
#define SM_SRC   0
#define SM_PERM  256
#define SM_BIAS  512
#define SM_WL    1024
#define SM_LOG   1536
#define SM_A     2048
#define SM_EDGE_TOTAL (SM_A + 64 * 272)   // 19456 bytes -> 4 CTAs/SM

__global__ __launch_bounds__(128, 4)
void edge_mma_kernel(const float* __restrict__ nf, const float* __restrict__ ef,
                     const int* __restrict__ src, const int* __restrict__ dst,
                     const float* __restrict__ b_edge,
                     const float* __restrict__ W_logit, const float* __restrict__ b_logit,
                     float* __restrict__ outEF)
{
    extern __shared__ __align__(16) char smem[];
    uint32_t sb = smem_u32(smem);
    int t = threadIdx.x, lane = t & 31, wid = t >> 5;
    int e0 = blockIdx.x * 64;
    int* sSrc = (int*)(smem + SM_SRC);
    int* sPerm = (int*)(smem + SM_PERM);
    float* sBias = (float*)(smem + SM_BIAS);
    float* sWL = (float*)(smem + SM_WL);
    float* sLog = (float*)(smem + SM_LOG);

    if (t < 64) {
        sSrc[t] = src[e0 + t];
        sPerm[t] = atomicAdd(&g_cur[dst[e0 + t]], 1);
    }
    sBias[t] = b_edge[t];
    sWL[t] = W_logit[128 + t];

    // ef passthrough: linear coalesced copy (16 KB)
    if (outEF) {
        const float4* efs = (const float4*)(ef + (size_t)e0 * 64);
        float4* efd = (float4*)(outEF + (size_t)e0 * 64);
#pragma unroll
        for (int i = t; i < 1024; i += 128) efd[i] = efs[i];
    }
    __syncthreads();

    // A gather: row r from [nf[src[r]] | ef[e0+r]], fp16, packed STS.128.
    {
        int r = t >> 1, hf = t & 1;
        const float4* xp = hf ? (const float4*)(ef + (size_t)(e0 + r) * 64)
                              : (const float4*)(nf + (size_t)sSrc[r] * 64);
        char* hi = smem + SM_A + r * 272 + hf * 128;
#pragma unroll
        for (int j2 = 0; j2 < 8; j2++) {
            float4 v0 = xp[2 * j2];
            float4 v1 = xp[2 * j2 + 1];
            __half2 a0 = __floats2half2_rn(v0.x, v0.y);
            __half2 a1 = __floats2half2_rn(v0.z, v0.w);
            __half2 a2 = __floats2half2_rn(v1.x, v1.y);
            __half2 a3 = __floats2half2_rn(v1.z, v1.w);
            *(uint4*)(hi + j2 * 16) = make_uint4(*(uint32_t*)&a0, *(uint32_t*)&a1,
                                                 *(uint32_t*)&a2, *(uint32_t*)&a3);
        }
    }
    __syncthreads();

    // warp tile: 4 warps, M=32 (mg in 0..1), N=64 (ng in 0..1)
    int mg = wid & 1, ng = wid >> 1;
    int m0 = mg * 32, n0 = ng * 64;
    float acc[2][8][4];
#pragma unroll
    for (int i = 0; i < 2; i++)
#pragma unroll
        for (int j = 0; j < 8; j++)
#pragma unroll
            for (int c = 0; c < 4; c++) acc[i][j][c] = 0.f;

    uint32_t aOffL = ((lane & 15) * A_STRIDE + (lane >> 4) * 8) * 2;
    uint32_t Ab = sb + SM_A;
    const uint4* bf = g_BfragE + ng * 1024 + lane;

#pragma unroll
    for (int k8 = 0; k8 < 8; k8++) {
        uint32_t kb = k8 * 32;
        uint4 bq[4];
#pragma unroll
        for (int q = 0; q < 4; q++)
            bq[q] = bf[k8 * 128 + q * 32];
        uint32_t a[2][4];
        ldsm_x4(a[0], Ab + aOffL + (uint32_t)m0 * 272 + kb);
        ldsm_x4(a[1], Ab + aOffL + (uint32_t)(m0 + 16) * 272 + kb);
#pragma unroll
        for (int ms = 0; ms < 2; ms++)
#pragma unroll
            for (int q = 0; q < 4; q++) {
                const uint32_t* bb = (const uint32_t*)&bq[q];
                mma_f16(acc[ms][q * 2],     a[ms], bb);
                mma_f16(acc[ms][q * 2 + 1], a[ms], bb + 2);
            }
    }

    // epilogue: bias + leaky + store h_e fp16 (CSR slot) + partial logit
#pragma unroll
    for (int ms = 0; ms < 2; ms++) {
        int r1 = m0 + ms * 16 + (lane >> 2);
        int r2 = r1 + 8;
        float lg1 = 0.f, lg2 = 0.f;
        __half* o1 = g_h_e16 + (size_t)sPerm[r1] * 128;
        __half* o2 = g_h_e16 + (size_t)sPerm[r2] * 128;
#pragma unroll
        for (int ns = 0; ns < 8; ns++) {
            int col = n0 + ns * 8 + (lane & 3) * 2;
            float v0 = leaky01(acc[ms][ns][0] + sBias[col]);
            float v1 = leaky01(acc[ms][ns][1] + sBias[col + 1]);
            float v2 = leaky01(acc[ms][ns][2] + sBias[col]);
            float v3 = leaky01(acc[ms][ns][3] + sBias[col + 1]);
            lg1 += v0 * sWL[col] + v1 * sWL[col + 1];
            lg2 += v2 * sWL[col] + v3 * sWL[col + 1];
            *(__half2*)(o1 + col) = __floats2half2_rn(v0, v1);
            *(__half2*)(o2 + col) = __floats2half2_rn(v2, v3);
        }
        lg1 += __shfl_xor_sync(0xffffffffu, lg1, 1);
        lg1 += __shfl_xor_sync(0xffffffffu, lg1, 2);
        lg2 += __shfl_xor_sync(0xffffffffu, lg2, 1);
        lg2 += __shfl_xor_sync(0xffffffffu, lg2, 2);
        if ((lane & 3) == 0) {
            sLog[r1 * 2 + ng] = lg1;
            sLog[r2 * 2 + ng] = lg2;
        }
    }
    __syncthreads();
    if (t < 64) {
        float s = sLog[t * 2] + sLog[t * 2 + 1] + g_hvdot[sSrc[t]] + b_logit[0];
        g_logit[sPerm[t]] = leaky01(s);
    }
}

// ---------------- launch #5: per-node softmax + weighted sum -> A (fp16) ----------------
__global__ void aggregate_kernel() {
    int v = (blockIdx.x * blockDim.x + threadIdx.x) >> 5;
    int lane = threadIdx.x & 31;
    if (v >= N_NODES) return;
    int s = g_off[v], e = g_off[v + 1];
    float mx = -1e30f;
    for (int i = s + lane; i < e; i += 32)
        mx = fmaxf(mx, g_logit[i]);
    for (int o = 16; o; o >>= 1)
        mx = fmaxf(mx, __shfl_xor_sync(0xffffffffu, mx, o));
    float4 acc = make_float4(0.f, 0.f, 0.f, 0.f);
    float den = 0.f;
    for (int i = s; i < e; i++) {
        float w = expf(g_logit[i] - mx);
        den += w;
        uint2 raw = *(const uint2*)(g_h_e16 + (size_t)i * 128 + lane * 4);
        float2 f01 = __half22float2(*(__half2*)&raw.x);
        float2 f23 = __half22float2(*(__half2*)&raw.y);
        acc.x += w * f01.x; acc.y += w * f01.y;
        acc.z += w * f23.x; acc.w += w * f23.y;
    }
    float inv = (e > s) ? 1.f / den : 0.f;
    __half2 p01 = __floats2half2_rn(acc.x * inv, acc.y * inv);
    __half2 p23 = __floats2half2_rn(acc.z * inv, acc.w * inv);
    *(uint2*)&g_A16[v * 128 + lane * 4] = make_uint2(*(uint32_t*)&p01, *(uint32_t*)&p23);
}

// ============ HMMA GEMM body: 64 rows x 128 cols, K=128, fp16 in ============
// MODE 0: float out (ldo stride), no act.  MODE 1: half out (stride 128), elu.
#define SM16_BIAS 0
#define SM16_X    512
#define SM16_TOTAL (SM16_X + 64 * 272)   // 17920 bytes

template <int MODE>
__device__ __forceinline__ void gemm16_body(
    const __half* __restrict__ X, const uint4* __restrict__ bfrag,
    const float* __restrict__ bias, float* __restrict__ outF,
    __half* __restrict__ outH, int ldo, int e0)
{
    extern __shared__ __align__(16) char smem[];
    uint32_t sb = smem_u32(smem);
    int t = threadIdx.x, lane = t & 31, wid = t >> 5;
    float* sBias = (float*)(smem + SM16_BIAS);
    sBias[t] = bias[t];

    // load X tile (64 rows x 128 halves), stride 272B
    {
        int row = t >> 1, half = t & 1;
        int gr = e0 + row;
        uint4* xd = (uint4*)(smem + SM16_X + row * 272 + half * 128);
        if (gr < N_NODES) {
            const uint4* xp = (const uint4*)(X + (size_t)gr * 128 + half * 64);
#pragma unroll
            for (int j = 0; j < 8; j++) xd[j] = xp[j];
        } else {
#pragma unroll
            for (int j = 0; j < 8; j++) xd[j] = make_uint4(0, 0, 0, 0);
        }
    }
    __syncthreads();

    int mg = wid & 1, ng = wid >> 1;
    int m0 = mg * 32, n0 = ng * 64;
    float acc[2][8][4];
#pragma unroll
    for (int i = 0; i < 2; i++)
#pragma unroll
        for (int j = 0; j < 8; j++)
#pragma unroll
            for (int c = 0; c < 4; c++) acc[i][j][c] = 0.f;

    uint32_t aOffL = ((lane & 15) * A_STRIDE + (lane >> 4) * 8) * 2;
    uint32_t Ab = sb + SM16_X;
    const uint4* bf = bfrag + ng * 1024 + lane;

#pragma unroll
    for (int k8 = 0; k8 < 8; k8++) {
        uint32_t kb = k8 * 32;
        uint4 bq[4];
#pragma unroll
        for (int q = 0; q < 4; q++)
            bq[q] = bf[k8 * 128 + q * 32];
        uint32_t a[2][4];
        ldsm_x4(a[0], Ab + aOffL + (uint32_t)m0 * 272 + kb);
        ldsm_x4(a[1], Ab + aOffL + (uint32_t)(m0 + 16) * 272 + kb);
#pragma unroll
        for (int ms = 0; ms < 2; ms++)
#pragma unroll
            for (int q = 0; q < 4; q++) {
                const uint32_t* bb = (const uint32_t*)&bq[q];
                mma_f16(acc[ms][q * 2],     a[ms], bb);
                mma_f16(acc[ms][q * 2 + 1], a[ms], bb + 2);
            }
    }

#pragma unroll
    for (int ms = 0; ms < 2; ms++) {
        int r1 = m0 + ms * 16 + (lane >> 2);
        int r2 = r1 + 8;
#pragma unroll
        for (int rr = 0; rr < 2; rr++) {
            int row = rr ? r2 : r1;
            int gr = e0 + row;
            if (gr >= N_NODES) continue;
#pragma unroll
            for (int ns = 0; ns < 8; ns++) {
                int col = n0 + ns * 8 + (lane & 3) * 2;
                float v0 = acc[ms][ns][rr * 2]     + sBias[col];
                float v1 = acc[ms][ns][rr * 2 + 1] + sBias[col + 1];
                if (MODE == 1) {
                    v0 = (v0 > 0.f) ? v0 : (expf(v0) - 1.f);
                    v1 = (v1 > 0.f) ? v1 : (expf(v1) - 1.f);
                    *(__half2*)(outH + (size_t)gr * 128 + col) = __floats2half2_rn(v0, v1);
                } else {
                    *(float2*)(outF + (size_t)gr * ldo + col) = make_float2(v0, v1);
                }
            }
        }
    }
}

// launch #6: C_v = elu(A @ W_msg + b_msg) in fp16
__global__ __launch_bounds__(128, 4) void cv16_kernel(const float* __restrict__ b_msg) {
    gemm16_body<1>(g_A16, g_WmsgFrag, b_msg, nullptr, g_cv16, 128, blockIdx.x * 64);
}

// launch #7: gi = cv @ Wih^T + b_ih ; gh = h_v @ Whh^T + b_hh (fp32 out)
__global__ __launch_bounds__(128, 4) void gru16_kernel(const float* __restrict__ b_ih,
                                                       const float* __restrict__ b_hh) {
    int mat = blockIdx.y / 3, chunk = blockIdx.y % 3;
    const __half* X = mat ? g_h_v16 : g_cv16;
    const uint4* bf = (mat ? g_WhhFrag : g_WihFrag) + chunk * 2048;
    const float* bias = (mat ? b_hh : b_ih) + chunk * 128;
    float* outp = (mat ? g_gh : g_gi) + chunk * 128;
    gemm16_body<0>(X, bf, bias, outp, nullptr, 384, blockIdx.x * 64);
}

// ---------------- launch #8: GRU gates + relu ----------------
__global__ void gate_kernel(float* __restrict__ out) {
    int idx = blockIdx.x * blockDim.x + threadIdx.x;
    if (idx >= N_NODES * NHID) return;
    int n = idx >> 7, j = idx & 127;
    const float* gi = &g_gi[n * 384];
    const float* gh = &g_gh[n * 384];
    float r = 1.f / (1.f + expf(-(gi[j] + gh[j])));
    float z = 1.f / (1.f + expf(-(gi[128 + j] + gh[128 + j])));
    float nn = tanhf(gi[256 + j] + r * gh[256 + j]);
    float hv = g_h_v[idx];
    float h = (1.f - z) * nn + z * hv;
    out[idx] = h > 0.f ? h : 0.f;
}

// ---------------- launch ----------------
extern "C" void kernel_launch(void* const* d_in, const int* in_sizes, int n_in,
                              void* d_out, int out_size) {
    const float* node_feats = (const float*)d_in[0];
    const float* edge_feats = (const float*)d_in[1];
    const float* W_node  = (const float*)d_in[2];
    const float* b_node  = (const float*)d_in[3];
    const float* W_edge  = (const float*)d_in[4];
    const float* b_edge  = (const float*)d_in[5];
    const float* W_logit = (const float*)d_in[6];
    const float* b_logit = (const float*)d_in[7];
    const float* W_msg   = (const float*)d_in[8];
    const float* b_msg   = (const float*)d_in[9];
    const float* W_ih    = (const float*)d_in[10];
    const float* W_hh    = (const float*)d_in[11];
    const float* b_ih    = (const float*)d_in[12];
    const float* b_hh    = (const float*)d_in[13];
    const int*   src     = (const int*)d_in[14];
    const int*   dst     = (const int*)d_in[15];
    float* out = (float*)d_out;

    int* p_cnt;
    cudaGetSymbolAddress((void**)&p_cnt, g_cnt);

    const int SM_NODE = (64 * 128 + 64 * 64 + 256) * 4;
    cudaFuncSetAttribute(edge_mma_kernel, cudaFuncAttributeMaxDynamicSharedMemorySize, SM_EDGE_TOTAL);
    cudaFuncSetAttribute(node_embed_kernel, cudaFuncAttributeMaxDynamicSharedMemorySize, SM_NODE);
    cudaFuncSetAttribute(cv16_kernel, cudaFuncAttributeMaxDynamicSharedMemorySize, SM16_TOTAL);
    cudaFuncSetAttribute(gru16_kernel, cudaFuncAttributeMaxDynamicSharedMemorySize, SM16_TOTAL);

    cudaMemsetAsync(p_cnt, 0, N_NODES * sizeof(int));

    // #1 histogram + all fragment prep
    hist_prep_kernel<<<(N_EDGES + 255) / 256, 256>>>(dst, W_edge, W_ih, W_hh, W_msg);
    // #2 scan
    scan_kernel<<<1, 1024>>>();
    // #3 node embed + fused hvdot + fp16 copy
    int ntiles64 = (N_NODES + 63) / 64;
    node_embed_kernel<<<ntiles64, 256, SM_NODE>>>(node_feats, W_node, b_node, W_logit);
    // #4 edge GEMM on tensor cores (profiled slot)
    float* outEF = (out_size >= N_NODES * NHID + N_EDGES * 64) ? (out + N_NODES * NHID) : nullptr;
    edge_mma_kernel<<<N_EDGES / 64, 128, SM_EDGE_TOTAL>>>(node_feats, edge_feats, src, dst,
                                                          b_edge, W_logit, b_logit, outEF);
    // #5 softmax-weighted segment sum -> A16
    aggregate_kernel<<<(N_NODES + 7) / 8, 256>>>();
    // #6 C_v (HMMA, fp16 out)
    cv16_kernel<<<ntiles64, 128, SM16_TOTAL>>>(b_msg);
    // #7 gi / gh (HMMA, fp32 out)
    gru16_kernel<<<dim3(ntiles64, 6), 128, SM16_TOTAL>>>(b_ih, b_hh);
    // #8 gates -> h_new
    gate_kernel<<<(N_NODES * NHID + 255) / 256, 256>>>(out);
}

// round 10
// speedup vs baseline: 3.8547x; 1.1936x over previous
#include <cuda_runtime.h>
#include <cuda_bf16.h>
#include <cuda_fp16.h>
#include <math.h>
#include <stdint.h>

#define N_NODES 10000
#define N_EDGES 640000
#define NHID    128
#define EHID    128
#define CSIZE   128

// ---------------- scratch (device globals; no allocation) ----------------
__device__ float g_h_v[N_NODES * NHID];
__device__ __half g_h_v16[N_NODES * NHID];
__device__ __half g_nf16[N_NODES * 64];
__device__ float g_hvdot[N_NODES];
__device__ __half g_h_e16[(size_t)N_EDGES * EHID];  // CSR-ordered rows, fp16 (164MB)
__device__ float g_logit[N_EDGES];                  // CSR-ordered
__device__ __half g_A16[N_NODES * EHID];
__device__ __half g_cv16[N_NODES * CSIZE];
__device__ float g_gi[N_NODES * 3 * NHID];
__device__ float g_gh[N_NODES * 3 * NHID];
__device__ int   g_cnt[N_NODES];
__device__ int   g_off[N_NODES + 1];
__device__ int   g_cur[N_NODES];
// fragment images: [ng(2)][k8(8)][q(4)][lane(32)] uint4 each (2048 entries / 128x128 matrix)
__device__ uint4 g_BfragE[2048];        // W_edge^T
__device__ uint4 g_WihFrag[3 * 2048];   // W_ih rows (B[n][k] = Wih[n][k])
__device__ uint4 g_WhhFrag[3 * 2048];
__device__ uint4 g_WmsgFrag[2048];      // W_msg^T

#define A_STRIDE 136   // halves; 272 bytes

__device__ __forceinline__ float leaky01(float v) { return v > 0.f ? v : 0.01f * v; }

__device__ __forceinline__ uint32_t smem_u32(const void* p) {
    uint32_t a;
    asm("{ .reg .u64 t; cvta.to.shared.u64 t, %1; cvt.u32.u64 %0, t; }" : "=r"(a) : "l"(p));
    return a;
}
__device__ __forceinline__ void ldsm_x4(uint32_t* r, uint32_t addr) {
    asm volatile("ldmatrix.sync.aligned.m8n8.x4.shared.b16 {%0,%1,%2,%3}, [%4];"
        : "=r"(r[0]), "=r"(r[1]), "=r"(r[2]), "=r"(r[3]) : "r"(addr));
}
__device__ __forceinline__ void mma_f16(float* c, const uint32_t* a, const uint32_t* b) {
    asm volatile("mma.sync.aligned.m16n8k16.row.col.f32.f16.f16.f32 "
        "{%0,%1,%2,%3}, {%4,%5,%6,%7}, {%8,%9}, {%0,%1,%2,%3};"
        : "+f"(c[0]), "+f"(c[1]), "+f"(c[2]), "+f"(c[3])
        : "r"(a[0]), "r"(a[1]), "r"(a[2]), "r"(a[3]), "r"(b[0]), "r"(b[1]));
}

// fragment builders for mma m16n8k16 .col B fragments
__device__ __forceinline__ uint4 frag_colmajor(const float* M, int f) {  // B[n][k] = M[k*128+n]
    int lane = f & 31, q = (f >> 5) & 3, k8 = (f >> 7) & 7, ng = f >> 10;
    int n1 = ng * 64 + q * 16 + (lane >> 2), n2 = n1 + 8;
    int k0 = k8 * 16 + 2 * (lane & 3);
    uint4 v; __half2 h;
    h = __floats2half2_rn(M[k0 * 128 + n1], M[(k0 + 1) * 128 + n1]); v.x = *(uint32_t*)&h;
    h = __floats2half2_rn(M[(k0 + 8) * 128 + n1], M[(k0 + 9) * 128 + n1]); v.y = *(uint32_t*)&h;
    h = __floats2half2_rn(M[k0 * 128 + n2], M[(k0 + 1) * 128 + n2]); v.z = *(uint32_t*)&h;
    h = __floats2half2_rn(M[(k0 + 8) * 128 + n2], M[(k0 + 9) * 128 + n2]); v.w = *(uint32_t*)&h;
    return v;
}
__device__ __forceinline__ uint4 frag_rowmajor(const float* M, int f, int nbase) { // B[n][k] = M[(nbase+n)*128+k]
    int lane = f & 31, q = (f >> 5) & 3, k8 = (f >> 7) & 7, ng = f >> 10;
    int n1 = nbase + ng * 64 + q * 16 + (lane >> 2), n2 = n1 + 8;
    int k0 = k8 * 16 + 2 * (lane & 3);
    uint4 v; __half2 h;
    h = __floats2half2_rn(M[n1 * 128 + k0], M[n1 * 128 + k0 + 1]); v.x = *(uint32_t*)&h;
    h = __floats2half2_rn(M[n1 * 128 + k0 + 8], M[n1 * 128 + k0 + 9]); v.y = *(uint32_t*)&h;
    h = __floats2half2_rn(M[n2 * 128 + k0], M[n2 * 128 + k0 + 1]); v.z = *(uint32_t*)&h;
    h = __floats2half2_rn(M[n2 * 128 + k0 + 8], M[n2 * 128 + k0 + 9]); v.w = *(uint32_t*)&h;
    return v;
}

// ---------------- launch #1: histogram + nf16 + all fragment-image prep ----------------
__global__ void hist_prep_kernel(const int* __restrict__ dst,
                                 const float* __restrict__ nf,
                                 const float* __restrict__ We,
                                 const float* __restrict__ Wih,
                                 const float* __restrict__ Whh,
                                 const float* __restrict__ Wmsg)
{
    int e = blockIdx.x * blockDim.x + threadIdx.x;
    if (e < N_EDGES) atomicAdd(&g_cnt[dst[e]], 1);
    if (e < N_NODES * 32) {
        float2 f = *(const float2*)&nf[e * 2];
        *(__half2*)&g_nf16[e * 2] = __floats2half2_rn(f.x, f.y);
    }
    if (e < 2048) {
        g_BfragE[e] = frag_colmajor(We, e);
    } else if (e < 2048 + 3 * 2048) {
        int idx = e - 2048;
        g_WihFrag[idx] = frag_rowmajor(Wih, idx & 2047, (idx >> 11) * 128);
    } else if (e < 2048 + 6 * 2048) {
        int idx = e - 2048 - 3 * 2048;
        g_WhhFrag[idx] = frag_rowmajor(Whh, idx & 2047, (idx >> 11) * 128);
    } else if (e < 2048 + 7 * 2048) {
        int idx = e - 2048 - 6 * 2048;
        g_WmsgFrag[idx] = frag_colmajor(Wmsg, idx);
    }
}

// ---------------- launch #2: exclusive scan of counts -> off/cur ----------------
__global__ void scan_kernel() {
    __shared__ int s[1024];
    __shared__ int s_carry;
    if (threadIdx.x == 0) s_carry = 0;
    __syncthreads();
    for (int base = 0; base < N_NODES; base += 1024) {
        int i = base + threadIdx.x;
        int v = (i < N_NODES) ? g_cnt[i] : 0;
        s[threadIdx.x] = v;
        __syncthreads();
        for (int d = 1; d < 1024; d <<= 1) {
            int t = 0;
            if ((int)threadIdx.x >= d) t = s[threadIdx.x - d];
            __syncthreads();
            s[threadIdx.x] += t;
            __syncthreads();
        }
        int incl = s[threadIdx.x] + s_carry;
        if (i < N_NODES) { g_off[i] = incl - v; g_cur[i] = incl - v; }
        __syncthreads();
        if (threadIdx.x == 1023) s_carry = incl;
        __syncthreads();
    }
    if (threadIdx.x == 0) g_off[N_NODES] = s_carry;
}

// ---------------- launch #3: node embed GEMM (K=64, leaky) + fused hvdot + fp16 copy ----------------
__global__ __launch_bounds__(256) void node_embed_kernel(
    const float* __restrict__ nf, const float* __restrict__ Wn,
    const float* __restrict__ bn, const float* __restrict__ Wl)
{
    extern __shared__ float sm[];
    float* sW = sm;            // 64*128
    float* sX = sm + 8192;     // 64*64
    float* sB = sm + 12288;    // 128
    float* sWL = sm + 12416;   // 128
    int t = threadIdx.x;
    int r0g = blockIdx.x * 64;
    for (int i = t; i < 64 * 128; i += 256) {
        int k = i >> 7, c = i & 127;
        sW[i] = Wn[k * 128 + c];
    }
    for (int i = t; i < 64 * 64; i += 256) {
        int r = i >> 6, k = i & 63;
        int gr = r0g + r;
        sX[i] = (gr < N_NODES) ? nf[gr * 64 + k] : 0.f;
    }
    if (t < 128) { sB[t] = bn[t]; sWL[t] = Wl[t]; }
    __syncthreads();
    int cx = t & 31, cy = t >> 5;
    int r0 = cy * 8, c0 = cx * 4;
    float acc[8][4] = {};
#pragma unroll 4
    for (int k = 0; k < 64; k++) {
        float4 w = *(const float4*)&sW[k * 128 + c0];
#pragma unroll
        for (int r = 0; r < 8; r++) {
            float x = sX[(r0 + r) * 64 + k];
            acc[r][0] += x * w.x; acc[r][1] += x * w.y;
            acc[r][2] += x * w.z; acc[r][3] += x * w.w;
        }
    }
    float wl0 = sWL[c0], wl1 = sWL[c0 + 1], wl2 = sWL[c0 + 2], wl3 = sWL[c0 + 3];
#pragma unroll
    for (int r = 0; r < 8; r++) {
        int gr = r0g + r0 + r;
        if (gr >= N_NODES) break;
        float v0 = leaky01(acc[r][0] + sB[c0]);
        float v1 = leaky01(acc[r][1] + sB[c0 + 1]);
        float v2 = leaky01(acc[r][2] + sB[c0 + 2]);
        float v3 = leaky01(acc[r][3] + sB[c0 + 3]);
        *(float4*)&g_h_v[(size_t)gr * 128 + c0] = make_float4(v0, v1, v2, v3);
        __half2 p01 = __floats2half2_rn(v0, v1);
        __half2 p23 = __floats2half2_rn(v2, v3);
        *(uint2*)&g_h_v16[(size_t)gr * 128 + c0] = make_uint2(*(uint32_t*)&p01, *(uint32_t*)&p23);
        float p = v0 * wl0 + v1 * wl1 + v2 * wl2 + v3 * wl3;
        for (int o = 16; o; o >>= 1) p += __shfl_xor_sync(0xffffffffu, p, o);
        if (cx == 0) g_hvdot[gr] = p;
    }
}

// ============ launch #4: edge GEMM on HMMA, 64 edges/CTA, staged h_e writeout ============
#define SM_SRC   0
#define SM_PERM  256
#define SM_BIAS  512
#define SM_WL    1024
#define SM_LOG   1536
#define SM_A     2048
#define SM_EDGE_TOTAL (SM_A + 64 * 272)   // 19456 bytes -> 4 CTAs/SM

__global__ __launch_bounds__(128, 4)
void edge_mma_kernel(const __half* __restrict__ nf16, const float* __restrict__ ef,
                     const int* __restrict__ src, const int* __restrict__ dst,
                     const float* __restrict__ b_edge,
                     const float* __restrict__ W_logit, const float* __restrict__ b_logit,
                     float* __restrict__ outEF)
{
    extern __shared__ __align__(16) char smem[];
    uint32_t sb = smem_u32(smem);
    int t = threadIdx.x, lane = t & 31, wid = t >> 5;
    int e0 = blockIdx.x * 64;
    int* sSrc = (int*)(smem + SM_SRC);
    int* sPerm = (int*)(smem + SM_PERM);
    float* sBias = (float*)(smem + SM_BIAS);
    float* sWL = (float*)(smem + SM_WL);
    float* sLog = (float*)(smem + SM_LOG);

    if (t < 64) {
        sSrc[t] = src[e0 + t];
        sPerm[t] = atomicAdd(&g_cur[dst[e0 + t]], 1);
    }
    sBias[t] = b_edge[t];
    sWL[t] = W_logit[128 + t];
    __syncthreads();

    // ef: single read; passthrough copy + fp16 into A tile (concat cols 64..127)
    {
        const float4* efs = (const float4*)(ef + (size_t)e0 * 64);
        float4* efd = outEF ? (float4*)(outEF + (size_t)e0 * 64) : nullptr;
#pragma unroll
        for (int it = 0; it < 8; it++) {
            int i = t + it * 128;
            float4 v = efs[i];
            if (efd) efd[i] = v;
            int row = i >> 4, j = i & 15;
            __half2 h01 = __floats2half2_rn(v.x, v.y);
            __half2 h23 = __floats2half2_rn(v.z, v.w);
            *(uint2*)(smem + SM_A + row * 272 + 128 + j * 8)
                = make_uint2(*(uint32_t*)&h01, *(uint32_t*)&h23);
        }
    }
    // nf gather: fp16 rows straight into A tile (concat cols 0..63)
    {
        int r = t >> 1, hf = t & 1;
        const uint4* xp = (const uint4*)(nf16 + (size_t)sSrc[r] * 64 + hf * 32);
        uint4* xd = (uint4*)(smem + SM_A + r * 272 + hf * 64);
#pragma unroll
        for (int j = 0; j < 4; j++) xd[j] = xp[j];
    }
    __syncthreads();

    // warp tile: 4 warps, M=32 (mg in 0..1), N=64 (ng in 0..1)
    int mg = wid & 1, ng = wid >> 1;
    int m0 = mg * 32, n0 = ng * 64;
    float acc[2][8][4];
#pragma unroll
    for (int i = 0; i < 2; i++)
#pragma unroll
        for (int j = 0; j < 8; j++)
#pragma unroll
            for (int c = 0; c < 4; c++) acc[i][j][c] = 0.f;

    uint32_t aOffL = ((lane & 15) * A_STRIDE + (lane >> 4) * 8) * 2;
    uint32_t Ab = sb + SM_A;
    const uint4* bf = g_BfragE + ng * 1024 + lane;

#pragma unroll
    for (int k8 = 0; k8 < 8; k8++) {
        uint32_t kb = k8 * 32;
        uint4 bq[4];
#pragma unroll
        for (int q = 0; q < 4; q++)
            bq[q] = bf[k8 * 128 + q * 32];
        uint32_t a[2][4];
        ldsm_x4(a[0], Ab + aOffL + (uint32_t)m0 * 272 + kb);
        ldsm_x4(a[1], Ab + aOffL + (uint32_t)(m0 + 16) * 272 + kb);
#pragma unroll
        for (int ms = 0; ms < 2; ms++)
#pragma unroll
            for (int q = 0; q < 4; q++) {
                const uint32_t* bb = (const uint32_t*)&bq[q];
                mma_f16(acc[ms][q * 2],     a[ms], bb);
                mma_f16(acc[ms][q * 2 + 1], a[ms], bb + 2);
            }
    }
    __syncthreads();   // A tile reads done -> safe to reuse as h_e staging

    // epilogue: bias + leaky -> smem staging (272B-stride rows) + partial logit
#pragma unroll
    for (int ms = 0; ms < 2; ms++) {
        int r1 = m0 + ms * 16 + (lane >> 2);
        int r2 = r1 + 8;
        float lg1 = 0.f, lg2 = 0.f;
#pragma unroll
        for (int ns = 0; ns < 8; ns++) {
            int col = n0 + ns * 8 + (lane & 3) * 2;
            float v0 = leaky01(acc[ms][ns][0] + sBias[col]);
            float v1 = leaky01(acc[ms][ns][1] + sBias[col + 1]);
            float v2 = leaky01(acc[ms][ns][2] + sBias[col]);
            float v3 = leaky01(acc[ms][ns][3] + sBias[col + 1]);
            lg1 += v0 * sWL[col] + v1 * sWL[col + 1];
            lg2 += v2 * sWL[col] + v3 * sWL[col + 1];
            *(__half2*)(smem + SM_A + r1 * 272 + col * 2) = __floats2half2_rn(v0, v1);
            *(__half2*)(smem + SM_A + r2 * 272 + col * 2) = __floats2half2_rn(v2, v3);
        }
        lg1 += __shfl_xor_sync(0xffffffffu, lg1, 1);
        lg1 += __shfl_xor_sync(0xffffffffu, lg1, 2);
        lg2 += __shfl_xor_sync(0xffffffffu, lg2, 1);
        lg2 += __shfl_xor_sync(0xffffffffu, lg2, 2);
        if ((lane & 3) == 0) {
            sLog[r1 * 2 + ng] = lg1;
            sLog[r2 * 2 + ng] = lg2;
        }
    }
    __syncthreads();

    // coalesced h_e writeout: 2 threads/row, 128B each
    {
        int r = t >> 1, hf = t & 1;
        const uint4* sp = (const uint4*)(smem + SM_A + r * 272 + hf * 128);
        uint4* dp = (uint4*)(g_h_e16 + (size_t)sPerm[r] * 128 + hf * 64);
#pragma unroll
        for (int j = 0; j < 8; j++) dp[j] = sp[j];
    }
    if (t < 64) {
        float s = sLog[t * 2] + sLog[t * 2 + 1] + g_hvdot[sSrc[t]] + b_logit[0];
        g_logit[sPerm[t]] = leaky01(s);
    }
}

// ---------------- launch #5: per-node softmax + weighted sum -> A (fp16) ----------------
__global__ void aggregate_kernel() {
    int v = (blockIdx.x * blockDim.x + threadIdx.x) >> 5;
    int lane = threadIdx.x & 31;
    if (v >= N_NODES) return;
    int s = g_off[v], e = g_off[v + 1];
    float mx = -1e30f;
    for (int i = s + lane; i < e; i += 32)
        mx = fmaxf(mx, g_logit[i]);
    for (int o = 16; o; o >>= 1)
        mx = fmaxf(mx, __shfl_xor_sync(0xffffffffu, mx, o));
    float4 acc = make_float4(0.f, 0.f, 0.f, 0.f);
    float den = 0.f;
    for (int i = s; i < e; i++) {
        float w = expf(g_logit[i] - mx);
        den += w;
        uint2 raw = *(const uint2*)(g_h_e16 + (size_t)i * 128 + lane * 4);
        float2 f01 = __half22float2(*(__half2*)&raw.x);
        float2 f23 = __half22float2(*(__half2*)&raw.y);
        acc.x += w * f01.x; acc.y += w * f01.y;
        acc.z += w * f23.x; acc.w += w * f23.y;
    }
    float inv = (e > s) ? 1.f / den : 0.f;
    __half2 p01 = __floats2half2_rn(acc.x * inv, acc.y * inv);
    __half2 p23 = __floats2half2_rn(acc.z * inv, acc.w * inv);
    *(uint2*)&g_A16[v * 128 + lane * 4] = make_uint2(*(uint32_t*)&p01, *(uint32_t*)&p23);
}

// ============ HMMA GEMM body: 64 rows x 128 cols, K=128, fp16 in ============
#define SM16_BIAS 0
#define SM16_X    512
#define SM16_TOTAL (SM16_X + 64 * 272)   // 17920 bytes

template <int MODE>
__device__ __forceinline__ void gemm16_body(
    const __half* __restrict__ X, const uint4* __restrict__ bfrag,
    const float* __restrict__ bias, float* __restrict__ outF,
    __half* __restrict__ outH, int ldo, int e0)
{
    extern __shared__ __align__(16) char smem[];
    uint32_t sb = smem_u32(smem);
    int t = threadIdx.x, lane = t & 31, wid = t >> 5;
    float* sBias = (float*)(smem + SM16_BIAS);
    sBias[t] = bias[t];

    {
        int row = t >> 1, half = t & 1;
        int gr = e0 + row;
        uint4* xd = (uint4*)(smem + SM16_X + row * 272 + half * 128);
        if (gr < N_NODES) {
            const uint4* xp = (const uint4*)(X + (size_t)gr * 128 + half * 64);
#pragma unroll
            for (int j = 0; j < 8; j++) xd[j] = xp[j];
        } else {
#pragma unroll
            for (int j = 0; j < 8; j++) xd[j] = make_uint4(0, 0, 0, 0);
        }
    }
    __syncthreads();

    int mg = wid & 1, ng = wid >> 1;
    int m0 = mg * 32, n0 = ng * 64;
    float acc[2][8][4];
#pragma unroll
    for (int i = 0; i < 2; i++)
#pragma unroll
        for (int j = 0; j < 8; j++)
#pragma unroll
            for (int c = 0; c < 4; c++) acc[i][j][c] = 0.f;

    uint32_t aOffL = ((lane & 15) * A_STRIDE + (lane >> 4) * 8) * 2;
    uint32_t Ab = sb + SM16_X;
    const uint4* bf = bfrag + ng * 1024 + lane;

#pragma unroll
    for (int k8 = 0; k8 < 8; k8++) {
        uint32_t kb = k8 * 32;
        uint4 bq[4];
#pragma unroll
        for (int q = 0; q < 4; q++)
            bq[q] = bf[k8 * 128 + q * 32];
        uint32_t a[2][4];
        ldsm_x4(a[0], Ab + aOffL + (uint32_t)m0 * 272 + kb);
        ldsm_x4(a[1], Ab + aOffL + (uint32_t)(m0 + 16) * 272 + kb);
#pragma unroll
        for (int ms = 0; ms < 2; ms++)
#pragma unroll
            for (int q = 0; q < 4; q++) {
                const uint32_t* bb = (const uint32_t*)&bq[q];
                mma_f16(acc[ms][q * 2],     a[ms], bb);
                mma_f16(acc[ms][q * 2 + 1], a[ms], bb + 2);
            }
    }

#pragma unroll
    for (int ms = 0; ms < 2; ms++) {
        int r1 = m0 + ms * 16 + (lane >> 2);
        int r2 = r1 + 8;
#pragma unroll
        for (int rr = 0; rr < 2; rr++) {
            int row = rr ? r2 : r1;
            int gr = e0 + row;
            if (gr >= N_NODES) continue;
#pragma unroll
            for (int ns = 0; ns < 8; ns++) {
                int col = n0 + ns * 8 + (lane & 3) * 2;
                float v0 = acc[ms][ns][rr * 2]     + sBias[col];
                float v1 = acc[ms][ns][rr * 2 + 1] + sBias[col + 1];
                if (MODE == 1) {
                    v0 = (v0 > 0.f) ? v0 : (expf(v0) - 1.f);
                    v1 = (v1 > 0.f) ? v1 : (expf(v1) - 1.f);
                    *(__half2*)(outH + (size_t)gr * 128 + col) = __floats2half2_rn(v0, v1);
                } else {
                    *(float2*)(outF + (size_t)gr * ldo + col) = make_float2(v0, v1);
                }
            }
        }
    }
}

// launch #6: C_v = elu(A @ W_msg + b_msg) in fp16
__global__ __launch_bounds__(128, 4) void cv16_kernel(const float* __restrict__ b_msg) {
    gemm16_body<1>(g_A16, g_WmsgFrag, b_msg, nullptr, g_cv16, 128, blockIdx.x * 64);
}

// launch #7: gi = cv @ Wih^T + b_ih ; gh = h_v @ Whh^T + b_hh (fp32 out)
__global__ __launch_bounds__(128, 4) void gru16_kernel(const float* __restrict__ b_ih,
                                                       const float* __restrict__ b_hh) {
    int mat = blockIdx.y / 3, chunk = blockIdx.y % 3;
    const __half* X = mat ? g_h_v16 : g_cv16;
    const uint4* bf = (mat ? g_WhhFrag : g_WihFrag) + chunk * 2048;
    const float* bias = (mat ? b_hh : b_ih) + chunk * 128;
    float* outp = (mat ? g_gh : g_gi) + chunk * 128;
    gemm16_body<0>(X, bf, bias, outp, nullptr, 384, blockIdx.x * 64);
}

// ---------------- launch #8: GRU gates + relu ----------------
__global__ void gate_kernel(float* __restrict__ out) {
    int idx = blockIdx.x * blockDim.x + threadIdx.x;
    if (idx >= N_NODES * NHID) return;
    int n = idx >> 7, j = idx & 127;
    const float* gi = &g_gi[n * 384];
    const float* gh = &g_gh[n * 384];
    float r = 1.f / (1.f + expf(-(gi[j] + gh[j])));
    float z = 1.f / (1.f + expf(-(gi[128 + j] + gh[128 + j])));
    float nn = tanhf(gi[256 + j] + r * gh[256 + j]);
    float hv = g_h_v[idx];
    float h = (1.f - z) * nn + z * hv;
    out[idx] = h > 0.f ? h : 0.f;
}

// ---------------- launch ----------------
extern "C" void kernel_launch(void* const* d_in, const int* in_sizes, int n_in,
                              void* d_out, int out_size) {
    const float* node_feats = (const float*)d_in[0];
    const float* edge_feats = (const float*)d_in[1];
    const float* W_node  = (const float*)d_in[2];
    const float* b_node  = (const float*)d_in[3];
    const float* W_edge  = (const float*)d_in[4];
    const float* b_edge  = (const float*)d_in[5];
    const float* W_logit = (const float*)d_in[6];
    const float* b_logit = (const float*)d_in[7];
    const float* W_msg   = (const float*)d_in[8];
    const float* b_msg   = (const float*)d_in[9];
    const float* W_ih    = (const float*)d_in[10];
    const float* W_hh    = (const float*)d_in[11];
    const float* b_ih    = (const float*)d_in[12];
    const float* b_hh    = (const float*)d_in[13];
    const int*   src     = (const int*)d_in[14];
    const int*   dst     = (const int*)d_in[15];
    float* out = (float*)d_out;

    int* p_cnt;
    __half* p_nf16;
    cudaGetSymbolAddress((void**)&p_cnt, g_cnt);
    cudaGetSymbolAddress((void**)&p_nf16, g_nf16);

    const int SM_NODE = (64 * 128 + 64 * 64 + 256) * 4;
    cudaFuncSetAttribute(edge_mma_kernel, cudaFuncAttributeMaxDynamicSharedMemorySize, SM_EDGE_TOTAL);
    cudaFuncSetAttribute(node_embed_kernel, cudaFuncAttributeMaxDynamicSharedMemorySize, SM_NODE);
    cudaFuncSetAttribute(cv16_kernel, cudaFuncAttributeMaxDynamicSharedMemorySize, SM16_TOTAL);
    cudaFuncSetAttribute(gru16_kernel, cudaFuncAttributeMaxDynamicSharedMemorySize, SM16_TOTAL);

    cudaMemsetAsync(p_cnt, 0, N_NODES * sizeof(int));

    // #1 histogram + nf16 + all fragment prep
    hist_prep_kernel<<<(N_EDGES + 255) / 256, 256>>>(dst, node_feats, W_edge, W_ih, W_hh, W_msg);
    // #2 scan
    scan_kernel<<<1, 1024>>>();
    // #3 node embed + fused hvdot + fp16 copy
    int ntiles64 = (N_NODES + 63) / 64;
    node_embed_kernel<<<ntiles64, 256, SM_NODE>>>(node_feats, W_node, b_node, W_logit);
    // #4 edge GEMM on tensor cores (profiled slot)
    float* outEF = (out_size >= N_NODES * NHID + N_EDGES * 64) ? (out + N_NODES * NHID) : nullptr;
    edge_mma_kernel<<<N_EDGES / 64, 128, SM_EDGE_TOTAL>>>(p_nf16, edge_feats, src, dst,
                                                          b_edge, W_logit, b_logit, outEF);
    // #5 softmax-weighted segment sum -> A16
    aggregate_kernel<<<(N_NODES + 7) / 8, 256>>>();
    // #6 C_v (HMMA, fp16 out)
    cv16_kernel<<<ntiles64, 128, SM16_TOTAL>>>(b_msg);
    // #7 gi / gh (HMMA, fp32 out)
    gru16_kernel<<<dim3(ntiles64, 6), 128, SM16_TOTAL>>>(b_ih, b_hh);
    // #8 gates -> h_new
    gate_kernel<<<(N_NODES * NHID + 255) / 256, 256>>>(out);
}